// round 1
// baseline (speedup 1.0000x reference)
#include <cuda_runtime.h>
#include <math.h>

// ----------------------------------------------------------------------------
// Problem constants (hardcoded for this shape):
//   B=2, T=2048, C=4096, H=32, hd=128.  M = B*T = 4096, N = K = 4096.
// Reference rotary: freqs all == 1.0 (integer floor-div bug is faithful), so
// theta(t, j) = t for every pair j -> rotate each adjacent column pair by t.
// ----------------------------------------------------------------------------

#define MM 4096
#define NN 4096
#define KK 4096
#define TLEN 2048

// Scratch (allocation-free: __device__ globals)
__device__ float g_q[(size_t)MM * NN];
__device__ float g_k[(size_t)MM * NN];
__device__ float g_v[(size_t)MM * NN];
__device__ float g_o[(size_t)MM * NN];

// ============================================================================
// GEMM: C[m][n] = sum_k A[m][k] * B[n][k]   (both K-major, i.e. y = A @ B^T)
// 128x128 tile, BK=8, 256 threads, 8x8 per thread, fused rotary epilogue.
// ============================================================================
#define GT 128
#define GK 8

__global__ __launch_bounds__(256, 2)
void gemm_tn_kernel(const float* __restrict__ A, const float* __restrict__ B,
                    float* __restrict__ C, int rotate) {
    __shared__ float sA[GK][GT];
    __shared__ float sB[GK][GT];

    const int tid = threadIdx.x;
    const int tx = tid & 15, ty = tid >> 4;
    const int row0 = blockIdx.y * GT, col0 = blockIdx.x * GT;
    const int lr = tid >> 1;            // 0..127
    const int lp = (tid & 1) * 4;       // 0 or 4

    const float* Ap = A + (size_t)(row0 + lr) * KK + lp;
    const float* Bp = B + (size_t)(col0 + lr) * KK + lp;

    float acc[8][8];
#pragma unroll
    for (int i = 0; i < 8; i++)
#pragma unroll
        for (int j = 0; j < 8; j++) acc[i][j] = 0.f;

    float4 a4 = *(const float4*)Ap;
    float4 b4 = *(const float4*)Bp;

    const int nk = KK / GK;   // 512
    for (int kt = 0; kt < nk; kt++) {
        sA[lp + 0][lr] = a4.x; sA[lp + 1][lr] = a4.y;
        sA[lp + 2][lr] = a4.z; sA[lp + 3][lr] = a4.w;
        sB[lp + 0][lr] = b4.x; sB[lp + 1][lr] = b4.y;
        sB[lp + 2][lr] = b4.z; sB[lp + 3][lr] = b4.w;
        __syncthreads();

        if (kt + 1 < nk) {   // prefetch next k-slab while computing
            a4 = *(const float4*)(Ap + (size_t)(kt + 1) * GK);
            b4 = *(const float4*)(Bp + (size_t)(kt + 1) * GK);
        }

#pragma unroll
        for (int k = 0; k < GK; k++) {
            float4 av0 = *(const float4*)(&sA[k][ty * 8]);
            float4 av1 = *(const float4*)(&sA[k][ty * 8 + 4]);
            float4 bv0 = *(const float4*)(&sB[k][tx * 8]);
            float4 bv1 = *(const float4*)(&sB[k][tx * 8 + 4]);
            float av[8] = {av0.x, av0.y, av0.z, av0.w, av1.x, av1.y, av1.z, av1.w};
            float bv[8] = {bv0.x, bv0.y, bv0.z, bv0.w, bv1.x, bv1.y, bv1.z, bv1.w};
#pragma unroll
            for (int i = 0; i < 8; i++)
#pragma unroll
                for (int j = 0; j < 8; j++)
                    acc[i][j] = fmaf(av[i], bv[j], acc[i][j]);
        }
        __syncthreads();
    }

    // Epilogue: optional fused rotary (angle = token index t = m % TLEN,
    // pairs are adjacent even/odd columns), then vectorized store.
#pragma unroll
    for (int i = 0; i < 8; i++) {
        int m = row0 + ty * 8 + i;
        if (rotate) {
            float t = (float)(m & (TLEN - 1));
            float sn, cs;
            sincosf(t, &sn, &cs);
#pragma unroll
            for (int jj = 0; jj < 4; jj++) {
                float x0 = acc[i][2 * jj], x1 = acc[i][2 * jj + 1];
                acc[i][2 * jj]     = x0 * cs - x1 * sn;
                acc[i][2 * jj + 1] = x0 * sn + x1 * cs;
            }
        }
        float4* Cp = (float4*)(C + (size_t)m * NN + col0 + tx * 8);
        Cp[0] = make_float4(acc[i][0], acc[i][1], acc[i][2], acc[i][3]);
        Cp[1] = make_float4(acc[i][4], acc[i][5], acc[i][6], acc[i][7]);
    }
}

// ============================================================================
// Flash attention (fp32, causal). BQ=BK=64, hd=128.
// Grid: (T/BQ, B*H). 256 threads. Q/K/V layout: [B*T, H*128] row-major.
// ============================================================================
#define BQ 64
#define BK 64
#define HD 128
#define SKP 129   // padded K row (kills 16-way conflict on column reads)
#define SSP 65    // padded S row

// floats: Q 64*128, K 64*129, V 64*128, S 64*65
#define FLASH_SMEM_FLOATS (BQ * HD + BK * SKP + BK * HD + BQ * SSP)
#define FLASH_SMEM_BYTES  (FLASH_SMEM_FLOATS * 4)

__global__ __launch_bounds__(256, 1)
void flash_kernel(const float* __restrict__ Q, const float* __restrict__ K,
                  const float* __restrict__ V, float* __restrict__ O) {
    extern __shared__ float sm[];
    float* sQ = sm;                    // [64][128]
    float* sK = sQ + BQ * HD;          // [64][129]
    float* sV = sK + BK * SKP;         // [64][128]
    float* sS = sV + BK * HD;          // [64][65]

    const int tid = threadIdx.x;
    const int bh = blockIdx.y;
    const int b = bh >> 5, h = bh & 31;
    const int qb = blockIdx.x;
    const int q0 = qb * BQ;
    const float scale = 0.08838834764831845f;   // 128^-0.5

    const size_t base = ((size_t)b * TLEN) * NN + (size_t)h * HD;

    // Load Q tile (float4, coalesced)
    for (int v = tid; v < BQ * (HD / 4); v += 256) {
        int r = v >> 5, c = v & 31;
        ((float4*)(sQ + r * HD))[c] =
            ((const float4*)(Q + base + (size_t)(q0 + r) * NN))[c];
    }

    const int r   = tid >> 2;     // softmax/PV: row 0..63
    const int sub = tid & 3;      // 4 threads per row
    const int tr  = tid >> 4;     // S-phase: row-group 0..15
    const int tc  = tid & 15;     // S-phase: col-group 0..15
    const int ds  = sub * 32;     // output dims owned by this thread

    float m_i = -INFINITY, l_i = 0.f;
    float acc[32];
#pragma unroll
    for (int d = 0; d < 32; d++) acc[d] = 0.f;

    for (int kt = 0; kt <= qb; kt++) {
        const int k0 = kt * BK;
        __syncthreads();   // previous iter's sV/sS reads done before reuse

        // Load K (scalar into padded rows) and V (float4)
        for (int v = tid; v < BK * HD; v += 256) {
            int rr = v >> 7, d = v & 127;
            sK[rr * SKP + d] = K[base + (size_t)(k0 + rr) * NN + d];
        }
        for (int v = tid; v < BK * (HD / 4); v += 256) {
            int rr = v >> 5, c = v & 31;
            ((float4*)(sV + rr * HD))[c] =
                ((const float4*)(V + base + (size_t)(k0 + rr) * NN))[c];
        }
        __syncthreads();

        // S = scale * Q K^T, causal mask on diagonal block
        float s[4][4];
#pragma unroll
        for (int i = 0; i < 4; i++)
#pragma unroll
            for (int j = 0; j < 4; j++) s[i][j] = 0.f;

        for (int d = 0; d < HD; d++) {
            float qv[4], kv[4];
#pragma unroll
            for (int i = 0; i < 4; i++) qv[i] = sQ[(4 * tr + i) * HD + d];
#pragma unroll
            for (int j = 0; j < 4; j++) kv[j] = sK[(4 * tc + j) * SKP + d];
#pragma unroll
            for (int i = 0; i < 4; i++)
#pragma unroll
                for (int j = 0; j < 4; j++)
                    s[i][j] = fmaf(qv[i], kv[j], s[i][j]);
        }
#pragma unroll
        for (int i = 0; i < 4; i++)
#pragma unroll
            for (int j = 0; j < 4; j++) {
                float val = s[i][j] * scale;
                if (kt == qb && (4 * tc + j) > (4 * tr + i)) val = -INFINITY;
                sS[(4 * tr + i) * SSP + 4 * tc + j] = val;
            }
        __syncthreads();

        // Online softmax: 4 threads per row
        float mymax = -INFINITY;
#pragma unroll
        for (int j = 0; j < 16; j++)
            mymax = fmaxf(mymax, sS[r * SSP + sub * 16 + j]);
        mymax = fmaxf(mymax, __shfl_xor_sync(0xffffffff, mymax, 1));
        mymax = fmaxf(mymax, __shfl_xor_sync(0xffffffff, mymax, 2));

        float m_new = fmaxf(m_i, mymax);
        float alpha = __expf(m_i - m_new);

        float mysum = 0.f;
#pragma unroll
        for (int j = 0; j < 16; j++) {
            int idx = r * SSP + sub * 16 + j;
            float p = __expf(sS[idx] - m_new);
            sS[idx] = p;
            mysum += p;
        }
        __syncwarp();
        mysum += __shfl_xor_sync(0xffffffff, mysum, 1);
        mysum += __shfl_xor_sync(0xffffffff, mysum, 2);

        l_i = l_i * alpha + mysum;
        m_i = m_new;

#pragma unroll
        for (int d = 0; d < 32; d++) acc[d] *= alpha;

        // O += P @ V  (thread owns dims [ds, ds+32))
        for (int j = 0; j < BK; j++) {
            float p = sS[r * SSP + j];
            const float4* v4 = (const float4*)(sV + j * HD + ds);
#pragma unroll
            for (int c = 0; c < 8; c++) {
                float4 vv = v4[c];
                acc[4 * c + 0] = fmaf(p, vv.x, acc[4 * c + 0]);
                acc[4 * c + 1] = fmaf(p, vv.y, acc[4 * c + 1]);
                acc[4 * c + 2] = fmaf(p, vv.z, acc[4 * c + 2]);
                acc[4 * c + 3] = fmaf(p, vv.w, acc[4 * c + 3]);
            }
        }
    }

    // Normalize + write out (row q0+r, cols h*128+ds .. +32)
    float inv = 1.f / l_i;
    float4* Op = (float4*)(O + base + (size_t)(q0 + r) * NN + ds);
#pragma unroll
    for (int c = 0; c < 8; c++) {
        Op[c] = make_float4(acc[4 * c + 0] * inv, acc[4 * c + 1] * inv,
                            acc[4 * c + 2] * inv, acc[4 * c + 3] * inv);
    }
}

// ============================================================================
// Launch
// ============================================================================
extern "C" void kernel_launch(void* const* d_in, const int* in_sizes, int n_in,
                              void* d_out, int out_size) {
    const float* x  = (const float*)d_in[0];
    const float* wq = (const float*)d_in[1];
    const float* wk = (const float*)d_in[2];
    const float* wv = (const float*)d_in[3];
    const float* wo = (const float*)d_in[4];
    float* out = (float*)d_out;

    float *pq, *pk, *pv, *po;
    cudaGetSymbolAddress((void**)&pq, g_q);
    cudaGetSymbolAddress((void**)&pk, g_k);
    cudaGetSymbolAddress((void**)&pv, g_v);
    cudaGetSymbolAddress((void**)&po, g_o);

    cudaFuncSetAttribute(flash_kernel,
                         cudaFuncAttributeMaxDynamicSharedMemorySize,
                         FLASH_SMEM_BYTES);

    dim3 ggrid(NN / GT, MM / GT);   // (32, 32)

    gemm_tn_kernel<<<ggrid, 256>>>(x, wq, pq, 1);   // Q proj + rotary
    gemm_tn_kernel<<<ggrid, 256>>>(x, wk, pk, 1);   // K proj + rotary
    gemm_tn_kernel<<<ggrid, 256>>>(x, wv, pv, 0);   // V proj

    dim3 fgrid(TLEN / BQ, 2 * 32);  // (32, 64)
    flash_kernel<<<fgrid, 256, FLASH_SMEM_BYTES>>>(pq, pk, pv, po);

    gemm_tn_kernel<<<ggrid, 256>>>(po, wo, out, 0); // output proj
}

// round 3
// speedup vs baseline: 1.4744x; 1.4744x over previous
#include <cuda_runtime.h>
#include <cuda_bf16.h>
#include <cstdint>
#include <math.h>

// ----------------------------------------------------------------------------
// B=2, T=2048, C=4096, H=32, hd=128.  M=N=K=4096 for all projections.
// Rotary: reference freqs all == 1.0 -> theta(t) = t, adjacent col pairs.
// GEMMs on mma.sync bf16 (HMMA) with split-bf16 (hi+lo), 3 products:
//   C = Ahi*Bhi + Ahi*Blo + Alo*Bhi   (fp32 accum), err ~1e-5.
// (tcgen05 is PTX-gated behind sm_103a; harness targets compute_103, so the
//  legacy mma.sync path is the only tensor-core path that compiles.)
// ----------------------------------------------------------------------------

#define MM 4096
#define NN 4096
#define KK 4096
#define TLEN 2048

__device__ float g_q[(size_t)MM * NN];
__device__ float g_k[(size_t)MM * NN];
__device__ float g_v[(size_t)MM * NN];
__device__ float g_o[(size_t)MM * NN];

__device__ __forceinline__ uint32_t smem_u32(const void* p) {
    uint32_t a;
    asm("{ .reg .u64 t; cvta.to.shared.u64 t, %1; cvt.u32.u64 %0, t; }"
        : "=r"(a) : "l"(p));
    return a;
}

#define LDSM4(r, a)                                                            \
    asm volatile("ldmatrix.sync.aligned.m8n8.x4.shared.b16 {%0,%1,%2,%3}, [%4];" \
                 : "=r"((r)[0]), "=r"((r)[1]), "=r"((r)[2]), "=r"((r)[3])      \
                 : "r"(a))

#define MMA16816(c, a, b0, b1)                                                 \
    asm volatile("mma.sync.aligned.m16n8k16.row.col.f32.bf16.bf16.f32 "        \
                 "{%0,%1,%2,%3},{%4,%5,%6,%7},{%8,%9},{%0,%1,%2,%3};"          \
                 : "+f"((c)[0]), "+f"((c)[1]), "+f"((c)[2]), "+f"((c)[3])      \
                 : "r"((a)[0]), "r"((a)[1]), "r"((a)[2]), "r"((a)[3]),         \
                   "r"(b0), "r"(b1))

// ============================================================================
// GEMM: C[m][n] = sum_k A[m][k]*B[n][k], fp32 in/out.
// CTA tile 128x128, 8 warps (warp tile 32x64), K-chunk 32, double buffered.
// SMEM per stage: Ahi | Alo | Bhi | Blo, each 128 rows x 32 bf16, pitch 80B.
// ============================================================================
#define CH 32
#define PITCH 80
#define MAT_B (128 * PITCH)        // 10240 B per matrix
#define STAGE_B (4 * MAT_B)        // 40960 B
#define GEMM_SMEM (2 * STAGE_B)    // 81920 B
#define NCH (KK / CH)              // 128

// convert 16 fp32 -> 16 bf16 hi + 16 bf16 lo, store 32B each
__device__ __forceinline__ void conv16(const float* gp, char* hiP, char* loP) {
    float4 v[4];
#pragma unroll
    for (int j = 0; j < 4; j++) v[j] = ((const float4*)gp)[j];
    uint32_t hw[8], lw[8];
#pragma unroll
    for (int j = 0; j < 4; j++) {
        uint32_t ux = __float_as_uint(v[j].x), uy = __float_as_uint(v[j].y);
        uint32_t uz = __float_as_uint(v[j].z), uw = __float_as_uint(v[j].w);
        hw[2 * j]     = __byte_perm(ux, uy, 0x7632);
        hw[2 * j + 1] = __byte_perm(uz, uw, 0x7632);
        float lx = v[j].x - __uint_as_float(ux & 0xFFFF0000u);
        float ly = v[j].y - __uint_as_float(uy & 0xFFFF0000u);
        float lz = v[j].z - __uint_as_float(uz & 0xFFFF0000u);
        float lwv = v[j].w - __uint_as_float(uw & 0xFFFF0000u);
        asm("cvt.rn.bf16x2.f32 %0, %1, %2;" : "=r"(lw[2 * j])     : "f"(ly),  "f"(lx));
        asm("cvt.rn.bf16x2.f32 %0, %1, %2;" : "=r"(lw[2 * j + 1]) : "f"(lwv), "f"(lz));
    }
    ((uint4*)hiP)[0] = make_uint4(hw[0], hw[1], hw[2], hw[3]);
    ((uint4*)hiP)[1] = make_uint4(hw[4], hw[5], hw[6], hw[7]);
    ((uint4*)loP)[0] = make_uint4(lw[0], lw[1], lw[2], lw[3]);
    ((uint4*)loP)[1] = make_uint4(lw[4], lw[5], lw[6], lw[7]);
}

__global__ __launch_bounds__(256, 2)
void gemm_mma(const float* __restrict__ A, const float* __restrict__ B,
              float* __restrict__ C, int rotate) {
    extern __shared__ __align__(1024) char sm[];
    const uint32_t wbase = smem_u32(sm);
    const int tid = threadIdx.x;
    const int wid = tid >> 5, lane = tid & 31;

    const int row0 = blockIdx.y * 128, col0 = blockIdx.x * 128;

    // conversion assignment: thread handles one row-half (16 floats) of A and B
    const int crow = tid >> 1, chalf = tid & 1;
    const float* Ap = A + (size_t)(row0 + crow) * KK + chalf * 16;
    const float* Bp = B + (size_t)(col0 + crow) * KK + chalf * 16;
    const uint32_t coff = crow * PITCH + chalf * 32;

    // warp tile origin
    const int wm = (wid & 3) * 32, wn = (wid >> 2) * 64;

    // ldmatrix lane byte-offsets (within a stage)
    const int l = lane;
    const uint32_t aoff =
        (uint32_t)(wm + (l & 7) + 8 * ((l >> 3) & 1)) * PITCH + (l >> 4) * 16;
    const uint32_t boff =
        (uint32_t)(wn + (l & 7) + 8 * (l >> 4)) * PITCH + ((l >> 3) & 1) * 16;

    float acc[2][8][4];
#pragma unroll
    for (int i = 0; i < 2; i++)
#pragma unroll
        for (int j = 0; j < 8; j++)
#pragma unroll
            for (int q = 0; q < 4; q++) acc[i][j][q] = 0.f;

    // prologue: chunk 0 into stage 0
    {
        char* st = sm;
        conv16(Ap, st + coff, st + MAT_B + coff);
        conv16(Bp, st + 2 * MAT_B + coff, st + 3 * MAT_B + coff);
    }

    for (int i = 0; i < NCH; i++) {
        __syncthreads();
        if (i + 1 < NCH) {
            char* st = sm + ((i + 1) & 1) * STAGE_B;
            const float* ap = Ap + (size_t)(i + 1) * CH;
            const float* bp = Bp + (size_t)(i + 1) * CH;
            conv16(ap, st + coff, st + MAT_B + coff);
            conv16(bp, st + 2 * MAT_B + coff, st + 3 * MAT_B + coff);
        }
        const uint32_t sb = wbase + (i & 1) * STAGE_B;
#pragma unroll
        for (int ks = 0; ks < 2; ks++) {
            uint32_t a_h[2][4], a_l[2][4];
            const uint32_t ka = sb + aoff + ks * 32;
#pragma unroll
            for (int mt = 0; mt < 2; mt++) {
                LDSM4(a_h[mt], ka + mt * 16 * PITCH);
                LDSM4(a_l[mt], ka + mt * 16 * PITCH + MAT_B);
            }
            const uint32_t kb = sb + 2 * MAT_B + boff + ks * 32;
#pragma unroll
            for (int p = 0; p < 4; p++) {
                uint32_t bh[4], bl[4];
                LDSM4(bh, kb + p * 16 * PITCH);
                LDSM4(bl, kb + p * 16 * PITCH + MAT_B);
#pragma unroll
                for (int mt = 0; mt < 2; mt++) {
#pragma unroll
                    for (int q = 0; q < 2; q++) {
                        float* c = acc[mt][2 * p + q];
                        MMA16816(c, a_h[mt], bh[2 * q], bh[2 * q + 1]);
                        MMA16816(c, a_h[mt], bl[2 * q], bl[2 * q + 1]);
                        MMA16816(c, a_l[mt], bh[2 * q], bh[2 * q + 1]);
                    }
                }
            }
        }
    }

    // epilogue: fused rotary + direct global store (float2 pairs)
    const int mrow = lane >> 2, ncol = 2 * (lane & 3);
#pragma unroll
    for (int mt = 0; mt < 2; mt++) {
#pragma unroll
        for (int part = 0; part < 2; part++) {
            const int m = row0 + wm + mt * 16 + mrow + part * 8;
            float sn = 0.f, cs = 1.f;
            if (rotate) sincosf((float)(m & (TLEN - 1)), &sn, &cs);
            float* crow_p = C + (size_t)m * NN + col0 + wn + ncol;
#pragma unroll
            for (int nt = 0; nt < 8; nt++) {
                float x0 = acc[mt][nt][2 * part];
                float x1 = acc[mt][nt][2 * part + 1];
                float y0 = rotate ? x0 * cs - x1 * sn : x0;
                float y1 = rotate ? x0 * sn + x1 * cs : x1;
                *(float2*)(crow_p + nt * 8) = make_float2(y0, y1);
            }
        }
    }
}

// ============================================================================
// Flash attention (fp32, causal). BQ=BK=64, hd=128.  (unchanged this round)
// ============================================================================
#define BQ 64
#define BK 64
#define HD 128
#define SKP 129
#define SSP 65
#define FLASH_SMEM_FLOATS (BQ * HD + BK * SKP + BK * HD + BQ * SSP)
#define FLASH_SMEM_BYTES  (FLASH_SMEM_FLOATS * 4)

__global__ __launch_bounds__(256, 1)
void flash_kernel(const float* __restrict__ Q, const float* __restrict__ K,
                  const float* __restrict__ V, float* __restrict__ O) {
    extern __shared__ float smf[];
    float* sQ = smf;
    float* sK = sQ + BQ * HD;
    float* sV = sK + BK * SKP;
    float* sS = sV + BK * HD;

    const int tid = threadIdx.x;
    const int bh = blockIdx.y;
    const int b = bh >> 5, h = bh & 31;
    const int qb = blockIdx.x;
    const int q0 = qb * BQ;
    const float scale = 0.08838834764831845f;

    const size_t base = ((size_t)b * TLEN) * NN + (size_t)h * HD;

    for (int v = tid; v < BQ * (HD / 4); v += 256) {
        int r = v >> 5, c = v & 31;
        ((float4*)(sQ + r * HD))[c] =
            ((const float4*)(Q + base + (size_t)(q0 + r) * NN))[c];
    }

    const int r   = tid >> 2;
    const int sub = tid & 3;
    const int tr  = tid >> 4;
    const int tc  = tid & 15;
    const int ds  = sub * 32;

    float m_i = -INFINITY, l_i = 0.f;
    float acc[32];
#pragma unroll
    for (int d = 0; d < 32; d++) acc[d] = 0.f;

    for (int kt = 0; kt <= qb; kt++) {
        const int k0 = kt * BK;
        __syncthreads();

        for (int v = tid; v < BK * HD; v += 256) {
            int rr = v >> 7, d = v & 127;
            sK[rr * SKP + d] = K[base + (size_t)(k0 + rr) * NN + d];
        }
        for (int v = tid; v < BK * (HD / 4); v += 256) {
            int rr = v >> 5, c = v & 31;
            ((float4*)(sV + rr * HD))[c] =
                ((const float4*)(V + base + (size_t)(k0 + rr) * NN))[c];
        }
        __syncthreads();

        float s[4][4];
#pragma unroll
        for (int i = 0; i < 4; i++)
#pragma unroll
            for (int j = 0; j < 4; j++) s[i][j] = 0.f;

        for (int d = 0; d < HD; d++) {
            float qv[4], kv[4];
#pragma unroll
            for (int i = 0; i < 4; i++) qv[i] = sQ[(4 * tr + i) * HD + d];
#pragma unroll
            for (int j = 0; j < 4; j++) kv[j] = sK[(4 * tc + j) * SKP + d];
#pragma unroll
            for (int i = 0; i < 4; i++)
#pragma unroll
                for (int j = 0; j < 4; j++)
                    s[i][j] = fmaf(qv[i], kv[j], s[i][j]);
        }
#pragma unroll
        for (int i = 0; i < 4; i++)
#pragma unroll
            for (int j = 0; j < 4; j++) {
                float val = s[i][j] * scale;
                if (kt == qb && (4 * tc + j) > (4 * tr + i)) val = -INFINITY;
                sS[(4 * tr + i) * SSP + 4 * tc + j] = val;
            }
        __syncthreads();

        float mymax = -INFINITY;
#pragma unroll
        for (int j = 0; j < 16; j++)
            mymax = fmaxf(mymax, sS[r * SSP + sub * 16 + j]);
        mymax = fmaxf(mymax, __shfl_xor_sync(0xffffffff, mymax, 1));
        mymax = fmaxf(mymax, __shfl_xor_sync(0xffffffff, mymax, 2));

        float m_new = fmaxf(m_i, mymax);
        float alpha = __expf(m_i - m_new);

        float mysum = 0.f;
#pragma unroll
        for (int j = 0; j < 16; j++) {
            int idx = r * SSP + sub * 16 + j;
            float p = __expf(sS[idx] - m_new);
            sS[idx] = p;
            mysum += p;
        }
        __syncwarp();
        mysum += __shfl_xor_sync(0xffffffff, mysum, 1);
        mysum += __shfl_xor_sync(0xffffffff, mysum, 2);

        l_i = l_i * alpha + mysum;
        m_i = m_new;

#pragma unroll
        for (int d = 0; d < 32; d++) acc[d] *= alpha;

        for (int j = 0; j < BK; j++) {
            float p = sS[r * SSP + j];
            const float4* v4 = (const float4*)(sV + j * HD + ds);
#pragma unroll
            for (int c = 0; c < 8; c++) {
                float4 vv = v4[c];
                acc[4 * c + 0] = fmaf(p, vv.x, acc[4 * c + 0]);
                acc[4 * c + 1] = fmaf(p, vv.y, acc[4 * c + 1]);
                acc[4 * c + 2] = fmaf(p, vv.z, acc[4 * c + 2]);
                acc[4 * c + 3] = fmaf(p, vv.w, acc[4 * c + 3]);
            }
        }
    }

    float inv = 1.f / l_i;
    float4* Op = (float4*)(O + base + (size_t)(q0 + r) * NN + ds);
#pragma unroll
    for (int c = 0; c < 8; c++) {
        Op[c] = make_float4(acc[4 * c + 0] * inv, acc[4 * c + 1] * inv,
                            acc[4 * c + 2] * inv, acc[4 * c + 3] * inv);
    }
}

// ============================================================================
// Launch
// ============================================================================
extern "C" void kernel_launch(void* const* d_in, const int* in_sizes, int n_in,
                              void* d_out, int out_size) {
    const float* x  = (const float*)d_in[0];
    const float* wq = (const float*)d_in[1];
    const float* wk = (const float*)d_in[2];
    const float* wv = (const float*)d_in[3];
    const float* wo = (const float*)d_in[4];
    float* out = (float*)d_out;

    float *pq, *pk, *pv, *po;
    cudaGetSymbolAddress((void**)&pq, g_q);
    cudaGetSymbolAddress((void**)&pk, g_k);
    cudaGetSymbolAddress((void**)&pv, g_v);
    cudaGetSymbolAddress((void**)&po, g_o);

    cudaFuncSetAttribute(gemm_mma, cudaFuncAttributeMaxDynamicSharedMemorySize,
                         GEMM_SMEM);
    cudaFuncSetAttribute(flash_kernel,
                         cudaFuncAttributeMaxDynamicSharedMemorySize,
                         FLASH_SMEM_BYTES);

    dim3 ggrid(NN / 128, MM / 128);   // (32, 32)

    gemm_mma<<<ggrid, 256, GEMM_SMEM>>>(x, wq, pq, 1);
    gemm_mma<<<ggrid, 256, GEMM_SMEM>>>(x, wk, pk, 1);
    gemm_mma<<<ggrid, 256, GEMM_SMEM>>>(x, wv, pv, 0);

    dim3 fgrid(TLEN / BQ, 2 * 32);    // (32, 64)
    flash_kernel<<<fgrid, 256, FLASH_SMEM_BYTES>>>(pq, pk, pv, po);

    gemm_mma<<<ggrid, 256, GEMM_SMEM>>>(po, wo, out, 0);
}

// round 4
// speedup vs baseline: 2.6213x; 1.7779x over previous
#include <cuda_runtime.h>
#include <cuda_bf16.h>
#include <cstdint>
#include <math.h>

// ----------------------------------------------------------------------------
// B=2, T=2048, C=4096, H=32, hd=128.  M=N=K=4096 for all projections.
// Rotary: reference freqs all == 1.0 -> theta(t) = t, adjacent col pairs.
// Pipeline:
//   1) split fp32 -> (hi,lo) bf16 for x, wq, wk, wv, wo          (6 tiny kernels)
//   2) bf16 HMMA GEMM (3-product split: AhBh + AhBl + AlBh), cp.async pipelined
//   3) fp32 flash attention (vectorized LDS, 4x8 PV mapping)
//   4) split attention output, final GEMM
// ----------------------------------------------------------------------------

#define MM 4096
#define NN 4096
#define KK 4096
#define TLEN 2048

__device__ float g_q[(size_t)MM * NN];
__device__ float g_k[(size_t)MM * NN];
__device__ float g_v[(size_t)MM * NN];
__device__ float g_o[(size_t)MM * NN];

__device__ __nv_bfloat16 g_x_hi[(size_t)MM * KK],  g_x_lo[(size_t)MM * KK];
__device__ __nv_bfloat16 g_wq_hi[(size_t)NN * KK], g_wq_lo[(size_t)NN * KK];
__device__ __nv_bfloat16 g_wk_hi[(size_t)NN * KK], g_wk_lo[(size_t)NN * KK];
__device__ __nv_bfloat16 g_wv_hi[(size_t)NN * KK], g_wv_lo[(size_t)NN * KK];
__device__ __nv_bfloat16 g_wo_hi[(size_t)NN * KK], g_wo_lo[(size_t)NN * KK];
__device__ __nv_bfloat16 g_ao_hi[(size_t)MM * KK], g_ao_lo[(size_t)MM * KK];

__device__ __forceinline__ uint32_t smem_u32(const void* p) {
    uint32_t a;
    asm("{ .reg .u64 t; cvta.to.shared.u64 t, %1; cvt.u32.u64 %0, t; }"
        : "=r"(a) : "l"(p));
    return a;
}

#define LDSM4(r, a)                                                            \
    asm volatile("ldmatrix.sync.aligned.m8n8.x4.shared.b16 {%0,%1,%2,%3}, [%4];" \
                 : "=r"((r)[0]), "=r"((r)[1]), "=r"((r)[2]), "=r"((r)[3])      \
                 : "r"(a))

#define MMA16816(c, a, b0, b1)                                                 \
    asm volatile("mma.sync.aligned.m16n8k16.row.col.f32.bf16.bf16.f32 "        \
                 "{%0,%1,%2,%3},{%4,%5,%6,%7},{%8,%9},{%0,%1,%2,%3};"          \
                 : "+f"((c)[0]), "+f"((c)[1]), "+f"((c)[2]), "+f"((c)[3])      \
                 : "r"((a)[0]), "r"((a)[1]), "r"((a)[2]), "r"((a)[3]),         \
                   "r"(b0), "r"(b1))

#define CPA16(dst, src)                                                        \
    asm volatile("cp.async.cg.shared.global [%0], [%1], 16;"                   \
                 :: "r"(dst), "l"(src) : "memory")

// ============================================================================
// Split: fp32 -> hi (truncated bf16) + lo (rn-bf16 of residual).
// ============================================================================
__global__ __launch_bounds__(256)
void split_kernel(const float4* __restrict__ in, uint2* __restrict__ hi,
                  uint2* __restrict__ lo) {
    size_t i = (size_t)blockIdx.x * 256 + threadIdx.x;
    float4 v = in[i];
    uint32_t ux = __float_as_uint(v.x), uy = __float_as_uint(v.y);
    uint32_t uz = __float_as_uint(v.z), uw = __float_as_uint(v.w);
    uint2 h = make_uint2(__byte_perm(ux, uy, 0x7632), __byte_perm(uz, uw, 0x7632));
    float lx = v.x - __uint_as_float(ux & 0xFFFF0000u);
    float ly = v.y - __uint_as_float(uy & 0xFFFF0000u);
    float lz = v.z - __uint_as_float(uz & 0xFFFF0000u);
    float lw = v.w - __uint_as_float(uw & 0xFFFF0000u);
    uint2 l;
    asm("cvt.rn.bf16x2.f32 %0, %1, %2;" : "=r"(l.x) : "f"(ly), "f"(lx));
    asm("cvt.rn.bf16x2.f32 %0, %1, %2;" : "=r"(l.y) : "f"(lw), "f"(lz));
    hi[i] = h;
    lo[i] = l;
}

// ============================================================================
// GEMM: C[m][n] = sum_k A[m][k]*B[n][k], bf16 hi/lo in, fp32 out.
// CTA tile 128x128, 8 warps (32x64 each), K-chunk 32, 2-stage cp.async.
// SMEM stage: Ahi | Alo | Bhi | Blo, each 128 rows x 32 bf16, pitch 80 B.
// ============================================================================
#define CH 32
#define PITCH 80
#define MAT_B (128 * PITCH)        // 10240 B
#define STAGE_B (4 * MAT_B)        // 40960 B
#define GEMM_SMEM (2 * STAGE_B)    // 81920 B
#define NCH (KK / CH)              // 128

__global__ __launch_bounds__(256, 2)
void gemm_bf16(const __nv_bfloat16* __restrict__ Ahi,
               const __nv_bfloat16* __restrict__ Alo,
               const __nv_bfloat16* __restrict__ Bhi,
               const __nv_bfloat16* __restrict__ Blo,
               float* __restrict__ C, int rotate) {
    extern __shared__ __align__(1024) char sm[];
    const uint32_t wbase = smem_u32(sm);
    const int tid = threadIdx.x;
    const int wid = tid >> 5, lane = tid & 31;
    const int row0 = blockIdx.y * 128, col0 = blockIdx.x * 128;

    // per-thread load coords: 2 rows per matrix (j=0: rows 0-63, j=1: 64-127)
    const int lrow = tid >> 2, lseg = tid & 3;
    const __nv_bfloat16* pAh = Ahi + (size_t)(row0 + lrow) * KK + lseg * 8;
    const __nv_bfloat16* pAl = Alo + (size_t)(row0 + lrow) * KK + lseg * 8;
    const __nv_bfloat16* pBh = Bhi + (size_t)(col0 + lrow) * KK + lseg * 8;
    const __nv_bfloat16* pBl = Blo + (size_t)(col0 + lrow) * KK + lseg * 8;
    const uint32_t doff = (uint32_t)lrow * PITCH + lseg * 16;
    const size_t rstep = (size_t)64 * KK;   // j=1 row offset

#define LOAD_STAGE(chunk, buf)                                                 \
    do {                                                                       \
        const uint32_t sb_ = wbase + (buf) * STAGE_B + doff;                   \
        const size_t ko_ = (size_t)(chunk) * CH;                               \
        CPA16(sb_,                  pAh + ko_);                                \
        CPA16(sb_ + 64 * PITCH,     pAh + ko_ + rstep);                        \
        CPA16(sb_ + MAT_B,          pAl + ko_);                                \
        CPA16(sb_ + MAT_B + 64 * PITCH, pAl + ko_ + rstep);                    \
        CPA16(sb_ + 2 * MAT_B,      pBh + ko_);                                \
        CPA16(sb_ + 2 * MAT_B + 64 * PITCH, pBh + ko_ + rstep);                \
        CPA16(sb_ + 3 * MAT_B,      pBl + ko_);                                \
        CPA16(sb_ + 3 * MAT_B + 64 * PITCH, pBl + ko_ + rstep);                \
        asm volatile("cp.async.commit_group;" ::: "memory");                   \
    } while (0)

    // warp tile origin + ldmatrix lane offsets
    const int wm = (wid & 3) * 32, wn = (wid >> 2) * 64;
    const int l = lane;
    const uint32_t aoff =
        (uint32_t)(wm + (l & 7) + 8 * ((l >> 3) & 1)) * PITCH + (l >> 4) * 16;
    const uint32_t boff =
        (uint32_t)(wn + (l & 7) + 8 * (l >> 4)) * PITCH + ((l >> 3) & 1) * 16;

    float acc[2][8][4];
#pragma unroll
    for (int i = 0; i < 2; i++)
#pragma unroll
        for (int j = 0; j < 8; j++)
#pragma unroll
            for (int q = 0; q < 4; q++) acc[i][j][q] = 0.f;

    LOAD_STAGE(0, 0);

    for (int i = 0; i < NCH; i++) {
        __syncthreads();                       // buf (i+1)&1 free for reload
        if (i + 1 < NCH) {
            LOAD_STAGE(i + 1, (i + 1) & 1);
            asm volatile("cp.async.wait_group 1;" ::: "memory");
        } else {
            asm volatile("cp.async.wait_group 0;" ::: "memory");
        }
        __syncthreads();                       // chunk i data visible to all

        const uint32_t sb = wbase + (i & 1) * STAGE_B;
#pragma unroll
        for (int ks = 0; ks < 2; ks++) {
            uint32_t a_h[2][4], a_l[2][4];
            const uint32_t ka = sb + aoff + ks * 32;
#pragma unroll
            for (int mt = 0; mt < 2; mt++) {
                LDSM4(a_h[mt], ka + mt * 16 * PITCH);
                LDSM4(a_l[mt], ka + mt * 16 * PITCH + MAT_B);
            }
            const uint32_t kb = sb + 2 * MAT_B + boff + ks * 32;
#pragma unroll
            for (int p = 0; p < 4; p++) {
                uint32_t bh[4], bl[4];
                LDSM4(bh, kb + p * 16 * PITCH);
                LDSM4(bl, kb + p * 16 * PITCH + MAT_B);
#pragma unroll
                for (int mt = 0; mt < 2; mt++) {
#pragma unroll
                    for (int q = 0; q < 2; q++) {
                        float* c = acc[mt][2 * p + q];
                        MMA16816(c, a_h[mt], bh[2 * q], bh[2 * q + 1]);
                        MMA16816(c, a_h[mt], bl[2 * q], bl[2 * q + 1]);
                        MMA16816(c, a_l[mt], bh[2 * q], bh[2 * q + 1]);
                    }
                }
            }
        }
    }

    // epilogue: fused rotary + direct global store
    const int mrow = lane >> 2, ncol = 2 * (lane & 3);
#pragma unroll
    for (int mt = 0; mt < 2; mt++) {
#pragma unroll
        for (int part = 0; part < 2; part++) {
            const int m = row0 + wm + mt * 16 + mrow + part * 8;
            float sn = 0.f, cs = 1.f;
            if (rotate) sincosf((float)(m & (TLEN - 1)), &sn, &cs);
            float* crow_p = C + (size_t)m * NN + col0 + wn + ncol;
#pragma unroll
            for (int nt = 0; nt < 8; nt++) {
                float x0 = acc[mt][nt][2 * part];
                float x1 = acc[mt][nt][2 * part + 1];
                float y0 = rotate ? x0 * cs - x1 * sn : x0;
                float y1 = rotate ? x0 * sn + x1 * cs : x1;
                *(float2*)(crow_p + nt * 8) = make_float2(y0, y1);
            }
        }
    }
}

// ============================================================================
// Flash attention (fp32, causal). BQ=BK=64, hd=128.
// Vectorized LDS: rows padded to 132 floats; PV mapping 4 rows x 8 dims.
// ============================================================================
#define BQ 64
#define BK 64
#define HD 128
#define QP 132
#define SSP 65
#define FLASH_FLOATS (3 * 64 * QP + 64 * SSP + 128)
#define FLASH_SMEM_BYTES (FLASH_FLOATS * 4)

__global__ __launch_bounds__(256, 1)
void flash_kernel(const float* __restrict__ Q, const float* __restrict__ K,
                  const float* __restrict__ V, float* __restrict__ O) {
    extern __shared__ float smf[];
    float* sQ = smf;                 // [64][132]
    float* sK = sQ + 64 * QP;        // [64][132]
    float* sV = sK + 64 * QP;        // [64][132]
    float* sS = sV + 64 * QP;        // [64][65]
    float* sAl = sS + 64 * SSP;      // [64]
    float* sL  = sAl + 64;           // [64]

    const int tid = threadIdx.x;
    const int bh = blockIdx.y;
    const int b = bh >> 5, h = bh & 31;
    const int qb = blockIdx.x;
    const int q0 = qb * BQ;
    const float scale = 0.08838834764831845f;

    const size_t base = ((size_t)b * TLEN) * NN + (size_t)h * HD;

    // load Q tile
    for (int v = tid; v < BQ * (HD / 4); v += 256) {
        int r = v >> 5, c = v & 31;
        *(float4*)(sQ + r * QP + 4 * c) =
            ((const float4*)(Q + base + (size_t)(q0 + r) * NN))[c];
    }

    const int r   = tid >> 2;      // softmax: row 0..63
    const int sub = tid & 3;       // 4 threads/row
    const int tr  = tid >> 4;      // S: row group 0..15
    const int tc  = tid & 15;      // S: col group 0..15
    const int rg  = tid >> 4;      // PV: rows 4rg..4rg+3
    const int cg  = tid & 15;      // PV: cols 8cg..8cg+7

    float m_i = -INFINITY, l_i = 0.f;
    float acc[4][8];
#pragma unroll
    for (int i = 0; i < 4; i++)
#pragma unroll
        for (int j = 0; j < 8; j++) acc[i][j] = 0.f;

    for (int kt = 0; kt <= qb; kt++) {
        const int k0 = kt * BK;
        __syncthreads();   // prior PV reads of sV/sS done

        for (int v = tid; v < BK * (HD / 4); v += 256) {
            int rr = v >> 5, c = v & 31;
            *(float4*)(sK + rr * QP + 4 * c) =
                ((const float4*)(K + base + (size_t)(k0 + rr) * NN))[c];
        }
        for (int v = tid; v < BK * (HD / 4); v += 256) {
            int rr = v >> 5, c = v & 31;
            *(float4*)(sV + rr * QP + 4 * c) =
                ((const float4*)(V + base + (size_t)(k0 + rr) * NN))[c];
        }
        __syncthreads();

        // S = scale * Q K^T (vector LDS along d)
        float s[4][4];
#pragma unroll
        for (int i = 0; i < 4; i++)
#pragma unroll
            for (int j = 0; j < 4; j++) s[i][j] = 0.f;

        for (int d4 = 0; d4 < HD / 4; d4++) {
            float4 qv[4], kv[4];
#pragma unroll
            for (int i = 0; i < 4; i++)
                qv[i] = *(const float4*)(sQ + (4 * tr + i) * QP + 4 * d4);
#pragma unroll
            for (int j = 0; j < 4; j++)
                kv[j] = *(const float4*)(sK + (4 * tc + j) * QP + 4 * d4);
#pragma unroll
            for (int i = 0; i < 4; i++)
#pragma unroll
                for (int j = 0; j < 4; j++) {
                    s[i][j] = fmaf(qv[i].x, kv[j].x, s[i][j]);
                    s[i][j] = fmaf(qv[i].y, kv[j].y, s[i][j]);
                    s[i][j] = fmaf(qv[i].z, kv[j].z, s[i][j]);
                    s[i][j] = fmaf(qv[i].w, kv[j].w, s[i][j]);
                }
        }
#pragma unroll
        for (int i = 0; i < 4; i++)
#pragma unroll
            for (int j = 0; j < 4; j++) {
                float val = s[i][j] * scale;
                if (kt == qb && (4 * tc + j) > (4 * tr + i)) val = -INFINITY;
                sS[(4 * tr + i) * SSP + 4 * tc + j] = val;
            }
        __syncthreads();

        // online softmax (4 threads per row)
        float mymax = -INFINITY;
#pragma unroll
        for (int j = 0; j < 16; j++)
            mymax = fmaxf(mymax, sS[r * SSP + sub * 16 + j]);
        mymax = fmaxf(mymax, __shfl_xor_sync(0xffffffff, mymax, 1));
        mymax = fmaxf(mymax, __shfl_xor_sync(0xffffffff, mymax, 2));

        float m_new = fmaxf(m_i, mymax);
        float alpha = __expf(m_i - m_new);

        float mysum = 0.f;
#pragma unroll
        for (int j = 0; j < 16; j++) {
            int idx = r * SSP + sub * 16 + j;
            float p = __expf(sS[idx] - m_new);
            sS[idx] = p;
            mysum += p;
        }
        __syncwarp();
        mysum += __shfl_xor_sync(0xffffffff, mysum, 1);
        mysum += __shfl_xor_sync(0xffffffff, mysum, 2);

        l_i = l_i * alpha + mysum;
        m_i = m_new;
        if (sub == 0) sAl[r] = alpha;
        __syncthreads();

        // PV: thread owns rows 4rg..+3, cols 8cg..+7
        float al[4];
#pragma unroll
        for (int i = 0; i < 4; i++) al[i] = sAl[4 * rg + i];
#pragma unroll
        for (int i = 0; i < 4; i++)
#pragma unroll
            for (int j = 0; j < 8; j++) acc[i][j] *= al[i];

        for (int j = 0; j < BK; j++) {
            float4 v0 = *(const float4*)(sV + j * QP + 8 * cg);
            float4 v1 = *(const float4*)(sV + j * QP + 8 * cg + 4);
            float p[4];
#pragma unroll
            for (int i = 0; i < 4; i++) p[i] = sS[(4 * rg + i) * SSP + j];
#pragma unroll
            for (int i = 0; i < 4; i++) {
                acc[i][0] = fmaf(p[i], v0.x, acc[i][0]);
                acc[i][1] = fmaf(p[i], v0.y, acc[i][1]);
                acc[i][2] = fmaf(p[i], v0.z, acc[i][2]);
                acc[i][3] = fmaf(p[i], v0.w, acc[i][3]);
                acc[i][4] = fmaf(p[i], v1.x, acc[i][4]);
                acc[i][5] = fmaf(p[i], v1.y, acc[i][5]);
                acc[i][6] = fmaf(p[i], v1.z, acc[i][6]);
                acc[i][7] = fmaf(p[i], v1.w, acc[i][7]);
            }
        }
    }

    if (sub == 0) sL[r] = l_i;
    __syncthreads();

#pragma unroll
    for (int i = 0; i < 4; i++) {
        float inv = 1.f / sL[4 * rg + i];
        float* op = O + base + (size_t)(q0 + 4 * rg + i) * NN + 8 * cg;
        *(float4*)op = make_float4(acc[i][0] * inv, acc[i][1] * inv,
                                   acc[i][2] * inv, acc[i][3] * inv);
        *(float4*)(op + 4) = make_float4(acc[i][4] * inv, acc[i][5] * inv,
                                         acc[i][6] * inv, acc[i][7] * inv);
    }
}

// ============================================================================
// Launch
// ============================================================================
extern "C" void kernel_launch(void* const* d_in, const int* in_sizes, int n_in,
                              void* d_out, int out_size) {
    const float* x  = (const float*)d_in[0];
    const float* wq = (const float*)d_in[1];
    const float* wk = (const float*)d_in[2];
    const float* wv = (const float*)d_in[3];
    const float* wo = (const float*)d_in[4];
    float* out = (float*)d_out;

    float *pq, *pk, *pv, *po;
    cudaGetSymbolAddress((void**)&pq, g_q);
    cudaGetSymbolAddress((void**)&pk, g_k);
    cudaGetSymbolAddress((void**)&pv, g_v);
    cudaGetSymbolAddress((void**)&po, g_o);

    __nv_bfloat16 *xh, *xl, *qh, *ql, *kh, *kl, *vh, *vl, *oh, *ol, *ah, *al;
    cudaGetSymbolAddress((void**)&xh, g_x_hi);  cudaGetSymbolAddress((void**)&xl, g_x_lo);
    cudaGetSymbolAddress((void**)&qh, g_wq_hi); cudaGetSymbolAddress((void**)&ql, g_wq_lo);
    cudaGetSymbolAddress((void**)&kh, g_wk_hi); cudaGetSymbolAddress((void**)&kl, g_wk_lo);
    cudaGetSymbolAddress((void**)&vh, g_wv_hi); cudaGetSymbolAddress((void**)&vl, g_wv_lo);
    cudaGetSymbolAddress((void**)&oh, g_wo_hi); cudaGetSymbolAddress((void**)&ol, g_wo_lo);
    cudaGetSymbolAddress((void**)&ah, g_ao_hi); cudaGetSymbolAddress((void**)&al, g_ao_lo);

    cudaFuncSetAttribute(gemm_bf16, cudaFuncAttributeMaxDynamicSharedMemorySize,
                         GEMM_SMEM);
    cudaFuncSetAttribute(flash_kernel,
                         cudaFuncAttributeMaxDynamicSharedMemorySize,
                         FLASH_SMEM_BYTES);

    const int splitBlocks = (MM * 4096) / (4 * 256);   // 16384

    split_kernel<<<splitBlocks, 256>>>((const float4*)x,  (uint2*)xh, (uint2*)xl);
    split_kernel<<<splitBlocks, 256>>>((const float4*)wq, (uint2*)qh, (uint2*)ql);
    split_kernel<<<splitBlocks, 256>>>((const float4*)wk, (uint2*)kh, (uint2*)kl);
    split_kernel<<<splitBlocks, 256>>>((const float4*)wv, (uint2*)vh, (uint2*)vl);
    split_kernel<<<splitBlocks, 256>>>((const float4*)wo, (uint2*)oh, (uint2*)ol);

    dim3 ggrid(NN / 128, MM / 128);   // (32, 32)
    gemm_bf16<<<ggrid, 256, GEMM_SMEM>>>(xh, xl, qh, ql, pq, 1);
    gemm_bf16<<<ggrid, 256, GEMM_SMEM>>>(xh, xl, kh, kl, pk, 1);
    gemm_bf16<<<ggrid, 256, GEMM_SMEM>>>(xh, xl, vh, vl, pv, 0);

    dim3 fgrid(TLEN / BQ, 2 * 32);    // (32, 64)
    flash_kernel<<<fgrid, 256, FLASH_SMEM_BYTES>>>(pq, pk, pv, po);

    split_kernel<<<splitBlocks, 256>>>((const float4*)po, (uint2*)ah, (uint2*)al);
    gemm_bf16<<<ggrid, 256, GEMM_SMEM>>>(ah, al, oh, ol, out, 0);
}

// round 5
// speedup vs baseline: 2.8454x; 1.0855x over previous
#include <cuda_runtime.h>
#include <cuda_bf16.h>
#include <cstdint>
#include <math.h>

// ----------------------------------------------------------------------------
// B=2, T=2048, C=4096, H=32, hd=128.  M=N=K=4096.
// All heavy math on HMMA (mma.sync bf16) with split-bf16 3-product trick:
//   X*Y ~= Xh*Yh + Xh*Yl + Xl*Yh  (fp32 accum), rel err ~1e-5.
// Rotary (theta = t, adjacent col pairs) fused in Q/K GEMM epilogue.
// Flash attention fully on HMMA; P kept in registers (C-frag == A-frag trick).
// ----------------------------------------------------------------------------

#define MM 4096
#define NN 4096
#define KK 4096
#define TLEN 2048

// bf16 hi/lo operand storage
__device__ __nv_bfloat16 g_x_hi[(size_t)MM * KK],  g_x_lo[(size_t)MM * KK];
__device__ __nv_bfloat16 g_wq_hi[(size_t)NN * KK], g_wq_lo[(size_t)NN * KK];
__device__ __nv_bfloat16 g_wk_hi[(size_t)NN * KK], g_wk_lo[(size_t)NN * KK];
__device__ __nv_bfloat16 g_wv_hi[(size_t)NN * KK], g_wv_lo[(size_t)NN * KK];
__device__ __nv_bfloat16 g_wo_hi[(size_t)NN * KK], g_wo_lo[(size_t)NN * KK];
__device__ __nv_bfloat16 g_qa_hi[(size_t)MM * NN], g_qa_lo[(size_t)MM * NN];
__device__ __nv_bfloat16 g_ka_hi[(size_t)MM * NN], g_ka_lo[(size_t)MM * NN];
__device__ __nv_bfloat16 g_va_hi[(size_t)MM * NN], g_va_lo[(size_t)MM * NN];
__device__ __nv_bfloat16 g_ao_hi[(size_t)MM * NN], g_ao_lo[(size_t)MM * NN];

__device__ __forceinline__ uint32_t smem_u32(const void* p) {
    uint32_t a;
    asm("{ .reg .u64 t; cvta.to.shared.u64 t, %1; cvt.u32.u64 %0, t; }"
        : "=r"(a) : "l"(p));
    return a;
}

#define LDSM4(r, a)                                                            \
    asm volatile("ldmatrix.sync.aligned.m8n8.x4.shared.b16 {%0,%1,%2,%3}, [%4];" \
                 : "=r"((r)[0]), "=r"((r)[1]), "=r"((r)[2]), "=r"((r)[3])      \
                 : "r"(a))

#define LDSM4T(r, a)                                                           \
    asm volatile("ldmatrix.sync.aligned.m8n8.x4.trans.shared.b16 {%0,%1,%2,%3}, [%4];" \
                 : "=r"((r)[0]), "=r"((r)[1]), "=r"((r)[2]), "=r"((r)[3])      \
                 : "r"(a))

#define MMA16816(c, a, b0, b1)                                                 \
    asm volatile("mma.sync.aligned.m16n8k16.row.col.f32.bf16.bf16.f32 "        \
                 "{%0,%1,%2,%3},{%4,%5,%6,%7},{%8,%9},{%0,%1,%2,%3};"          \
                 : "+f"((c)[0]), "+f"((c)[1]), "+f"((c)[2]), "+f"((c)[3])      \
                 : "r"((a)[0]), "r"((a)[1]), "r"((a)[2]), "r"((a)[3]),         \
                   "r"(b0), "r"(b1))

#define CPA16(dst, src)                                                        \
    asm volatile("cp.async.cg.shared.global [%0], [%1], 16;"                   \
                 :: "r"(dst), "l"(src) : "memory")

// split two fp32 into packed bf16 hi (truncate) + lo (rn of residual)
__device__ __forceinline__ void split2(float x0, float x1,
                                       uint32_t& hi, uint32_t& lo) {
    uint32_t u0 = __float_as_uint(x0), u1 = __float_as_uint(x1);
    hi = __byte_perm(u0, u1, 0x7632);
    float l0 = x0 - __uint_as_float(u0 & 0xFFFF0000u);
    float l1 = x1 - __uint_as_float(u1 & 0xFFFF0000u);
    asm("cvt.rn.bf16x2.f32 %0, %1, %2;" : "=r"(lo) : "f"(l1), "f"(l0));
}

// ============================================================================
// Split kernel: fp32 -> hi/lo bf16 (for x and the 4 weight matrices)
// ============================================================================
__global__ __launch_bounds__(256)
void split_kernel(const float4* __restrict__ in, uint2* __restrict__ hi,
                  uint2* __restrict__ lo) {
    size_t i = (size_t)blockIdx.x * 256 + threadIdx.x;
    float4 v = in[i];
    uint2 h, l;
    split2(v.x, v.y, h.x, l.x);
    split2(v.z, v.w, h.y, l.y);
    hi[i] = h;
    lo[i] = l;
}

// ============================================================================
// GEMM: C[m][n] = sum_k A[m][k]*B[n][k].  bf16 hi/lo in.
// CTA 256x128, 8 warps (64x64), K-chunk 32, 2-stage cp.async, 1 CTA/SM.
// mode 0: fp32 store; 1: rotary+split bf16 store; 2: split bf16 store.
// ============================================================================
#define PITCH 80
#define SA_H 0
#define SA_L 20480
#define SB_H 40960
#define SB_L 51200
#define STAGE_B 61440
#define GEMM_SMEM (2 * STAGE_B)
#define NCH (KK / 32)   // 128

__global__ __launch_bounds__(256, 1)
void gemm_bf16(const __nv_bfloat16* __restrict__ Ahi,
               const __nv_bfloat16* __restrict__ Alo,
               const __nv_bfloat16* __restrict__ Bhi,
               const __nv_bfloat16* __restrict__ Blo,
               float* __restrict__ Cf,
               __nv_bfloat16* __restrict__ Chi,
               __nv_bfloat16* __restrict__ Clo,
               int mode) {
    extern __shared__ __align__(1024) char sm[];
    const uint32_t smb = smem_u32(sm);
    const int tid = threadIdx.x;
    const int wid = tid >> 5, lane = tid & 31;
    const int row0 = blockIdx.y * 256, col0 = blockIdx.x * 128;

    // loads: thread t -> A row t (hi+lo, 4 chunks each); B row t&127 (hi or lo)
    const __nv_bfloat16* pAh = Ahi + (size_t)(row0 + tid) * KK;
    const __nv_bfloat16* pAl = Alo + (size_t)(row0 + tid) * KK;
    const __nv_bfloat16* pB =
        (tid < 128 ? Bhi : Blo) + (size_t)(col0 + (tid & 127)) * KK;
    const uint32_t adst = smb + tid * PITCH;
    const uint32_t bdst = smb + (tid < 128 ? SB_H : SB_L) + (tid & 127) * PITCH;

#define G_LOAD(chunk, buf)                                                     \
    do {                                                                       \
        const uint32_t so_ = (buf) * STAGE_B;                                  \
        const size_t ko_ = (size_t)(chunk) * 32;                               \
        CPA16(adst + so_,            pAh + ko_);                               \
        CPA16(adst + so_ + 16,       pAh + ko_ + 8);                           \
        CPA16(adst + so_ + 32,       pAh + ko_ + 16);                          \
        CPA16(adst + so_ + 48,       pAh + ko_ + 24);                          \
        CPA16(adst + so_ + SA_L,      pAl + ko_);                              \
        CPA16(adst + so_ + SA_L + 16, pAl + ko_ + 8);                          \
        CPA16(adst + so_ + SA_L + 32, pAl + ko_ + 16);                         \
        CPA16(adst + so_ + SA_L + 48, pAl + ko_ + 24);                         \
        CPA16(bdst + so_,            pB + ko_);                                \
        CPA16(bdst + so_ + 16,       pB + ko_ + 8);                            \
        CPA16(bdst + so_ + 32,       pB + ko_ + 16);                           \
        CPA16(bdst + so_ + 48,       pB + ko_ + 24);                           \
        asm volatile("cp.async.commit_group;" ::: "memory");                   \
    } while (0)

    const int wm = (wid & 3) * 64, wn = (wid >> 2) * 64;
    const int l = lane;
    const uint32_t aoff =
        (uint32_t)(wm + (l & 7) + 8 * ((l >> 3) & 1)) * PITCH + (l >> 4) * 16;
    const uint32_t boff = SB_H +
        (uint32_t)(wn + (l & 7) + 8 * (l >> 4)) * PITCH + ((l >> 3) & 1) * 16;

    float acc[4][8][4];
#pragma unroll
    for (int i = 0; i < 4; i++)
#pragma unroll
        for (int j = 0; j < 8; j++)
#pragma unroll
            for (int q = 0; q < 4; q++) acc[i][j][q] = 0.f;

    G_LOAD(0, 0);

    for (int i = 0; i < NCH; i++) {
        __syncthreads();
        if (i + 1 < NCH) {
            G_LOAD(i + 1, (i + 1) & 1);
            asm volatile("cp.async.wait_group 1;" ::: "memory");
        } else {
            asm volatile("cp.async.wait_group 0;" ::: "memory");
        }
        __syncthreads();

        const uint32_t sb = smb + (i & 1) * STAGE_B;
#pragma unroll
        for (int ks = 0; ks < 2; ks++) {
            uint32_t a_h[4][4], a_l[4][4];
            const uint32_t ka = sb + aoff + ks * 32;
#pragma unroll
            for (int mt = 0; mt < 4; mt++) {
                LDSM4(a_h[mt], ka + mt * 16 * PITCH);
                LDSM4(a_l[mt], ka + mt * 16 * PITCH + SA_L);
            }
            const uint32_t kb = sb + boff + ks * 32;
#pragma unroll
            for (int p = 0; p < 4; p++) {
                uint32_t bh[4], bl[4];
                LDSM4(bh, kb + p * 16 * PITCH);
                LDSM4(bl, kb + p * 16 * PITCH + (SB_L - SB_H));
                // product-major ordering: each acc touched every 8 MMAs
#pragma unroll
                for (int mt = 0; mt < 4; mt++) {
                    MMA16816(acc[mt][2 * p],     a_h[mt], bh[0], bh[1]);
                    MMA16816(acc[mt][2 * p + 1], a_h[mt], bh[2], bh[3]);
                }
#pragma unroll
                for (int mt = 0; mt < 4; mt++) {
                    MMA16816(acc[mt][2 * p],     a_h[mt], bl[0], bl[1]);
                    MMA16816(acc[mt][2 * p + 1], a_h[mt], bl[2], bl[3]);
                }
#pragma unroll
                for (int mt = 0; mt < 4; mt++) {
                    MMA16816(acc[mt][2 * p],     a_l[mt], bh[0], bh[1]);
                    MMA16816(acc[mt][2 * p + 1], a_l[mt], bh[2], bh[3]);
                }
            }
        }
    }

    // epilogue
    const int mrow = lane >> 2, ncol = 2 * (lane & 3);
#pragma unroll
    for (int mt = 0; mt < 4; mt++) {
#pragma unroll
        for (int part = 0; part < 2; part++) {
            const int m = row0 + wm + mt * 16 + mrow + part * 8;
            float sn = 0.f, cs = 1.f;
            if (mode == 1) sincosf((float)(m & (TLEN - 1)), &sn, &cs);
            const size_t rowb = (size_t)m * NN + col0 + wn + ncol;
#pragma unroll
            for (int nt = 0; nt < 8; nt++) {
                float x0 = acc[mt][nt][2 * part];
                float x1 = acc[mt][nt][2 * part + 1];
                float y0 = (mode == 1) ? x0 * cs - x1 * sn : x0;
                float y1 = (mode == 1) ? x0 * sn + x1 * cs : x1;
                if (mode == 0) {
                    *(float2*)(Cf + rowb + nt * 8) = make_float2(y0, y1);
                } else {
                    uint32_t hi, lo;
                    split2(y0, y1, hi, lo);
                    *(uint32_t*)(Chi + rowb + nt * 8) = hi;
                    *(uint32_t*)(Clo + rowb + nt * 8) = lo;
                }
            }
        }
    }
}

// ============================================================================
// Flash attention on HMMA. BQ=BK=64, hd=128. 128 threads (4 warps x 16 rows).
// Q,K,V in smem as bf16 hi/lo (pitch 272B). P in registers via C->A frag trick.
// ============================================================================
#define FP 272
#define FQH 0
#define FQL 17408
#define FKH 34816
#define FKL 52224
#define FVH 69632
#define FVL 87040
#define FLASH_SMEM 104448

__global__ __launch_bounds__(128, 2)
void flash_mma(const __nv_bfloat16* __restrict__ Qh, const __nv_bfloat16* __restrict__ Ql,
               const __nv_bfloat16* __restrict__ Kh, const __nv_bfloat16* __restrict__ Kl,
               const __nv_bfloat16* __restrict__ Vh, const __nv_bfloat16* __restrict__ Vl,
               __nv_bfloat16* __restrict__ Oh, __nv_bfloat16* __restrict__ Ol) {
    extern __shared__ __align__(1024) char sm[];
    const uint32_t smb = smem_u32(sm);
    const int tid = threadIdx.x;
    const int wid = tid >> 5, lane = tid & 31;
    const int bh = blockIdx.y;
    const int b = bh >> 5, h = bh & 31;
    const int qb = blockIdx.x;
    const int q0 = qb * 64;
    const float scale = 0.08838834764831845f;

    const size_t gbase = ((size_t)b * TLEN) * NN + (size_t)h * 128;

    // load Q (hi/lo): thread -> row tid>>1, 8 chunks of 16B in half (tid&1)
    {
        const int qr = tid >> 1, qc = (tid & 1) * 8;
        const size_t gq = gbase + (size_t)(q0 + qr) * NN + qc * 8;
        const uint32_t sq = smb + qr * FP + qc * 16;
#pragma unroll
        for (int c = 0; c < 8; c++) {
            CPA16(sq + FQH + c * 16, Qh + gq + c * 8);
            CPA16(sq + FQL + c * 16, Ql + gq + c * 8);
        }
        asm volatile("cp.async.commit_group;" ::: "memory");
    }

    const int wm = wid * 16;
    const int l = lane;
    const uint32_t aoff =
        (uint32_t)(wm + (l & 7) + 8 * ((l >> 3) & 1)) * FP + (l >> 4) * 16;
    const uint32_t boff =
        (uint32_t)((l & 7) + 8 * (l >> 4)) * FP + ((l >> 3) & 1) * 16;
    const uint32_t voff =
        (uint32_t)((l & 7) + 8 * ((l >> 3) & 1)) * FP + (l >> 4) * 16;

    float o[16][4];
#pragma unroll
    for (int i = 0; i < 16; i++)
#pragma unroll
        for (int j = 0; j < 4; j++) o[i][j] = 0.f;
    float m0 = -INFINITY, m1 = -INFINITY, l0 = 0.f, l1 = 0.f;

    const int grow0 = q0 + wm + (lane >> 2);
    const int grow1 = grow0 + 8;

    for (int kt = 0; kt <= qb; kt++) {
        const int k0 = kt * 64;
        __syncthreads();   // prior tile's smem reads done

        {
            const int kr = tid >> 1, kc = (tid & 1) * 8;
            const size_t gk = gbase + (size_t)(k0 + kr) * NN + kc * 8;
            const uint32_t sk = smb + kr * FP + kc * 16;
#pragma unroll
            for (int c = 0; c < 8; c++) {
                CPA16(sk + FKH + c * 16, Kh + gk + c * 8);
                CPA16(sk + FKL + c * 16, Kl + gk + c * 8);
                CPA16(sk + FVH + c * 16, Vh + gk + c * 8);
                CPA16(sk + FVL + c * 16, Vl + gk + c * 8);
            }
            asm volatile("cp.async.commit_group;" ::: "memory");
            asm volatile("cp.async.wait_group 0;" ::: "memory");
        }
        __syncthreads();

        // ---- S = Q K^T (3-product split) ----
        float s[8][4];
#pragma unroll
        for (int i = 0; i < 8; i++)
#pragma unroll
            for (int j = 0; j < 4; j++) s[i][j] = 0.f;

#pragma unroll
        for (int ks = 0; ks < 8; ks++) {
            uint32_t qh4[4], ql4[4];
            LDSM4(qh4, smb + FQH + aoff + ks * 32);
            LDSM4(ql4, smb + FQL + aoff + ks * 32);
#pragma unroll
            for (int p = 0; p < 4; p++) {
                uint32_t kh4[4], kl4[4];
                LDSM4(kh4, smb + FKH + boff + p * 16 * FP + ks * 32);
                LDSM4(kl4, smb + FKL + boff + p * 16 * FP + ks * 32);
                MMA16816(s[2 * p],     qh4, kh4[0], kh4[1]);
                MMA16816(s[2 * p + 1], qh4, kh4[2], kh4[3]);
                MMA16816(s[2 * p],     qh4, kl4[0], kl4[1]);
                MMA16816(s[2 * p + 1], qh4, kl4[2], kl4[3]);
                MMA16816(s[2 * p],     ql4, kh4[0], kh4[1]);
                MMA16816(s[2 * p + 1], ql4, kh4[2], kh4[3]);
            }
        }

        // ---- mask + scale ----
        if (kt == qb) {
#pragma unroll
            for (int nt = 0; nt < 8; nt++) {
                const int cbase = k0 + nt * 8 + 2 * (lane & 3);
                s[nt][0] = (cbase     > grow0) ? -INFINITY : s[nt][0] * scale;
                s[nt][1] = (cbase + 1 > grow0) ? -INFINITY : s[nt][1] * scale;
                s[nt][2] = (cbase     > grow1) ? -INFINITY : s[nt][2] * scale;
                s[nt][3] = (cbase + 1 > grow1) ? -INFINITY : s[nt][3] * scale;
            }
        } else {
#pragma unroll
            for (int nt = 0; nt < 8; nt++)
#pragma unroll
                for (int e = 0; e < 4; e++) s[nt][e] *= scale;
        }

        // ---- online softmax ----
        float rmax0 = -INFINITY, rmax1 = -INFINITY;
#pragma unroll
        for (int nt = 0; nt < 8; nt++) {
            rmax0 = fmaxf(rmax0, fmaxf(s[nt][0], s[nt][1]));
            rmax1 = fmaxf(rmax1, fmaxf(s[nt][2], s[nt][3]));
        }
        rmax0 = fmaxf(rmax0, __shfl_xor_sync(0xffffffff, rmax0, 1));
        rmax0 = fmaxf(rmax0, __shfl_xor_sync(0xffffffff, rmax0, 2));
        rmax1 = fmaxf(rmax1, __shfl_xor_sync(0xffffffff, rmax1, 1));
        rmax1 = fmaxf(rmax1, __shfl_xor_sync(0xffffffff, rmax1, 2));

        const float mn0 = fmaxf(m0, rmax0), mn1 = fmaxf(m1, rmax1);
        const float a0 = __expf(m0 - mn0), a1 = __expf(m1 - mn1);

        float sum0 = 0.f, sum1 = 0.f;
#pragma unroll
        for (int nt = 0; nt < 8; nt++) {
            s[nt][0] = __expf(s[nt][0] - mn0);
            s[nt][1] = __expf(s[nt][1] - mn0);
            s[nt][2] = __expf(s[nt][2] - mn1);
            s[nt][3] = __expf(s[nt][3] - mn1);
            sum0 += s[nt][0] + s[nt][1];
            sum1 += s[nt][2] + s[nt][3];
        }
        sum0 += __shfl_xor_sync(0xffffffff, sum0, 1);
        sum0 += __shfl_xor_sync(0xffffffff, sum0, 2);
        sum1 += __shfl_xor_sync(0xffffffff, sum1, 1);
        sum1 += __shfl_xor_sync(0xffffffff, sum1, 2);

        l0 = l0 * a0 + sum0;
        l1 = l1 * a1 + sum1;
        m0 = mn0;
        m1 = mn1;

#pragma unroll
        for (int nt = 0; nt < 16; nt++) {
            o[nt][0] *= a0; o[nt][1] *= a0;
            o[nt][2] *= a1; o[nt][3] *= a1;
        }

        // ---- pack P to A-frags (hi/lo) ----
        uint32_t ph[4][4], pl[4][4];
#pragma unroll
        for (int ks2 = 0; ks2 < 4; ks2++) {
            split2(s[2 * ks2][0],     s[2 * ks2][1],     ph[ks2][0], pl[ks2][0]);
            split2(s[2 * ks2][2],     s[2 * ks2][3],     ph[ks2][1], pl[ks2][1]);
            split2(s[2 * ks2 + 1][0], s[2 * ks2 + 1][1], ph[ks2][2], pl[ks2][2]);
            split2(s[2 * ks2 + 1][2], s[2 * ks2 + 1][3], ph[ks2][3], pl[ks2][3]);
        }

        // ---- O += P V (3-product split), V via ldmatrix.trans ----
#pragma unroll
        for (int ks2 = 0; ks2 < 4; ks2++) {
#pragma unroll
            for (int ntp = 0; ntp < 8; ntp++) {
                uint32_t vh4[4], vl4[4];
                const uint32_t va = smb + voff + ks2 * 16 * FP + ntp * 32;
                LDSM4T(vh4, va + FVH);
                LDSM4T(vl4, va + FVL);
                MMA16816(o[2 * ntp],     ph[ks2], vh4[0], vh4[1]);
                MMA16816(o[2 * ntp + 1], ph[ks2], vh4[2], vh4[3]);
                MMA16816(o[2 * ntp],     ph[ks2], vl4[0], vl4[1]);
                MMA16816(o[2 * ntp + 1], ph[ks2], vl4[2], vl4[3]);
                MMA16816(o[2 * ntp],     pl[ks2], vh4[0], vh4[1]);
                MMA16816(o[2 * ntp + 1], pl[ks2], vh4[2], vh4[3]);
            }
        }
    }

    // ---- epilogue: normalize, split to hi/lo bf16, store ----
    const float inv0 = 1.f / l0, inv1 = 1.f / l1;
    const size_t rb0 = gbase + (size_t)grow0 * NN + 2 * (lane & 3);
    const size_t rb1 = gbase + (size_t)grow1 * NN + 2 * (lane & 3);
#pragma unroll
    for (int nt = 0; nt < 16; nt++) {
        uint32_t hi, lo;
        split2(o[nt][0] * inv0, o[nt][1] * inv0, hi, lo);
        *(uint32_t*)(Oh + rb0 + nt * 8) = hi;
        *(uint32_t*)(Ol + rb0 + nt * 8) = lo;
        split2(o[nt][2] * inv1, o[nt][3] * inv1, hi, lo);
        *(uint32_t*)(Oh + rb1 + nt * 8) = hi;
        *(uint32_t*)(Ol + rb1 + nt * 8) = lo;
    }
}

// ============================================================================
// Launch
// ============================================================================
extern "C" void kernel_launch(void* const* d_in, const int* in_sizes, int n_in,
                              void* d_out, int out_size) {
    const float* x  = (const float*)d_in[0];
    const float* wq = (const float*)d_in[1];
    const float* wk = (const float*)d_in[2];
    const float* wv = (const float*)d_in[3];
    const float* wo = (const float*)d_in[4];
    float* out = (float*)d_out;

    __nv_bfloat16 *xh, *xl, *qwh, *qwl, *kwh, *kwl, *vwh, *vwl, *owh, *owl;
    __nv_bfloat16 *qah, *qal, *kah, *kal, *vah, *val_, *aoh, *aol;
    cudaGetSymbolAddress((void**)&xh, g_x_hi);   cudaGetSymbolAddress((void**)&xl, g_x_lo);
    cudaGetSymbolAddress((void**)&qwh, g_wq_hi); cudaGetSymbolAddress((void**)&qwl, g_wq_lo);
    cudaGetSymbolAddress((void**)&kwh, g_wk_hi); cudaGetSymbolAddress((void**)&kwl, g_wk_lo);
    cudaGetSymbolAddress((void**)&vwh, g_wv_hi); cudaGetSymbolAddress((void**)&vwl, g_wv_lo);
    cudaGetSymbolAddress((void**)&owh, g_wo_hi); cudaGetSymbolAddress((void**)&owl, g_wo_lo);
    cudaGetSymbolAddress((void**)&qah, g_qa_hi); cudaGetSymbolAddress((void**)&qal, g_qa_lo);
    cudaGetSymbolAddress((void**)&kah, g_ka_hi); cudaGetSymbolAddress((void**)&kal, g_ka_lo);
    cudaGetSymbolAddress((void**)&vah, g_va_hi); cudaGetSymbolAddress((void**)&val_, g_va_lo);
    cudaGetSymbolAddress((void**)&aoh, g_ao_hi); cudaGetSymbolAddress((void**)&aol, g_ao_lo);

    cudaFuncSetAttribute(gemm_bf16, cudaFuncAttributeMaxDynamicSharedMemorySize,
                         GEMM_SMEM);
    cudaFuncSetAttribute(flash_mma, cudaFuncAttributeMaxDynamicSharedMemorySize,
                         FLASH_SMEM);

    const int splitBlocks = (MM * 4096) / (4 * 256);   // 16384
    split_kernel<<<splitBlocks, 256>>>((const float4*)x,  (uint2*)xh, (uint2*)xl);
    split_kernel<<<splitBlocks, 256>>>((const float4*)wq, (uint2*)qwh, (uint2*)qwl);
    split_kernel<<<splitBlocks, 256>>>((const float4*)wk, (uint2*)kwh, (uint2*)kwl);
    split_kernel<<<splitBlocks, 256>>>((const float4*)wv, (uint2*)vwh, (uint2*)vwl);
    split_kernel<<<splitBlocks, 256>>>((const float4*)wo, (uint2*)owh, (uint2*)owl);

    dim3 ggrid(NN / 128, MM / 256);   // (32, 16)
    gemm_bf16<<<ggrid, 256, GEMM_SMEM>>>(xh, xl, qwh, qwl, nullptr, qah, qal, 1);
    gemm_bf16<<<ggrid, 256, GEMM_SMEM>>>(xh, xl, kwh, kwl, nullptr, kah, kal, 1);
    gemm_bf16<<<ggrid, 256, GEMM_SMEM>>>(xh, xl, vwh, vwl, nullptr, vah, val_, 2);

    dim3 fgrid(TLEN / 64, 2 * 32);    // (32, 64)
    flash_mma<<<fgrid, 128, FLASH_SMEM>>>(qah, qal, kah, kal, vah, val_, aoh, aol);

    gemm_bf16<<<ggrid, 256, GEMM_SMEM>>>(aoh, aol, owh, owl, out, nullptr, nullptr, 0);
}

// round 6
// speedup vs baseline: 4.6858x; 1.6468x over previous
#include <cuda_runtime.h>
#include <cuda_bf16.h>
#include <cuda_fp16.h>
#include <cstdint>
#include <math.h>

// ----------------------------------------------------------------------------
// B=2, T=2048, C=4096, H=32, hd=128.  M=N=K=4096.
// Precision tiers:
//   softmax-amplified path (x->Q, x->K, S=QK^T): bf16 HMMA 3-product split.
//   linear path (x->V, P*V, attn-out, out=ao*Wo^T): fp16 HMMA 2-product
//     (A = rn-fp16 of A, B = Bh+Bl fp16; dropped Al*B ~ 2^-12 incoherent).
// Rotary (theta = t, adjacent pairs) fused in Q/K GEMM epilogue.
// GEMM topology: 128x128 CTA tile, 8 warps 32x64, K-chunk 32, 2-stage
// cp.async, 2 CTAs/SM (empirically fastest config from round 4).
// ----------------------------------------------------------------------------

#define MM 4096
#define NN 4096
#define KK 4096
#define TLEN 2048

// bf16 operands (Q/K path)
__device__ __nv_bfloat16 g_xb_h[(size_t)MM * KK], g_xb_l[(size_t)MM * KK];
__device__ __nv_bfloat16 g_wq_h[(size_t)NN * KK], g_wq_l[(size_t)NN * KK];
__device__ __nv_bfloat16 g_wk_h[(size_t)NN * KK], g_wk_l[(size_t)NN * KK];
__device__ __nv_bfloat16 g_qa_h[(size_t)MM * NN], g_qa_l[(size_t)MM * NN];
__device__ __nv_bfloat16 g_ka_h[(size_t)MM * NN], g_ka_l[(size_t)MM * NN];
// fp16 operands (V / output path)
__device__ __half g_xf_h[(size_t)MM * KK];
__device__ __half g_wv_h[(size_t)NN * KK], g_wv_l[(size_t)NN * KK];
__device__ __half g_wo_h[(size_t)NN * KK], g_wo_l[(size_t)NN * KK];
__device__ __half g_va_h[(size_t)MM * NN], g_va_l[(size_t)MM * NN];
__device__ __half g_ao_h[(size_t)MM * NN];

__device__ __forceinline__ uint32_t smem_u32(const void* p) {
    uint32_t a;
    asm("{ .reg .u64 t; cvta.to.shared.u64 t, %1; cvt.u32.u64 %0, t; }"
        : "=r"(a) : "l"(p));
    return a;
}

#define LDSM4(r, a)                                                            \
    asm volatile("ldmatrix.sync.aligned.m8n8.x4.shared.b16 {%0,%1,%2,%3}, [%4];" \
                 : "=r"((r)[0]), "=r"((r)[1]), "=r"((r)[2]), "=r"((r)[3])      \
                 : "r"(a))

#define LDSM4T(r, a)                                                           \
    asm volatile("ldmatrix.sync.aligned.m8n8.x4.trans.shared.b16 {%0,%1,%2,%3}, [%4];" \
                 : "=r"((r)[0]), "=r"((r)[1]), "=r"((r)[2]), "=r"((r)[3])      \
                 : "r"(a))

#define MMAB(c, a, b0, b1)                                                     \
    asm volatile("mma.sync.aligned.m16n8k16.row.col.f32.bf16.bf16.f32 "        \
                 "{%0,%1,%2,%3},{%4,%5,%6,%7},{%8,%9},{%0,%1,%2,%3};"          \
                 : "+f"((c)[0]), "+f"((c)[1]), "+f"((c)[2]), "+f"((c)[3])      \
                 : "r"((a)[0]), "r"((a)[1]), "r"((a)[2]), "r"((a)[3]),         \
                   "r"(b0), "r"(b1))

#define MMAH(c, a, b0, b1)                                                     \
    asm volatile("mma.sync.aligned.m16n8k16.row.col.f32.f16.f16.f32 "          \
                 "{%0,%1,%2,%3},{%4,%5,%6,%7},{%8,%9},{%0,%1,%2,%3};"          \
                 : "+f"((c)[0]), "+f"((c)[1]), "+f"((c)[2]), "+f"((c)[3])      \
                 : "r"((a)[0]), "r"((a)[1]), "r"((a)[2]), "r"((a)[3]),         \
                   "r"(b0), "r"(b1))

#define CPA16(dst, src)                                                        \
    asm volatile("cp.async.cg.shared.global [%0], [%1], 16;"                   \
                 :: "r"(dst), "l"(src) : "memory")

// bf16 split: hi = truncate, lo = rn(residual)
__device__ __forceinline__ void split2b(float x0, float x1,
                                        uint32_t& hi, uint32_t& lo) {
    uint32_t u0 = __float_as_uint(x0), u1 = __float_as_uint(x1);
    hi = __byte_perm(u0, u1, 0x7632);
    float l0 = x0 - __uint_as_float(u0 & 0xFFFF0000u);
    float l1 = x1 - __uint_as_float(u1 & 0xFFFF0000u);
    asm("cvt.rn.bf16x2.f32 %0, %1, %2;" : "=r"(lo) : "f"(l1), "f"(l0));
}

// fp16 pack (rn)
__device__ __forceinline__ uint32_t packh(float x0, float x1) {
    uint32_t r;
    asm("cvt.rn.f16x2.f32 %0, %1, %2;" : "=r"(r) : "f"(x1), "f"(x0));
    return r;
}

// fp16 split: hi = rn-fp16, lo = rn-fp16(residual)
__device__ __forceinline__ void split2h(float x0, float x1,
                                        uint32_t& hi, uint32_t& lo) {
    hi = packh(x0, x1);
    float2 b = __half22float2(*reinterpret_cast<__half2*>(&hi));
    lo = packh(x0 - b.x, x1 - b.y);
}

// ============================================================================
// Split kernels
// ============================================================================
__global__ __launch_bounds__(256)
void split_bf(const float4* __restrict__ in, uint2* __restrict__ hi,
              uint2* __restrict__ lo) {
    size_t i = (size_t)blockIdx.x * 256 + threadIdx.x;
    float4 v = in[i];
    uint2 h, l;
    split2b(v.x, v.y, h.x, l.x);
    split2b(v.z, v.w, h.y, l.y);
    hi[i] = h;
    lo[i] = l;
}

__global__ __launch_bounds__(256)
void split_f16(const float4* __restrict__ in, uint2* __restrict__ hi,
               uint2* __restrict__ lo) {
    size_t i = (size_t)blockIdx.x * 256 + threadIdx.x;
    float4 v = in[i];
    uint2 h, l;
    split2h(v.x, v.y, h.x, l.x);
    split2h(v.z, v.w, h.y, l.y);
    hi[i] = h;
    if (lo) lo[i] = l;
}

// x: bf16 hi/lo (Q,K proj) + fp16 hi (V proj) in one pass
__global__ __launch_bounds__(256)
void split_x3(const float4* __restrict__ in, uint2* __restrict__ bh,
              uint2* __restrict__ bl, uint2* __restrict__ fh) {
    size_t i = (size_t)blockIdx.x * 256 + threadIdx.x;
    float4 v = in[i];
    uint2 h, l;
    split2b(v.x, v.y, h.x, l.x);
    split2b(v.z, v.w, h.y, l.y);
    bh[i] = h;
    bl[i] = l;
    fh[i] = make_uint2(packh(v.x, v.y), packh(v.z, v.w));
}

// ============================================================================
// gemm3: bf16 3-product. C = A*B^T, epilogue rotary + split to bf16 hi/lo.
// (used for Q and K projections)
// ============================================================================
#define PITCH 80
#define MAT_B (128 * PITCH)        // 10240
#define STG3 (4 * MAT_B)           // 40960
#define SMEM3 (2 * STG3)           // 81920
#define NCH (KK / 32)              // 128

__global__ __launch_bounds__(256, 2)
void gemm3(const __nv_bfloat16* __restrict__ Ahi, const __nv_bfloat16* __restrict__ Alo,
           const __nv_bfloat16* __restrict__ Bhi, const __nv_bfloat16* __restrict__ Blo,
           __nv_bfloat16* __restrict__ Chi, __nv_bfloat16* __restrict__ Clo) {
    extern __shared__ __align__(1024) char sm[];
    const uint32_t wbase = smem_u32(sm);
    const int tid = threadIdx.x;
    const int wid = tid >> 5, lane = tid & 31;
    const int row0 = blockIdx.y * 128, col0 = blockIdx.x * 128;

    const int lrow = tid >> 2, lseg = tid & 3;
    const __nv_bfloat16* pAh = Ahi + (size_t)(row0 + lrow) * KK + lseg * 8;
    const __nv_bfloat16* pAl = Alo + (size_t)(row0 + lrow) * KK + lseg * 8;
    const __nv_bfloat16* pBh = Bhi + (size_t)(col0 + lrow) * KK + lseg * 8;
    const __nv_bfloat16* pBl = Blo + (size_t)(col0 + lrow) * KK + lseg * 8;
    const uint32_t doff = (uint32_t)lrow * PITCH + lseg * 16;
    const size_t rstep = (size_t)64 * KK;

#define LOAD3(chunk, buf)                                                      \
    do {                                                                       \
        const uint32_t sb_ = wbase + (buf) * STG3 + doff;                      \
        const size_t ko_ = (size_t)(chunk) * 32;                               \
        CPA16(sb_,                       pAh + ko_);                           \
        CPA16(sb_ + 64 * PITCH,          pAh + ko_ + rstep);                   \
        CPA16(sb_ + MAT_B,               pAl + ko_);                           \
        CPA16(sb_ + MAT_B + 64 * PITCH,  pAl + ko_ + rstep);                   \
        CPA16(sb_ + 2 * MAT_B,           pBh + ko_);                           \
        CPA16(sb_ + 2 * MAT_B + 64 * PITCH, pBh + ko_ + rstep);                \
        CPA16(sb_ + 3 * MAT_B,           pBl + ko_);                           \
        CPA16(sb_ + 3 * MAT_B + 64 * PITCH, pBl + ko_ + rstep);                \
        asm volatile("cp.async.commit_group;" ::: "memory");                   \
    } while (0)

    const int wm = (wid & 3) * 32, wn = (wid >> 2) * 64;
    const int l = lane;
    const uint32_t aoff =
        (uint32_t)(wm + (l & 7) + 8 * ((l >> 3) & 1)) * PITCH + (l >> 4) * 16;
    const uint32_t boff = 2 * MAT_B +
        (uint32_t)(wn + (l & 7) + 8 * (l >> 4)) * PITCH + ((l >> 3) & 1) * 16;

    float acc[2][8][4];
#pragma unroll
    for (int i = 0; i < 2; i++)
#pragma unroll
        for (int j = 0; j < 8; j++)
#pragma unroll
            for (int q = 0; q < 4; q++) acc[i][j][q] = 0.f;

    LOAD3(0, 0);

    for (int i = 0; i < NCH; i++) {
        __syncthreads();
        if (i + 1 < NCH) {
            LOAD3(i + 1, (i + 1) & 1);
            asm volatile("cp.async.wait_group 1;" ::: "memory");
        } else {
            asm volatile("cp.async.wait_group 0;" ::: "memory");
        }
        __syncthreads();

        const uint32_t sb = wbase + (i & 1) * STG3;
#pragma unroll
        for (int ks = 0; ks < 2; ks++) {
            uint32_t a_h[2][4], a_l[2][4];
            const uint32_t ka = sb + aoff + ks * 32;
#pragma unroll
            for (int mt = 0; mt < 2; mt++) {
                LDSM4(a_h[mt], ka + mt * 16 * PITCH);
                LDSM4(a_l[mt], ka + mt * 16 * PITCH + MAT_B);
            }
            const uint32_t kb = sb + boff + ks * 32;
#pragma unroll
            for (int p = 0; p < 4; p++) {
                uint32_t bh[4], bl[4];
                LDSM4(bh, kb + p * 16 * PITCH);
                LDSM4(bl, kb + p * 16 * PITCH + MAT_B);
#pragma unroll
                for (int mt = 0; mt < 2; mt++) {
#pragma unroll
                    for (int q = 0; q < 2; q++) {
                        float* c = acc[mt][2 * p + q];
                        MMAB(c, a_h[mt], bh[2 * q], bh[2 * q + 1]);
                        MMAB(c, a_h[mt], bl[2 * q], bl[2 * q + 1]);
                        MMAB(c, a_l[mt], bh[2 * q], bh[2 * q + 1]);
                    }
                }
            }
        }
    }

    // epilogue: rotary + split to bf16 hi/lo
    const int mrow = lane >> 2, ncol = 2 * (lane & 3);
#pragma unroll
    for (int mt = 0; mt < 2; mt++) {
#pragma unroll
        for (int part = 0; part < 2; part++) {
            const int m = row0 + wm + mt * 16 + mrow + part * 8;
            float sn, cs;
            sincosf((float)(m & (TLEN - 1)), &sn, &cs);
            const size_t rowb = (size_t)m * NN + col0 + wn + ncol;
#pragma unroll
            for (int nt = 0; nt < 8; nt++) {
                float x0 = acc[mt][nt][2 * part];
                float x1 = acc[mt][nt][2 * part + 1];
                float y0 = x0 * cs - x1 * sn;
                float y1 = x0 * sn + x1 * cs;
                uint32_t hi, lo;
                split2b(y0, y1, hi, lo);
                *(uint32_t*)(Chi + rowb + nt * 8) = hi;
                *(uint32_t*)(Clo + rowb + nt * 8) = lo;
            }
        }
    }
}

// ============================================================================
// gemm2: fp16 2-product. C = A*B^T with A = Ah only, B = Bh + Bl.
// mode 0: fp32 out.  mode 2: split fp16 hi/lo out.
// ============================================================================
#define STG2 (3 * MAT_B)           // 30720
#define SMEM2 (2 * STG2)           // 61440

__global__ __launch_bounds__(256, 2)
void gemm2(const __half* __restrict__ Ah,
           const __half* __restrict__ Bhi, const __half* __restrict__ Blo,
           float* __restrict__ Cf,
           __half* __restrict__ Chi, __half* __restrict__ Clo, int mode) {
    extern __shared__ __align__(1024) char sm[];
    const uint32_t wbase = smem_u32(sm);
    const int tid = threadIdx.x;
    const int wid = tid >> 5, lane = tid & 31;
    const int row0 = blockIdx.y * 128, col0 = blockIdx.x * 128;

    const int lrow = tid >> 2, lseg = tid & 3;
    const __half* pA  = Ah  + (size_t)(row0 + lrow) * KK + lseg * 8;
    const __half* pBh = Bhi + (size_t)(col0 + lrow) * KK + lseg * 8;
    const __half* pBl = Blo + (size_t)(col0 + lrow) * KK + lseg * 8;
    const uint32_t doff = (uint32_t)lrow * PITCH + lseg * 16;
    const size_t rstep = (size_t)64 * KK;

#define LOAD2(chunk, buf)                                                      \
    do {                                                                       \
        const uint32_t sb_ = wbase + (buf) * STG2 + doff;                      \
        const size_t ko_ = (size_t)(chunk) * 32;                               \
        CPA16(sb_,                       pA + ko_);                            \
        CPA16(sb_ + 64 * PITCH,          pA + ko_ + rstep);                    \
        CPA16(sb_ + MAT_B,               pBh + ko_);                           \
        CPA16(sb_ + MAT_B + 64 * PITCH,  pBh + ko_ + rstep);                   \
        CPA16(sb_ + 2 * MAT_B,           pBl + ko_);                           \
        CPA16(sb_ + 2 * MAT_B + 64 * PITCH, pBl + ko_ + rstep);                \
        asm volatile("cp.async.commit_group;" ::: "memory");                   \
    } while (0)

    const int wm = (wid & 3) * 32, wn = (wid >> 2) * 64;
    const int l = lane;
    const uint32_t aoff =
        (uint32_t)(wm + (l & 7) + 8 * ((l >> 3) & 1)) * PITCH + (l >> 4) * 16;
    const uint32_t boff = MAT_B +
        (uint32_t)(wn + (l & 7) + 8 * (l >> 4)) * PITCH + ((l >> 3) & 1) * 16;

    float acc[2][8][4];
#pragma unroll
    for (int i = 0; i < 2; i++)
#pragma unroll
        for (int j = 0; j < 8; j++)
#pragma unroll
            for (int q = 0; q < 4; q++) acc[i][j][q] = 0.f;

    LOAD2(0, 0);

    for (int i = 0; i < NCH; i++) {
        __syncthreads();
        if (i + 1 < NCH) {
            LOAD2(i + 1, (i + 1) & 1);
            asm volatile("cp.async.wait_group 1;" ::: "memory");
        } else {
            asm volatile("cp.async.wait_group 0;" ::: "memory");
        }
        __syncthreads();

        const uint32_t sb = wbase + (i & 1) * STG2;
#pragma unroll
        for (int ks = 0; ks < 2; ks++) {
            uint32_t a4[2][4];
            const uint32_t ka = sb + aoff + ks * 32;
#pragma unroll
            for (int mt = 0; mt < 2; mt++)
                LDSM4(a4[mt], ka + mt * 16 * PITCH);
            const uint32_t kb = sb + boff + ks * 32;
#pragma unroll
            for (int p = 0; p < 4; p++) {
                uint32_t bh[4], bl[4];
                LDSM4(bh, kb + p * 16 * PITCH);
                LDSM4(bl, kb + p * 16 * PITCH + MAT_B);
#pragma unroll
                for (int mt = 0; mt < 2; mt++) {
#pragma unroll
                    for (int q = 0; q < 2; q++) {
                        float* c = acc[mt][2 * p + q];
                        MMAH(c, a4[mt], bh[2 * q], bh[2 * q + 1]);
                        MMAH(c, a4[mt], bl[2 * q], bl[2 * q + 1]);
                    }
                }
            }
        }
    }

    const int mrow = lane >> 2, ncol = 2 * (lane & 3);
#pragma unroll
    for (int mt = 0; mt < 2; mt++) {
#pragma unroll
        for (int part = 0; part < 2; part++) {
            const int m = row0 + wm + mt * 16 + mrow + part * 8;
            const size_t rowb = (size_t)m * NN + col0 + wn + ncol;
#pragma unroll
            for (int nt = 0; nt < 8; nt++) {
                float x0 = acc[mt][nt][2 * part];
                float x1 = acc[mt][nt][2 * part + 1];
                if (mode == 0) {
                    *(float2*)(Cf + rowb + nt * 8) = make_float2(x0, x1);
                } else {
                    uint32_t hi, lo;
                    split2h(x0, x1, hi, lo);
                    *(uint32_t*)(Chi + rowb + nt * 8) = hi;
                    *(uint32_t*)(Clo + rowb + nt * 8) = lo;
                }
            }
        }
    }
}

// ============================================================================
// Flash attention: S = QK^T on bf16 3-product; PV on fp16 2-product.
// BQ=BK=64, hd=128, 128 threads, P in registers (C-frag == A-frag).
// ============================================================================
#define FP 272
#define FQH 0
#define FQL 17408
#define FKH 34816
#define FKL 52224
#define FVH 69632
#define FVL 87040
#define FLASH_SMEM 104448

__global__ __launch_bounds__(128, 2)
void flash_mma(const __nv_bfloat16* __restrict__ Qh, const __nv_bfloat16* __restrict__ Ql,
               const __nv_bfloat16* __restrict__ Kh, const __nv_bfloat16* __restrict__ Kl,
               const __half* __restrict__ Vh, const __half* __restrict__ Vl,
               __half* __restrict__ Oh) {
    extern __shared__ __align__(1024) char sm[];
    const uint32_t smb = smem_u32(sm);
    const int tid = threadIdx.x;
    const int wid = tid >> 5, lane = tid & 31;
    const int bh_ = blockIdx.y;
    const int b = bh_ >> 5, h = bh_ & 31;
    const int qb = blockIdx.x;
    const int q0 = qb * 64;
    const float scale = 0.08838834764831845f;

    const size_t gbase = ((size_t)b * TLEN) * NN + (size_t)h * 128;

    {
        const int qr = tid >> 1, qc = (tid & 1) * 8;
        const size_t gq = gbase + (size_t)(q0 + qr) * NN + qc * 8;
        const uint32_t sq = smb + qr * FP + qc * 16;
#pragma unroll
        for (int c = 0; c < 8; c++) {
            CPA16(sq + FQH + c * 16, Qh + gq + c * 8);
            CPA16(sq + FQL + c * 16, Ql + gq + c * 8);
        }
        asm volatile("cp.async.commit_group;" ::: "memory");
    }

    const int wm = wid * 16;
    const int l = lane;
    const uint32_t aoff =
        (uint32_t)(wm + (l & 7) + 8 * ((l >> 3) & 1)) * FP + (l >> 4) * 16;
    const uint32_t boff =
        (uint32_t)((l & 7) + 8 * (l >> 4)) * FP + ((l >> 3) & 1) * 16;
    const uint32_t voff =
        (uint32_t)((l & 7) + 8 * ((l >> 3) & 1)) * FP + (l >> 4) * 16;

    float o[16][4];
#pragma unroll
    for (int i = 0; i < 16; i++)
#pragma unroll
        for (int j = 0; j < 4; j++) o[i][j] = 0.f;
    float m0 = -INFINITY, m1 = -INFINITY, l0 = 0.f, l1 = 0.f;

    const int grow0 = q0 + wm + (lane >> 2);
    const int grow1 = grow0 + 8;

    for (int kt = 0; kt <= qb; kt++) {
        const int k0 = kt * 64;
        __syncthreads();

        {
            const int kr = tid >> 1, kc = (tid & 1) * 8;
            const size_t gk = gbase + (size_t)(k0 + kr) * NN + kc * 8;
            const uint32_t sk = smb + kr * FP + kc * 16;
#pragma unroll
            for (int c = 0; c < 8; c++) {
                CPA16(sk + FKH + c * 16, Kh + gk + c * 8);
                CPA16(sk + FKL + c * 16, Kl + gk + c * 8);
                CPA16(sk + FVH + c * 16, Vh + gk + c * 8);
                CPA16(sk + FVL + c * 16, Vl + gk + c * 8);
            }
            asm volatile("cp.async.commit_group;" ::: "memory");
            asm volatile("cp.async.wait_group 0;" ::: "memory");
        }
        __syncthreads();

        // S = Q K^T, bf16 3-product
        float s[8][4];
#pragma unroll
        for (int i = 0; i < 8; i++)
#pragma unroll
            for (int j = 0; j < 4; j++) s[i][j] = 0.f;

#pragma unroll
        for (int ks = 0; ks < 8; ks++) {
            uint32_t qh4[4], ql4[4];
            LDSM4(qh4, smb + FQH + aoff + ks * 32);
            LDSM4(ql4, smb + FQL + aoff + ks * 32);
#pragma unroll
            for (int p = 0; p < 4; p++) {
                uint32_t kh4[4], kl4[4];
                LDSM4(kh4, smb + FKH + boff + p * 16 * FP + ks * 32);
                LDSM4(kl4, smb + FKL + boff + p * 16 * FP + ks * 32);
                MMAB(s[2 * p],     qh4, kh4[0], kh4[1]);
                MMAB(s[2 * p + 1], qh4, kh4[2], kh4[3]);
                MMAB(s[2 * p],     qh4, kl4[0], kl4[1]);
                MMAB(s[2 * p + 1], qh4, kl4[2], kl4[3]);
                MMAB(s[2 * p],     ql4, kh4[0], kh4[1]);
                MMAB(s[2 * p + 1], ql4, kh4[2], kh4[3]);
            }
        }

        if (kt == qb) {
#pragma unroll
            for (int nt = 0; nt < 8; nt++) {
                const int cbase = k0 + nt * 8 + 2 * (lane & 3);
                s[nt][0] = (cbase     > grow0) ? -INFINITY : s[nt][0] * scale;
                s[nt][1] = (cbase + 1 > grow0) ? -INFINITY : s[nt][1] * scale;
                s[nt][2] = (cbase     > grow1) ? -INFINITY : s[nt][2] * scale;
                s[nt][3] = (cbase + 1 > grow1) ? -INFINITY : s[nt][3] * scale;
            }
        } else {
#pragma unroll
            for (int nt = 0; nt < 8; nt++)
#pragma unroll
                for (int e = 0; e < 4; e++) s[nt][e] *= scale;
        }

        float rmax0 = -INFINITY, rmax1 = -INFINITY;
#pragma unroll
        for (int nt = 0; nt < 8; nt++) {
            rmax0 = fmaxf(rmax0, fmaxf(s[nt][0], s[nt][1]));
            rmax1 = fmaxf(rmax1, fmaxf(s[nt][2], s[nt][3]));
        }
        rmax0 = fmaxf(rmax0, __shfl_xor_sync(0xffffffff, rmax0, 1));
        rmax0 = fmaxf(rmax0, __shfl_xor_sync(0xffffffff, rmax0, 2));
        rmax1 = fmaxf(rmax1, __shfl_xor_sync(0xffffffff, rmax1, 1));
        rmax1 = fmaxf(rmax1, __shfl_xor_sync(0xffffffff, rmax1, 2));

        const float mn0 = fmaxf(m0, rmax0), mn1 = fmaxf(m1, rmax1);
        const float a0 = __expf(m0 - mn0), a1 = __expf(m1 - mn1);

        float sum0 = 0.f, sum1 = 0.f;
#pragma unroll
        for (int nt = 0; nt < 8; nt++) {
            s[nt][0] = __expf(s[nt][0] - mn0);
            s[nt][1] = __expf(s[nt][1] - mn0);
            s[nt][2] = __expf(s[nt][2] - mn1);
            s[nt][3] = __expf(s[nt][3] - mn1);
            sum0 += s[nt][0] + s[nt][1];
            sum1 += s[nt][2] + s[nt][3];
        }
        sum0 += __shfl_xor_sync(0xffffffff, sum0, 1);
        sum0 += __shfl_xor_sync(0xffffffff, sum0, 2);
        sum1 += __shfl_xor_sync(0xffffffff, sum1, 1);
        sum1 += __shfl_xor_sync(0xffffffff, sum1, 2);

        l0 = l0 * a0 + sum0;
        l1 = l1 * a1 + sum1;
        m0 = mn0;
        m1 = mn1;

#pragma unroll
        for (int nt = 0; nt < 16; nt++) {
            o[nt][0] *= a0; o[nt][1] *= a0;
            o[nt][2] *= a1; o[nt][3] *= a1;
        }

        // pack P to fp16 A-frags (hi only)
        uint32_t ph[4][4];
#pragma unroll
        for (int ks2 = 0; ks2 < 4; ks2++) {
            ph[ks2][0] = packh(s[2 * ks2][0],     s[2 * ks2][1]);
            ph[ks2][1] = packh(s[2 * ks2][2],     s[2 * ks2][3]);
            ph[ks2][2] = packh(s[2 * ks2 + 1][0], s[2 * ks2 + 1][1]);
            ph[ks2][3] = packh(s[2 * ks2 + 1][2], s[2 * ks2 + 1][3]);
        }

        // O += P V, fp16 2-product (V = Vh + Vl)
#pragma unroll
        for (int ks2 = 0; ks2 < 4; ks2++) {
#pragma unroll
            for (int ntp = 0; ntp < 8; ntp++) {
                uint32_t vh4[4], vl4[4];
                const uint32_t va = smb + voff + ks2 * 16 * FP + ntp * 32;
                LDSM4T(vh4, va + FVH);
                LDSM4T(vl4, va + FVL);
                MMAH(o[2 * ntp],     ph[ks2], vh4[0], vh4[1]);
                MMAH(o[2 * ntp + 1], ph[ks2], vh4[2], vh4[3]);
                MMAH(o[2 * ntp],     ph[ks2], vl4[0], vl4[1]);
                MMAH(o[2 * ntp + 1], ph[ks2], vl4[2], vl4[3]);
            }
        }
    }

    // epilogue: normalize, pack fp16 hi, store
    const float inv0 = 1.f / l0, inv1 = 1.f / l1;
    const size_t rb0 = gbase + (size_t)grow0 * NN + 2 * (lane & 3);
    const size_t rb1 = gbase + (size_t)grow1 * NN + 2 * (lane & 3);
#pragma unroll
    for (int nt = 0; nt < 16; nt++) {
        *(uint32_t*)(Oh + rb0 + nt * 8) = packh(o[nt][0] * inv0, o[nt][1] * inv0);
        *(uint32_t*)(Oh + rb1 + nt * 8) = packh(o[nt][2] * inv1, o[nt][3] * inv1);
    }
}

// ============================================================================
// Launch
// ============================================================================
extern "C" void kernel_launch(void* const* d_in, const int* in_sizes, int n_in,
                              void* d_out, int out_size) {
    const float* x  = (const float*)d_in[0];
    const float* wq = (const float*)d_in[1];
    const float* wk = (const float*)d_in[2];
    const float* wv = (const float*)d_in[3];
    const float* wo = (const float*)d_in[4];
    float* out = (float*)d_out;

    __nv_bfloat16 *xbh, *xbl, *wqh, *wql, *wkh, *wkl, *qah, *qal, *kah, *kal;
    __half *xfh, *wvh, *wvl, *woh, *wol, *vah, *val_, *aoh;
    cudaGetSymbolAddress((void**)&xbh, g_xb_h); cudaGetSymbolAddress((void**)&xbl, g_xb_l);
    cudaGetSymbolAddress((void**)&wqh, g_wq_h); cudaGetSymbolAddress((void**)&wql, g_wq_l);
    cudaGetSymbolAddress((void**)&wkh, g_wk_h); cudaGetSymbolAddress((void**)&wkl, g_wk_l);
    cudaGetSymbolAddress((void**)&qah, g_qa_h); cudaGetSymbolAddress((void**)&qal, g_qa_l);
    cudaGetSymbolAddress((void**)&kah, g_ka_h); cudaGetSymbolAddress((void**)&kal, g_ka_l);
    cudaGetSymbolAddress((void**)&xfh, g_xf_h);
    cudaGetSymbolAddress((void**)&wvh, g_wv_h); cudaGetSymbolAddress((void**)&wvl, g_wv_l);
    cudaGetSymbolAddress((void**)&woh, g_wo_h); cudaGetSymbolAddress((void**)&wol, g_wo_l);
    cudaGetSymbolAddress((void**)&vah, g_va_h); cudaGetSymbolAddress((void**)&val_, g_va_l);
    cudaGetSymbolAddress((void**)&aoh, g_ao_h);

    cudaFuncSetAttribute(gemm3, cudaFuncAttributeMaxDynamicSharedMemorySize, SMEM3);
    cudaFuncSetAttribute(gemm2, cudaFuncAttributeMaxDynamicSharedMemorySize, SMEM2);
    cudaFuncSetAttribute(flash_mma, cudaFuncAttributeMaxDynamicSharedMemorySize,
                         FLASH_SMEM);

    const int splitBlocks = (MM * 4096) / (4 * 256);   // 16384
    split_x3 <<<splitBlocks, 256>>>((const float4*)x,  (uint2*)xbh, (uint2*)xbl,
                                    (uint2*)xfh);
    split_bf <<<splitBlocks, 256>>>((const float4*)wq, (uint2*)wqh, (uint2*)wql);
    split_bf <<<splitBlocks, 256>>>((const float4*)wk, (uint2*)wkh, (uint2*)wkl);
    split_f16<<<splitBlocks, 256>>>((const float4*)wv, (uint2*)wvh, (uint2*)wvl);
    split_f16<<<splitBlocks, 256>>>((const float4*)wo, (uint2*)woh, (uint2*)wol);

    dim3 ggrid(NN / 128, MM / 128);   // (32, 32)
    gemm3<<<ggrid, 256, SMEM3>>>(xbh, xbl, wqh, wql, qah, qal);        // Q + rotary
    gemm3<<<ggrid, 256, SMEM3>>>(xbh, xbl, wkh, wkl, kah, kal);        // K + rotary
    gemm2<<<ggrid, 256, SMEM2>>>(xfh, wvh, wvl, nullptr, vah, val_, 2); // V

    dim3 fgrid(TLEN / 64, 2 * 32);    // (32, 64)
    flash_mma<<<fgrid, 128, FLASH_SMEM>>>(qah, qal, kah, kal, vah, val_, aoh);

    gemm2<<<ggrid, 256, SMEM2>>>(aoh, woh, wol, out, nullptr, nullptr, 0);
}

// round 7
// speedup vs baseline: 5.7823x; 1.2340x over previous
#include <cuda_runtime.h>
#include <cuda_bf16.h>
#include <cuda_fp16.h>
#include <cstdint>
#include <math.h>

// ----------------------------------------------------------------------------
// B=2, T=2048, C=4096, H=32, hd=128.  M=N=K=4096.
// Precision tiers (error sources ~1.9e-4 each, quadrature budget vs 1e-3):
//   softmax-amplified path (x->Q, x->K, S=QK^T): bf16 HMMA 3-product split.
//   linear path (x->V, P*V, attn-out, out): fp16 HMMA 1-product (+P/ao packs).
// Rotary (theta = t, adjacent pairs) fused in Q/K GEMM epilogue.
// Q and K projections share one launch (gridDim.z) to cut wave quantization.
// ----------------------------------------------------------------------------

#define MM 4096
#define NN 4096
#define KK 4096
#define TLEN 2048

// bf16 operands (Q/K path)
__device__ __nv_bfloat16 g_xb_h[(size_t)MM * KK], g_xb_l[(size_t)MM * KK];
__device__ __nv_bfloat16 g_wq_h[(size_t)NN * KK], g_wq_l[(size_t)NN * KK];
__device__ __nv_bfloat16 g_wk_h[(size_t)NN * KK], g_wk_l[(size_t)NN * KK];
__device__ __nv_bfloat16 g_qa_h[(size_t)MM * NN], g_qa_l[(size_t)MM * NN];
__device__ __nv_bfloat16 g_ka_h[(size_t)MM * NN], g_ka_l[(size_t)MM * NN];
// fp16 operands (V / output path)
__device__ __half g_xf_h[(size_t)MM * KK];
__device__ __half g_wv_h[(size_t)NN * KK];
__device__ __half g_wo_h[(size_t)NN * KK];
__device__ __half g_va_h[(size_t)MM * NN];
__device__ __half g_ao_h[(size_t)MM * NN];

__device__ __forceinline__ uint32_t smem_u32(const void* p) {
    uint32_t a;
    asm("{ .reg .u64 t; cvta.to.shared.u64 t, %1; cvt.u32.u64 %0, t; }"
        : "=r"(a) : "l"(p));
    return a;
}

#define LDSM4(r, a)                                                            \
    asm volatile("ldmatrix.sync.aligned.m8n8.x4.shared.b16 {%0,%1,%2,%3}, [%4];" \
                 : "=r"((r)[0]), "=r"((r)[1]), "=r"((r)[2]), "=r"((r)[3])      \
                 : "r"(a))

#define LDSM4T(r, a)                                                           \
    asm volatile("ldmatrix.sync.aligned.m8n8.x4.trans.shared.b16 {%0,%1,%2,%3}, [%4];" \
                 : "=r"((r)[0]), "=r"((r)[1]), "=r"((r)[2]), "=r"((r)[3])      \
                 : "r"(a))

#define MMAB(c, a, b0, b1)                                                     \
    asm volatile("mma.sync.aligned.m16n8k16.row.col.f32.bf16.bf16.f32 "        \
                 "{%0,%1,%2,%3},{%4,%5,%6,%7},{%8,%9},{%0,%1,%2,%3};"          \
                 : "+f"((c)[0]), "+f"((c)[1]), "+f"((c)[2]), "+f"((c)[3])      \
                 : "r"((a)[0]), "r"((a)[1]), "r"((a)[2]), "r"((a)[3]),         \
                   "r"(b0), "r"(b1))

#define MMAH(c, a, b0, b1)                                                     \
    asm volatile("mma.sync.aligned.m16n8k16.row.col.f32.f16.f16.f32 "          \
                 "{%0,%1,%2,%3},{%4,%5,%6,%7},{%8,%9},{%0,%1,%2,%3};"          \
                 : "+f"((c)[0]), "+f"((c)[1]), "+f"((c)[2]), "+f"((c)[3])      \
                 : "r"((a)[0]), "r"((a)[1]), "r"((a)[2]), "r"((a)[3]),         \
                   "r"(b0), "r"(b1))

#define CPA16(dst, src)                                                        \
    asm volatile("cp.async.cg.shared.global [%0], [%1], 16;"                   \
                 :: "r"(dst), "l"(src) : "memory")

// bf16 split: hi = truncate, lo = rn(residual)
__device__ __forceinline__ void split2b(float x0, float x1,
                                        uint32_t& hi, uint32_t& lo) {
    uint32_t u0 = __float_as_uint(x0), u1 = __float_as_uint(x1);
    hi = __byte_perm(u0, u1, 0x7632);
    float l0 = x0 - __uint_as_float(u0 & 0xFFFF0000u);
    float l1 = x1 - __uint_as_float(u1 & 0xFFFF0000u);
    asm("cvt.rn.bf16x2.f32 %0, %1, %2;" : "=r"(lo) : "f"(l1), "f"(l0));
}

// fp16 pack (rn)
__device__ __forceinline__ uint32_t packh(float x0, float x1) {
    uint32_t r;
    asm("cvt.rn.f16x2.f32 %0, %1, %2;" : "=r"(r) : "f"(x1), "f"(x0));
    return r;
}

// ============================================================================
// Split / pack kernels
// ============================================================================
__global__ __launch_bounds__(256)
void split_bf(const float4* __restrict__ in, uint2* __restrict__ hi,
              uint2* __restrict__ lo) {
    size_t i = (size_t)blockIdx.x * 256 + threadIdx.x;
    float4 v = in[i];
    uint2 h, l;
    split2b(v.x, v.y, h.x, l.x);
    split2b(v.z, v.w, h.y, l.y);
    hi[i] = h;
    lo[i] = l;
}

__global__ __launch_bounds__(256)
void pack_f16(const float4* __restrict__ in, uint2* __restrict__ hi) {
    size_t i = (size_t)blockIdx.x * 256 + threadIdx.x;
    float4 v = in[i];
    hi[i] = make_uint2(packh(v.x, v.y), packh(v.z, v.w));
}

// x: bf16 hi/lo (Q,K proj) + fp16 hi (V proj) in one pass
__global__ __launch_bounds__(256)
void split_x3(const float4* __restrict__ in, uint2* __restrict__ bh,
              uint2* __restrict__ bl, uint2* __restrict__ fh) {
    size_t i = (size_t)blockIdx.x * 256 + threadIdx.x;
    float4 v = in[i];
    uint2 h, l;
    split2b(v.x, v.y, h.x, l.x);
    split2b(v.z, v.w, h.y, l.y);
    bh[i] = h;
    bl[i] = l;
    fh[i] = make_uint2(packh(v.x, v.y), packh(v.z, v.w));
}

// ============================================================================
// gemm3: bf16 3-product. C = A*B^T, epilogue rotary + split to bf16 hi/lo.
// gridDim.z selects (B, C) pair -> Q and K projections in ONE launch.
// ============================================================================
#define PITCH 80
#define MAT_B (128 * PITCH)        // 10240
#define STG3 (4 * MAT_B)           // 40960
#define SMEM3 (2 * STG3)           // 81920
#define NCH (KK / 32)              // 128

__global__ __launch_bounds__(256, 2)
void gemm3(const __nv_bfloat16* __restrict__ Ahi, const __nv_bfloat16* __restrict__ Alo,
           const __nv_bfloat16* __restrict__ B0h, const __nv_bfloat16* __restrict__ B0l,
           __nv_bfloat16* __restrict__ C0h, __nv_bfloat16* __restrict__ C0l,
           const __nv_bfloat16* __restrict__ B1h, const __nv_bfloat16* __restrict__ B1l,
           __nv_bfloat16* __restrict__ C1h, __nv_bfloat16* __restrict__ C1l) {
    extern __shared__ __align__(1024) char sm[];
    const uint32_t wbase = smem_u32(sm);
    const int tid = threadIdx.x;
    const int wid = tid >> 5, lane = tid & 31;
    const int row0 = blockIdx.y * 128, col0 = blockIdx.x * 128;

    const __nv_bfloat16* Bhi = blockIdx.z ? B1h : B0h;
    const __nv_bfloat16* Blo = blockIdx.z ? B1l : B0l;
    __nv_bfloat16* Chi = blockIdx.z ? C1h : C0h;
    __nv_bfloat16* Clo = blockIdx.z ? C1l : C0l;

    const int lrow = tid >> 2, lseg = tid & 3;
    const __nv_bfloat16* pAh = Ahi + (size_t)(row0 + lrow) * KK + lseg * 8;
    const __nv_bfloat16* pAl = Alo + (size_t)(row0 + lrow) * KK + lseg * 8;
    const __nv_bfloat16* pBh = Bhi + (size_t)(col0 + lrow) * KK + lseg * 8;
    const __nv_bfloat16* pBl = Blo + (size_t)(col0 + lrow) * KK + lseg * 8;
    const uint32_t doff = (uint32_t)lrow * PITCH + lseg * 16;
    const size_t rstep = (size_t)64 * KK;

#define LOAD3(chunk, buf)                                                      \
    do {                                                                       \
        const uint32_t sb_ = wbase + (buf) * STG3 + doff;                      \
        const size_t ko_ = (size_t)(chunk) * 32;                               \
        CPA16(sb_,                       pAh + ko_);                           \
        CPA16(sb_ + 64 * PITCH,          pAh + ko_ + rstep);                   \
        CPA16(sb_ + MAT_B,               pAl + ko_);                           \
        CPA16(sb_ + MAT_B + 64 * PITCH,  pAl + ko_ + rstep);                   \
        CPA16(sb_ + 2 * MAT_B,           pBh + ko_);                           \
        CPA16(sb_ + 2 * MAT_B + 64 * PITCH, pBh + ko_ + rstep);                \
        CPA16(sb_ + 3 * MAT_B,           pBl + ko_);                           \
        CPA16(sb_ + 3 * MAT_B + 64 * PITCH, pBl + ko_ + rstep);                \
        asm volatile("cp.async.commit_group;" ::: "memory");                   \
    } while (0)

    const int wm = (wid & 3) * 32, wn = (wid >> 2) * 64;
    const int l = lane;
    const uint32_t aoff =
        (uint32_t)(wm + (l & 7) + 8 * ((l >> 3) & 1)) * PITCH + (l >> 4) * 16;
    const uint32_t boff = 2 * MAT_B +
        (uint32_t)(wn + (l & 7) + 8 * (l >> 4)) * PITCH + ((l >> 3) & 1) * 16;

    float acc[2][8][4];
#pragma unroll
    for (int i = 0; i < 2; i++)
#pragma unroll
        for (int j = 0; j < 8; j++)
#pragma unroll
            for (int q = 0; q < 4; q++) acc[i][j][q] = 0.f;

    LOAD3(0, 0);

    for (int i = 0; i < NCH; i++) {
        __syncthreads();
        if (i + 1 < NCH) {
            LOAD3(i + 1, (i + 1) & 1);
            asm volatile("cp.async.wait_group 1;" ::: "memory");
        } else {
            asm volatile("cp.async.wait_group 0;" ::: "memory");
        }
        __syncthreads();

        const uint32_t sb = wbase + (i & 1) * STG3;
#pragma unroll
        for (int ks = 0; ks < 2; ks++) {
            uint32_t a_h[2][4], a_l[2][4];
            const uint32_t ka = sb + aoff + ks * 32;
#pragma unroll
            for (int mt = 0; mt < 2; mt++) {
                LDSM4(a_h[mt], ka + mt * 16 * PITCH);
                LDSM4(a_l[mt], ka + mt * 16 * PITCH + MAT_B);
            }
            const uint32_t kb = sb + boff + ks * 32;
#pragma unroll
            for (int p = 0; p < 4; p++) {
                uint32_t bh[4], bl[4];
                LDSM4(bh, kb + p * 16 * PITCH);
                LDSM4(bl, kb + p * 16 * PITCH + MAT_B);
#pragma unroll
                for (int mt = 0; mt < 2; mt++) {
#pragma unroll
                    for (int q = 0; q < 2; q++) {
                        float* c = acc[mt][2 * p + q];
                        MMAB(c, a_h[mt], bh[2 * q], bh[2 * q + 1]);
                        MMAB(c, a_h[mt], bl[2 * q], bl[2 * q + 1]);
                        MMAB(c, a_l[mt], bh[2 * q], bh[2 * q + 1]);
                    }
                }
            }
        }
    }

    // epilogue: rotary + split to bf16 hi/lo
    const int mrow = lane >> 2, ncol = 2 * (lane & 3);
#pragma unroll
    for (int mt = 0; mt < 2; mt++) {
#pragma unroll
        for (int part = 0; part < 2; part++) {
            const int m = row0 + wm + mt * 16 + mrow + part * 8;
            float sn, cs;
            sincosf((float)(m & (TLEN - 1)), &sn, &cs);
            const size_t rowb = (size_t)m * NN + col0 + wn + ncol;
#pragma unroll
            for (int nt = 0; nt < 8; nt++) {
                float x0 = acc[mt][nt][2 * part];
                float x1 = acc[mt][nt][2 * part + 1];
                float y0 = x0 * cs - x1 * sn;
                float y1 = x0 * sn + x1 * cs;
                uint32_t hi, lo;
                split2b(y0, y1, hi, lo);
                *(uint32_t*)(Chi + rowb + nt * 8) = hi;
                *(uint32_t*)(Clo + rowb + nt * 8) = lo;
            }
        }
    }
}

// ============================================================================
// gemm1: fp16 1-product. C = Ah*Bh^T.
// mode 0: fp32 out.  mode 2: fp16 hi out.
// ============================================================================
#define STG1 (2 * MAT_B)           // 20480
#define SMEM1 (2 * STG1)           // 40960

__global__ __launch_bounds__(256, 2)
void gemm1(const __half* __restrict__ Ah, const __half* __restrict__ Bh,
           float* __restrict__ Cf, __half* __restrict__ Chi, int mode) {
    extern __shared__ __align__(1024) char sm[];
    const uint32_t wbase = smem_u32(sm);
    const int tid = threadIdx.x;
    const int wid = tid >> 5, lane = tid & 31;
    const int row0 = blockIdx.y * 128, col0 = blockIdx.x * 128;

    const int lrow = tid >> 2, lseg = tid & 3;
    const __half* pA = Ah + (size_t)(row0 + lrow) * KK + lseg * 8;
    const __half* pB = Bh + (size_t)(col0 + lrow) * KK + lseg * 8;
    const uint32_t doff = (uint32_t)lrow * PITCH + lseg * 16;
    const size_t rstep = (size_t)64 * KK;

#define LOAD1(chunk, buf)                                                      \
    do {                                                                       \
        const uint32_t sb_ = wbase + (buf) * STG1 + doff;                      \
        const size_t ko_ = (size_t)(chunk) * 32;                               \
        CPA16(sb_,                      pA + ko_);                             \
        CPA16(sb_ + 64 * PITCH,         pA + ko_ + rstep);                     \
        CPA16(sb_ + MAT_B,              pB + ko_);                             \
        CPA16(sb_ + MAT_B + 64 * PITCH, pB + ko_ + rstep);                     \
        asm volatile("cp.async.commit_group;" ::: "memory");                   \
    } while (0)

    const int wm = (wid & 3) * 32, wn = (wid >> 2) * 64;
    const int l = lane;
    const uint32_t aoff =
        (uint32_t)(wm + (l & 7) + 8 * ((l >> 3) & 1)) * PITCH + (l >> 4) * 16;
    const uint32_t boff = MAT_B +
        (uint32_t)(wn + (l & 7) + 8 * (l >> 4)) * PITCH + ((l >> 3) & 1) * 16;

    float acc[2][8][4];
#pragma unroll
    for (int i = 0; i < 2; i++)
#pragma unroll
        for (int j = 0; j < 8; j++)
#pragma unroll
            for (int q = 0; q < 4; q++) acc[i][j][q] = 0.f;

    LOAD1(0, 0);

    for (int i = 0; i < NCH; i++) {
        __syncthreads();
        if (i + 1 < NCH) {
            LOAD1(i + 1, (i + 1) & 1);
            asm volatile("cp.async.wait_group 1;" ::: "memory");
        } else {
            asm volatile("cp.async.wait_group 0;" ::: "memory");
        }
        __syncthreads();

        const uint32_t sb = wbase + (i & 1) * STG1;
#pragma unroll
        for (int ks = 0; ks < 2; ks++) {
            uint32_t a4[2][4];
            const uint32_t ka = sb + aoff + ks * 32;
#pragma unroll
            for (int mt = 0; mt < 2; mt++)
                LDSM4(a4[mt], ka + mt * 16 * PITCH);
            const uint32_t kb = sb + boff + ks * 32;
#pragma unroll
            for (int p = 0; p < 4; p++) {
                uint32_t bh[4];
                LDSM4(bh, kb + p * 16 * PITCH);
#pragma unroll
                for (int mt = 0; mt < 2; mt++) {
                    MMAH(acc[mt][2 * p],     a4[mt], bh[0], bh[1]);
                    MMAH(acc[mt][2 * p + 1], a4[mt], bh[2], bh[3]);
                }
            }
        }
    }

    const int mrow = lane >> 2, ncol = 2 * (lane & 3);
#pragma unroll
    for (int mt = 0; mt < 2; mt++) {
#pragma unroll
        for (int part = 0; part < 2; part++) {
            const int m = row0 + wm + mt * 16 + mrow + part * 8;
            const size_t rowb = (size_t)m * NN + col0 + wn + ncol;
#pragma unroll
            for (int nt = 0; nt < 8; nt++) {
                float x0 = acc[mt][nt][2 * part];
                float x1 = acc[mt][nt][2 * part + 1];
                if (mode == 0) {
                    *(float2*)(Cf + rowb + nt * 8) = make_float2(x0, x1);
                } else {
                    *(uint32_t*)(Chi + rowb + nt * 8) = packh(x0, x1);
                }
            }
        }
    }
}

// ============================================================================
// Flash attention: S = QK^T bf16 3-product; PV fp16 1-product (V single fp16).
// BQ=BK=64, hd=128, 128 threads, P in registers (C-frag == A-frag).
// ============================================================================
#define FP 272
#define FQH 0
#define FQL 17408
#define FKH 34816
#define FKL 52224
#define FVH 69632
#define FLASH_SMEM 87040

__global__ __launch_bounds__(128, 2)
void flash_mma(const __nv_bfloat16* __restrict__ Qh, const __nv_bfloat16* __restrict__ Ql,
               const __nv_bfloat16* __restrict__ Kh, const __nv_bfloat16* __restrict__ Kl,
               const __half* __restrict__ Vh, __half* __restrict__ Oh) {
    extern __shared__ __align__(1024) char sm[];
    const uint32_t smb = smem_u32(sm);
    const int tid = threadIdx.x;
    const int wid = tid >> 5, lane = tid & 31;
    const int bh_ = blockIdx.y;
    const int b = bh_ >> 5, h = bh_ & 31;
    const int qb = (gridDim.x - 1) - blockIdx.x;   // heavy tiles launch first
    const int q0 = qb * 64;
    const float scale = 0.08838834764831845f;

    const size_t gbase = ((size_t)b * TLEN) * NN + (size_t)h * 128;

    {
        const int qr = tid >> 1, qc = (tid & 1) * 8;
        const size_t gq = gbase + (size_t)(q0 + qr) * NN + qc * 8;
        const uint32_t sq = smb + qr * FP + qc * 16;
#pragma unroll
        for (int c = 0; c < 8; c++) {
            CPA16(sq + FQH + c * 16, Qh + gq + c * 8);
            CPA16(sq + FQL + c * 16, Ql + gq + c * 8);
        }
        asm volatile("cp.async.commit_group;" ::: "memory");
    }

    const int wm = wid * 16;
    const int l = lane;
    const uint32_t aoff =
        (uint32_t)(wm + (l & 7) + 8 * ((l >> 3) & 1)) * FP + (l >> 4) * 16;
    const uint32_t boff =
        (uint32_t)((l & 7) + 8 * (l >> 4)) * FP + ((l >> 3) & 1) * 16;
    const uint32_t voff =
        (uint32_t)((l & 7) + 8 * ((l >> 3) & 1)) * FP + (l >> 4) * 16;

    float o[16][4];
#pragma unroll
    for (int i = 0; i < 16; i++)
#pragma unroll
        for (int j = 0; j < 4; j++) o[i][j] = 0.f;
    float m0 = -INFINITY, m1 = -INFINITY, l0 = 0.f, l1 = 0.f;

    const int grow0 = q0 + wm + (lane >> 2);
    const int grow1 = grow0 + 8;

    for (int kt = 0; kt <= qb; kt++) {
        const int k0 = kt * 64;
        __syncthreads();

        {
            const int kr = tid >> 1, kc = (tid & 1) * 8;
            const size_t gk = gbase + (size_t)(k0 + kr) * NN + kc * 8;
            const uint32_t sk = smb + kr * FP + kc * 16;
#pragma unroll
            for (int c = 0; c < 8; c++) {
                CPA16(sk + FKH + c * 16, Kh + gk + c * 8);
                CPA16(sk + FKL + c * 16, Kl + gk + c * 8);
                CPA16(sk + FVH + c * 16, Vh + gk + c * 8);
            }
            asm volatile("cp.async.commit_group;" ::: "memory");
            asm volatile("cp.async.wait_group 0;" ::: "memory");
        }
        __syncthreads();

        // S = Q K^T, bf16 3-product
        float s[8][4];
#pragma unroll
        for (int i = 0; i < 8; i++)
#pragma unroll
            for (int j = 0; j < 4; j++) s[i][j] = 0.f;

#pragma unroll
        for (int ks = 0; ks < 8; ks++) {
            uint32_t qh4[4], ql4[4];
            LDSM4(qh4, smb + FQH + aoff + ks * 32);
            LDSM4(ql4, smb + FQL + aoff + ks * 32);
#pragma unroll
            for (int p = 0; p < 4; p++) {
                uint32_t kh4[4], kl4[4];
                LDSM4(kh4, smb + FKH + boff + p * 16 * FP + ks * 32);
                LDSM4(kl4, smb + FKL + boff + p * 16 * FP + ks * 32);
                MMAB(s[2 * p],     qh4, kh4[0], kh4[1]);
                MMAB(s[2 * p + 1], qh4, kh4[2], kh4[3]);
                MMAB(s[2 * p],     qh4, kl4[0], kl4[1]);
                MMAB(s[2 * p + 1], qh4, kl4[2], kl4[3]);
                MMAB(s[2 * p],     ql4, kh4[0], kh4[1]);
                MMAB(s[2 * p + 1], ql4, kh4[2], kh4[3]);
            }
        }

        if (kt == qb) {
#pragma unroll
            for (int nt = 0; nt < 8; nt++) {
                const int cbase = k0 + nt * 8 + 2 * (lane & 3);
                s[nt][0] = (cbase     > grow0) ? -INFINITY : s[nt][0] * scale;
                s[nt][1] = (cbase + 1 > grow0) ? -INFINITY : s[nt][1] * scale;
                s[nt][2] = (cbase     > grow1) ? -INFINITY : s[nt][2] * scale;
                s[nt][3] = (cbase + 1 > grow1) ? -INFINITY : s[nt][3] * scale;
            }
        } else {
#pragma unroll
            for (int nt = 0; nt < 8; nt++)
#pragma unroll
                for (int e = 0; e < 4; e++) s[nt][e] *= scale;
        }

        float rmax0 = -INFINITY, rmax1 = -INFINITY;
#pragma unroll
        for (int nt = 0; nt < 8; nt++) {
            rmax0 = fmaxf(rmax0, fmaxf(s[nt][0], s[nt][1]));
            rmax1 = fmaxf(rmax1, fmaxf(s[nt][2], s[nt][3]));
        }
        rmax0 = fmaxf(rmax0, __shfl_xor_sync(0xffffffff, rmax0, 1));
        rmax0 = fmaxf(rmax0, __shfl_xor_sync(0xffffffff, rmax0, 2));
        rmax1 = fmaxf(rmax1, __shfl_xor_sync(0xffffffff, rmax1, 1));
        rmax1 = fmaxf(rmax1, __shfl_xor_sync(0xffffffff, rmax1, 2));

        const float mn0 = fmaxf(m0, rmax0), mn1 = fmaxf(m1, rmax1);
        const float a0 = __expf(m0 - mn0), a1 = __expf(m1 - mn1);

        float sum0 = 0.f, sum1 = 0.f;
#pragma unroll
        for (int nt = 0; nt < 8; nt++) {
            s[nt][0] = __expf(s[nt][0] - mn0);
            s[nt][1] = __expf(s[nt][1] - mn0);
            s[nt][2] = __expf(s[nt][2] - mn1);
            s[nt][3] = __expf(s[nt][3] - mn1);
            sum0 += s[nt][0] + s[nt][1];
            sum1 += s[nt][2] + s[nt][3];
        }
        sum0 += __shfl_xor_sync(0xffffffff, sum0, 1);
        sum0 += __shfl_xor_sync(0xffffffff, sum0, 2);
        sum1 += __shfl_xor_sync(0xffffffff, sum1, 1);
        sum1 += __shfl_xor_sync(0xffffffff, sum1, 2);

        l0 = l0 * a0 + sum0;
        l1 = l1 * a1 + sum1;
        m0 = mn0;
        m1 = mn1;

#pragma unroll
        for (int nt = 0; nt < 16; nt++) {
            o[nt][0] *= a0; o[nt][1] *= a0;
            o[nt][2] *= a1; o[nt][3] *= a1;
        }

        // pack P to fp16 A-frags
        uint32_t ph[4][4];
#pragma unroll
        for (int ks2 = 0; ks2 < 4; ks2++) {
            ph[ks2][0] = packh(s[2 * ks2][0],     s[2 * ks2][1]);
            ph[ks2][1] = packh(s[2 * ks2][2],     s[2 * ks2][3]);
            ph[ks2][2] = packh(s[2 * ks2 + 1][0], s[2 * ks2 + 1][1]);
            ph[ks2][3] = packh(s[2 * ks2 + 1][2], s[2 * ks2 + 1][3]);
        }

        // O += P V, fp16 1-product
#pragma unroll
        for (int ks2 = 0; ks2 < 4; ks2++) {
#pragma unroll
            for (int ntp = 0; ntp < 8; ntp++) {
                uint32_t vh4[4];
                LDSM4T(vh4, smb + FVH + voff + ks2 * 16 * FP + ntp * 32);
                MMAH(o[2 * ntp],     ph[ks2], vh4[0], vh4[1]);
                MMAH(o[2 * ntp + 1], ph[ks2], vh4[2], vh4[3]);
            }
        }
    }

    // epilogue: normalize, pack fp16, store
    const float inv0 = 1.f / l0, inv1 = 1.f / l1;
    const size_t rb0 = gbase + (size_t)grow0 * NN + 2 * (lane & 3);
    const size_t rb1 = gbase + (size_t)grow1 * NN + 2 * (lane & 3);
#pragma unroll
    for (int nt = 0; nt < 16; nt++) {
        *(uint32_t*)(Oh + rb0 + nt * 8) = packh(o[nt][0] * inv0, o[nt][1] * inv0);
        *(uint32_t*)(Oh + rb1 + nt * 8) = packh(o[nt][2] * inv1, o[nt][3] * inv1);
    }
}

// ============================================================================
// Launch
// ============================================================================
extern "C" void kernel_launch(void* const* d_in, const int* in_sizes, int n_in,
                              void* d_out, int out_size) {
    const float* x  = (const float*)d_in[0];
    const float* wq = (const float*)d_in[1];
    const float* wk = (const float*)d_in[2];
    const float* wv = (const float*)d_in[3];
    const float* wo = (const float*)d_in[4];
    float* out = (float*)d_out;

    __nv_bfloat16 *xbh, *xbl, *wqh, *wql, *wkh, *wkl, *qah, *qal, *kah, *kal;
    __half *xfh, *wvh, *woh, *vah, *aoh;
    cudaGetSymbolAddress((void**)&xbh, g_xb_h); cudaGetSymbolAddress((void**)&xbl, g_xb_l);
    cudaGetSymbolAddress((void**)&wqh, g_wq_h); cudaGetSymbolAddress((void**)&wql, g_wq_l);
    cudaGetSymbolAddress((void**)&wkh, g_wk_h); cudaGetSymbolAddress((void**)&wkl, g_wk_l);
    cudaGetSymbolAddress((void**)&qah, g_qa_h); cudaGetSymbolAddress((void**)&qal, g_qa_l);
    cudaGetSymbolAddress((void**)&kah, g_ka_h); cudaGetSymbolAddress((void**)&kal, g_ka_l);
    cudaGetSymbolAddress((void**)&xfh, g_xf_h);
    cudaGetSymbolAddress((void**)&wvh, g_wv_h);
    cudaGetSymbolAddress((void**)&woh, g_wo_h);
    cudaGetSymbolAddress((void**)&vah, g_va_h);
    cudaGetSymbolAddress((void**)&aoh, g_ao_h);

    cudaFuncSetAttribute(gemm3, cudaFuncAttributeMaxDynamicSharedMemorySize, SMEM3);
    cudaFuncSetAttribute(gemm1, cudaFuncAttributeMaxDynamicSharedMemorySize, SMEM1);
    cudaFuncSetAttribute(flash_mma, cudaFuncAttributeMaxDynamicSharedMemorySize,
                         FLASH_SMEM);

    const int splitBlocks = (MM * 4096) / (4 * 256);   // 16384
    split_x3<<<splitBlocks, 256>>>((const float4*)x,  (uint2*)xbh, (uint2*)xbl,
                                   (uint2*)xfh);
    split_bf<<<splitBlocks, 256>>>((const float4*)wq, (uint2*)wqh, (uint2*)wql);
    split_bf<<<splitBlocks, 256>>>((const float4*)wk, (uint2*)wkh, (uint2*)wkl);
    pack_f16<<<splitBlocks, 256>>>((const float4*)wv, (uint2*)wvh);
    pack_f16<<<splitBlocks, 256>>>((const float4*)wo, (uint2*)woh);

    dim3 gQK(NN / 128, MM / 128, 2);   // Q and K in one launch
    gemm3<<<gQK, 256, SMEM3>>>(xbh, xbl, wqh, wql, qah, qal, wkh, wkl, kah, kal);

    dim3 ggrid(NN / 128, MM / 128);
    gemm1<<<ggrid, 256, SMEM1>>>(xfh, wvh, nullptr, vah, 2);   // V projection

    dim3 fgrid(TLEN / 64, 2 * 32);     // (32, 64), heavy-first inside kernel
    flash_mma<<<fgrid, 128, FLASH_SMEM>>>(qah, qal, kah, kal, vah, aoh);

    gemm1<<<ggrid, 256, SMEM1>>>(aoh, woh, out, nullptr, 0);   // output proj
}

// round 8
// speedup vs baseline: 6.5876x; 1.1393x over previous
#include <cuda_runtime.h>
#include <cuda_bf16.h>
#include <cuda_fp16.h>
#include <cstdint>
#include <math.h>

// ----------------------------------------------------------------------------
// B=2, T=2048, C=4096, H=32, hd=128.  M=N=K=4096.
// Precision plan (validated quadrature model, ~2e-4 per fp16 source):
//   Q/K projections: x_fp16 * (W_hi + W_lo)_fp16  -> 2-product HMMA.
//   V/output path:   fp16 1-product.
//   Flash S = QK^T:  bf16 3-product (Q,K stored bf16 hi/lo by proj epilogue).
//   Flash PV:        fp16 1-product.
// Rotary (theta = t, adjacent pairs) fused in Q/K projection epilogue.
// Q,K,V projections share ONE launch (gridDim.z = 3; V last -> tail packing).
// ----------------------------------------------------------------------------

#define MM 4096
#define NN 4096
#define KK 4096
#define TLEN 2048

// fp16 operands
__device__ __half g_xf_h[(size_t)MM * KK];
__device__ __half g_wq_h[(size_t)NN * KK], g_wq_l[(size_t)NN * KK];
__device__ __half g_wk_h[(size_t)NN * KK], g_wk_l[(size_t)NN * KK];
__device__ __half g_wv_h[(size_t)NN * KK];
__device__ __half g_wo_h[(size_t)NN * KK];
__device__ __half g_va_h[(size_t)MM * NN];
__device__ __half g_ao_h[(size_t)MM * NN];
// bf16 hi/lo Q,K activations (flash S path needs 3-product accuracy)
__device__ __nv_bfloat16 g_qa_h[(size_t)MM * NN], g_qa_l[(size_t)MM * NN];
__device__ __nv_bfloat16 g_ka_h[(size_t)MM * NN], g_ka_l[(size_t)MM * NN];

__device__ __forceinline__ uint32_t smem_u32(const void* p) {
    uint32_t a;
    asm("{ .reg .u64 t; cvta.to.shared.u64 t, %1; cvt.u32.u64 %0, t; }"
        : "=r"(a) : "l"(p));
    return a;
}

#define LDSM4(r, a)                                                            \
    asm volatile("ldmatrix.sync.aligned.m8n8.x4.shared.b16 {%0,%1,%2,%3}, [%4];" \
                 : "=r"((r)[0]), "=r"((r)[1]), "=r"((r)[2]), "=r"((r)[3])      \
                 : "r"(a))

#define LDSM4T(r, a)                                                           \
    asm volatile("ldmatrix.sync.aligned.m8n8.x4.trans.shared.b16 {%0,%1,%2,%3}, [%4];" \
                 : "=r"((r)[0]), "=r"((r)[1]), "=r"((r)[2]), "=r"((r)[3])      \
                 : "r"(a))

#define MMAB(c, a, b0, b1)                                                     \
    asm volatile("mma.sync.aligned.m16n8k16.row.col.f32.bf16.bf16.f32 "        \
                 "{%0,%1,%2,%3},{%4,%5,%6,%7},{%8,%9},{%0,%1,%2,%3};"          \
                 : "+f"((c)[0]), "+f"((c)[1]), "+f"((c)[2]), "+f"((c)[3])      \
                 : "r"((a)[0]), "r"((a)[1]), "r"((a)[2]), "r"((a)[3]),         \
                   "r"(b0), "r"(b1))

#define MMAH(c, a, b0, b1)                                                     \
    asm volatile("mma.sync.aligned.m16n8k16.row.col.f32.f16.f16.f32 "          \
                 "{%0,%1,%2,%3},{%4,%5,%6,%7},{%8,%9},{%0,%1,%2,%3};"          \
                 : "+f"((c)[0]), "+f"((c)[1]), "+f"((c)[2]), "+f"((c)[3])      \
                 : "r"((a)[0]), "r"((a)[1]), "r"((a)[2]), "r"((a)[3]),         \
                   "r"(b0), "r"(b1))

#define CPA16(dst, src)                                                        \
    asm volatile("cp.async.cg.shared.global [%0], [%1], 16;"                   \
                 :: "r"(dst), "l"(src) : "memory")

// bf16 split: hi = truncate, lo = rn(residual)
__device__ __forceinline__ void split2b(float x0, float x1,
                                        uint32_t& hi, uint32_t& lo) {
    uint32_t u0 = __float_as_uint(x0), u1 = __float_as_uint(x1);
    hi = __byte_perm(u0, u1, 0x7632);
    float l0 = x0 - __uint_as_float(u0 & 0xFFFF0000u);
    float l1 = x1 - __uint_as_float(u1 & 0xFFFF0000u);
    asm("cvt.rn.bf16x2.f32 %0, %1, %2;" : "=r"(lo) : "f"(l1), "f"(l0));
}

// fp16 pack (rn)
__device__ __forceinline__ uint32_t packh(float x0, float x1) {
    uint32_t r;
    asm("cvt.rn.f16x2.f32 %0, %1, %2;" : "=r"(r) : "f"(x1), "f"(x0));
    return r;
}

// fp16 split: hi = rn-fp16, lo = rn-fp16(residual)
__device__ __forceinline__ void split2h(float x0, float x1,
                                        uint32_t& hi, uint32_t& lo) {
    hi = packh(x0, x1);
    float2 b = __half22float2(*reinterpret_cast<__half2*>(&hi));
    lo = packh(x0 - b.x, x1 - b.y);
}

// ============================================================================
// Pack / split kernels
// ============================================================================
__global__ __launch_bounds__(256)
void pack_f16(const float4* __restrict__ in, uint2* __restrict__ hi) {
    size_t i = (size_t)blockIdx.x * 256 + threadIdx.x;
    float4 v = in[i];
    hi[i] = make_uint2(packh(v.x, v.y), packh(v.z, v.w));
}

__global__ __launch_bounds__(256)
void split_h16(const float4* __restrict__ in, uint2* __restrict__ hi,
               uint2* __restrict__ lo) {
    size_t i = (size_t)blockIdx.x * 256 + threadIdx.x;
    float4 v = in[i];
    uint2 h, l;
    split2h(v.x, v.y, h.x, l.x);
    split2h(v.z, v.w, h.y, l.y);
    hi[i] = h;
    lo[i] = l;
}

// ============================================================================
// proj_all: fused Q/K/V projections.  C = x * W^T.
// z=0: Q = x*(Wqh+Wql), rotary, out bf16 hi/lo.
// z=1: K = x*(Wkh+Wkl), rotary, out bf16 hi/lo.
// z=2: V = x*Wvh (1-product), out fp16.
// CTA 128x128, 8 warps 32x64, K-chunk 32, 2-stage cp.async, 2 CTA/SM.
// ============================================================================
#define PITCH 80
#define PMAT (128 * PITCH)         // 10240
#define PSTG (3 * PMAT)            // 30720
#define PSMEM (2 * PSTG)           // 61440
#define NCH (KK / 32)              // 128

__global__ __launch_bounds__(256, 2)
void proj_all(const __half* __restrict__ Ah,
              const __half* __restrict__ Wqh, const __half* __restrict__ Wql,
              const __half* __restrict__ Wkh, const __half* __restrict__ Wkl,
              const __half* __restrict__ Wvh,
              __nv_bfloat16* __restrict__ Qh, __nv_bfloat16* __restrict__ Qlo,
              __nv_bfloat16* __restrict__ Kh, __nv_bfloat16* __restrict__ Klo,
              __half* __restrict__ Vh) {
    extern __shared__ __align__(1024) char sm[];
    const uint32_t wbase = smem_u32(sm);
    const int tid = threadIdx.x;
    const int wid = tid >> 5, lane = tid & 31;
    const int row0 = blockIdx.y * 128, col0 = blockIdx.x * 128;
    const int z = blockIdx.z;
    const bool twoP = (z < 2);

    const __half* Bh_ = (z == 0) ? Wqh : (z == 1) ? Wkh : Wvh;
    const __half* Bl_ = (z == 1) ? Wkl : Wql;   // dummy-valid when z==2 (unused)

    const int lrow = tid >> 2, lseg = tid & 3;
    const __half* pA  = Ah  + (size_t)(row0 + lrow) * KK + lseg * 8;
    const __half* pBh = Bh_ + (size_t)(col0 + lrow) * KK + lseg * 8;
    const __half* pBl = Bl_ + (size_t)(col0 + lrow) * KK + lseg * 8;
    const uint32_t doff = (uint32_t)lrow * PITCH + lseg * 16;
    const size_t rstep = (size_t)64 * KK;

#define LOADP(chunk, buf)                                                      \
    do {                                                                       \
        const uint32_t sb_ = wbase + (buf) * PSTG + doff;                      \
        const size_t ko_ = (size_t)(chunk) * 32;                               \
        CPA16(sb_,                      pA + ko_);                             \
        CPA16(sb_ + 64 * PITCH,         pA + ko_ + rstep);                     \
        CPA16(sb_ + PMAT,               pBh + ko_);                            \
        CPA16(sb_ + PMAT + 64 * PITCH,  pBh + ko_ + rstep);                    \
        if (twoP) {                                                            \
            CPA16(sb_ + 2 * PMAT,              pBl + ko_);                     \
            CPA16(sb_ + 2 * PMAT + 64 * PITCH, pBl + ko_ + rstep);             \
        }                                                                      \
        asm volatile("cp.async.commit_group;" ::: "memory");                   \
    } while (0)

    const int wm = (wid & 3) * 32, wn = (wid >> 2) * 64;
    const int l = lane;
    const uint32_t aoff =
        (uint32_t)(wm + (l & 7) + 8 * ((l >> 3) & 1)) * PITCH + (l >> 4) * 16;
    const uint32_t boff = PMAT +
        (uint32_t)(wn + (l & 7) + 8 * (l >> 4)) * PITCH + ((l >> 3) & 1) * 16;

    float acc[2][8][4];
#pragma unroll
    for (int i = 0; i < 2; i++)
#pragma unroll
        for (int j = 0; j < 8; j++)
#pragma unroll
            for (int q = 0; q < 4; q++) acc[i][j][q] = 0.f;

    LOADP(0, 0);

    for (int i = 0; i < NCH; i++) {
        __syncthreads();
        if (i + 1 < NCH) {
            LOADP(i + 1, (i + 1) & 1);
            asm volatile("cp.async.wait_group 1;" ::: "memory");
        } else {
            asm volatile("cp.async.wait_group 0;" ::: "memory");
        }
        __syncthreads();

        const uint32_t sb = wbase + (i & 1) * PSTG;
#pragma unroll
        for (int ks = 0; ks < 2; ks++) {
            uint32_t a4[2][4];
            const uint32_t ka = sb + aoff + ks * 32;
#pragma unroll
            for (int mt = 0; mt < 2; mt++)
                LDSM4(a4[mt], ka + mt * 16 * PITCH);
            const uint32_t kb = sb + boff + ks * 32;
#pragma unroll
            for (int p = 0; p < 4; p++) {
                uint32_t bh4[4];
                LDSM4(bh4, kb + p * 16 * PITCH);
#pragma unroll
                for (int mt = 0; mt < 2; mt++) {
                    MMAH(acc[mt][2 * p],     a4[mt], bh4[0], bh4[1]);
                    MMAH(acc[mt][2 * p + 1], a4[mt], bh4[2], bh4[3]);
                }
                if (twoP) {
                    uint32_t bl4[4];
                    LDSM4(bl4, kb + p * 16 * PITCH + PMAT);
#pragma unroll
                    for (int mt = 0; mt < 2; mt++) {
                        MMAH(acc[mt][2 * p],     a4[mt], bl4[0], bl4[1]);
                        MMAH(acc[mt][2 * p + 1], a4[mt], bl4[2], bl4[3]);
                    }
                }
            }
        }
    }

    // epilogue
    const int mrow = lane >> 2, ncol = 2 * (lane & 3);
    __nv_bfloat16* Ch = (z == 0) ? Qh : Kh;
    __nv_bfloat16* Cl = (z == 0) ? Qlo : Klo;
#pragma unroll
    for (int mt = 0; mt < 2; mt++) {
#pragma unroll
        for (int part = 0; part < 2; part++) {
            const int m = row0 + wm + mt * 16 + mrow + part * 8;
            const size_t rowb = (size_t)m * NN + col0 + wn + ncol;
            if (twoP) {
                float sn, cs;
                sincosf((float)(m & (TLEN - 1)), &sn, &cs);
#pragma unroll
                for (int nt = 0; nt < 8; nt++) {
                    float x0 = acc[mt][nt][2 * part];
                    float x1 = acc[mt][nt][2 * part + 1];
                    float y0 = x0 * cs - x1 * sn;
                    float y1 = x0 * sn + x1 * cs;
                    uint32_t hi, lo;
                    split2b(y0, y1, hi, lo);
                    *(uint32_t*)(Ch + rowb + nt * 8) = hi;
                    *(uint32_t*)(Cl + rowb + nt * 8) = lo;
                }
            } else {
#pragma unroll
                for (int nt = 0; nt < 8; nt++) {
                    *(uint32_t*)(Vh + rowb + nt * 8) =
                        packh(acc[mt][nt][2 * part], acc[mt][nt][2 * part + 1]);
                }
            }
        }
    }
}

// ============================================================================
// gemm1: fp16 1-product. C = Ah*Bh^T, fp32 out (final projection).
// ============================================================================
#define STG1 (2 * PMAT)            // 20480
#define SMEM1 (2 * STG1)           // 40960

__global__ __launch_bounds__(256, 2)
void gemm1(const __half* __restrict__ Ah, const __half* __restrict__ Bh,
           float* __restrict__ Cf) {
    extern __shared__ __align__(1024) char sm[];
    const uint32_t wbase = smem_u32(sm);
    const int tid = threadIdx.x;
    const int wid = tid >> 5, lane = tid & 31;
    const int row0 = blockIdx.y * 128, col0 = blockIdx.x * 128;

    const int lrow = tid >> 2, lseg = tid & 3;
    const __half* pA = Ah + (size_t)(row0 + lrow) * KK + lseg * 8;
    const __half* pB = Bh + (size_t)(col0 + lrow) * KK + lseg * 8;
    const uint32_t doff = (uint32_t)lrow * PITCH + lseg * 16;
    const size_t rstep = (size_t)64 * KK;

#define LOAD1(chunk, buf)                                                      \
    do {                                                                       \
        const uint32_t sb_ = wbase + (buf) * STG1 + doff;                      \
        const size_t ko_ = (size_t)(chunk) * 32;                               \
        CPA16(sb_,                      pA + ko_);                             \
        CPA16(sb_ + 64 * PITCH,         pA + ko_ + rstep);                     \
        CPA16(sb_ + PMAT,               pB + ko_);                             \
        CPA16(sb_ + PMAT + 64 * PITCH,  pB + ko_ + rstep);                     \
        asm volatile("cp.async.commit_group;" ::: "memory");                   \
    } while (0)

    const int wm = (wid & 3) * 32, wn = (wid >> 2) * 64;
    const int l = lane;
    const uint32_t aoff =
        (uint32_t)(wm + (l & 7) + 8 * ((l >> 3) & 1)) * PITCH + (l >> 4) * 16;
    const uint32_t boff = PMAT +
        (uint32_t)(wn + (l & 7) + 8 * (l >> 4)) * PITCH + ((l >> 3) & 1) * 16;

    float acc[2][8][4];
#pragma unroll
    for (int i = 0; i < 2; i++)
#pragma unroll
        for (int j = 0; j < 8; j++)
#pragma unroll
            for (int q = 0; q < 4; q++) acc[i][j][q] = 0.f;

    LOAD1(0, 0);

    for (int i = 0; i < NCH; i++) {
        __syncthreads();
        if (i + 1 < NCH) {
            LOAD1(i + 1, (i + 1) & 1);
            asm volatile("cp.async.wait_group 1;" ::: "memory");
        } else {
            asm volatile("cp.async.wait_group 0;" ::: "memory");
        }
        __syncthreads();

        const uint32_t sb = wbase + (i & 1) * STG1;
#pragma unroll
        for (int ks = 0; ks < 2; ks++) {
            uint32_t a4[2][4];
            const uint32_t ka = sb + aoff + ks * 32;
#pragma unroll
            for (int mt = 0; mt < 2; mt++)
                LDSM4(a4[mt], ka + mt * 16 * PITCH);
            const uint32_t kb = sb + boff + ks * 32;
#pragma unroll
            for (int p = 0; p < 4; p++) {
                uint32_t bh4[4];
                LDSM4(bh4, kb + p * 16 * PITCH);
#pragma unroll
                for (int mt = 0; mt < 2; mt++) {
                    MMAH(acc[mt][2 * p],     a4[mt], bh4[0], bh4[1]);
                    MMAH(acc[mt][2 * p + 1], a4[mt], bh4[2], bh4[3]);
                }
            }
        }
    }

    const int mrow = lane >> 2, ncol = 2 * (lane & 3);
#pragma unroll
    for (int mt = 0; mt < 2; mt++) {
#pragma unroll
        for (int part = 0; part < 2; part++) {
            const int m = row0 + wm + mt * 16 + mrow + part * 8;
            const size_t rowb = (size_t)m * NN + col0 + wn + ncol;
#pragma unroll
            for (int nt = 0; nt < 8; nt++) {
                *(float2*)(Cf + rowb + nt * 8) =
                    make_float2(acc[mt][nt][2 * part], acc[mt][nt][2 * part + 1]);
            }
        }
    }
}

// ============================================================================
// Flash attention: S = QK^T bf16 3-product; PV fp16 1-product (V single fp16).
// BQ=BK=64, hd=128, 128 threads, P in registers (C-frag == A-frag).
// ============================================================================
#define FP 272
#define FQH 0
#define FQL 17408
#define FKH 34816
#define FKL 52224
#define FVH 69632
#define FLASH_SMEM 87040

__global__ __launch_bounds__(128, 2)
void flash_mma(const __nv_bfloat16* __restrict__ Qh, const __nv_bfloat16* __restrict__ Ql,
               const __nv_bfloat16* __restrict__ Kh, const __nv_bfloat16* __restrict__ Kl,
               const __half* __restrict__ Vh, __half* __restrict__ Oh) {
    extern __shared__ __align__(1024) char sm[];
    const uint32_t smb = smem_u32(sm);
    const int tid = threadIdx.x;
    const int wid = tid >> 5, lane = tid & 31;
    const int bh_ = blockIdx.y;
    const int b = bh_ >> 5, h = bh_ & 31;
    const int qb = (gridDim.x - 1) - blockIdx.x;   // heavy tiles launch first
    const int q0 = qb * 64;
    const float scale = 0.08838834764831845f;

    const size_t gbase = ((size_t)b * TLEN) * NN + (size_t)h * 128;

    {
        const int qr = tid >> 1, qc = (tid & 1) * 8;
        const size_t gq = gbase + (size_t)(q0 + qr) * NN + qc * 8;
        const uint32_t sq = smb + qr * FP + qc * 16;
#pragma unroll
        for (int c = 0; c < 8; c++) {
            CPA16(sq + FQH + c * 16, Qh + gq + c * 8);
            CPA16(sq + FQL + c * 16, Ql + gq + c * 8);
        }
        asm volatile("cp.async.commit_group;" ::: "memory");
    }

    const int wm = wid * 16;
    const int l = lane;
    const uint32_t aoff =
        (uint32_t)(wm + (l & 7) + 8 * ((l >> 3) & 1)) * FP + (l >> 4) * 16;
    const uint32_t boff =
        (uint32_t)((l & 7) + 8 * (l >> 4)) * FP + ((l >> 3) & 1) * 16;
    const uint32_t voff =
        (uint32_t)((l & 7) + 8 * ((l >> 3) & 1)) * FP + (l >> 4) * 16;

    float o[16][4];
#pragma unroll
    for (int i = 0; i < 16; i++)
#pragma unroll
        for (int j = 0; j < 4; j++) o[i][j] = 0.f;
    float m0 = -INFINITY, m1 = -INFINITY, l0 = 0.f, l1 = 0.f;

    const int grow0 = q0 + wm + (lane >> 2);
    const int grow1 = grow0 + 8;

    for (int kt = 0; kt <= qb; kt++) {
        const int k0 = kt * 64;
        __syncthreads();

        {
            const int kr = tid >> 1, kc = (tid & 1) * 8;
            const size_t gk = gbase + (size_t)(k0 + kr) * NN + kc * 8;
            const uint32_t sk = smb + kr * FP + kc * 16;
#pragma unroll
            for (int c = 0; c < 8; c++) {
                CPA16(sk + FKH + c * 16, Kh + gk + c * 8);
                CPA16(sk + FKL + c * 16, Kl + gk + c * 8);
                CPA16(sk + FVH + c * 16, Vh + gk + c * 8);
            }
            asm volatile("cp.async.commit_group;" ::: "memory");
            asm volatile("cp.async.wait_group 0;" ::: "memory");
        }
        __syncthreads();

        // S = Q K^T, bf16 3-product
        float s[8][4];
#pragma unroll
        for (int i = 0; i < 8; i++)
#pragma unroll
            for (int j = 0; j < 4; j++) s[i][j] = 0.f;

#pragma unroll
        for (int ks = 0; ks < 8; ks++) {
            uint32_t qh4[4], ql4[4];
            LDSM4(qh4, smb + FQH + aoff + ks * 32);
            LDSM4(ql4, smb + FQL + aoff + ks * 32);
#pragma unroll
            for (int p = 0; p < 4; p++) {
                uint32_t kh4[4], kl4[4];
                LDSM4(kh4, smb + FKH + boff + p * 16 * FP + ks * 32);
                LDSM4(kl4, smb + FKL + boff + p * 16 * FP + ks * 32);
                MMAB(s[2 * p],     qh4, kh4[0], kh4[1]);
                MMAB(s[2 * p + 1], qh4, kh4[2], kh4[3]);
                MMAB(s[2 * p],     qh4, kl4[0], kl4[1]);
                MMAB(s[2 * p + 1], qh4, kl4[2], kl4[3]);
                MMAB(s[2 * p],     ql4, kh4[0], kh4[1]);
                MMAB(s[2 * p + 1], ql4, kh4[2], kh4[3]);
            }
        }

        if (kt == qb) {
#pragma unroll
            for (int nt = 0; nt < 8; nt++) {
                const int cbase = k0 + nt * 8 + 2 * (lane & 3);
                s[nt][0] = (cbase     > grow0) ? -INFINITY : s[nt][0] * scale;
                s[nt][1] = (cbase + 1 > grow0) ? -INFINITY : s[nt][1] * scale;
                s[nt][2] = (cbase     > grow1) ? -INFINITY : s[nt][2] * scale;
                s[nt][3] = (cbase + 1 > grow1) ? -INFINITY : s[nt][3] * scale;
            }
        } else {
#pragma unroll
            for (int nt = 0; nt < 8; nt++)
#pragma unroll
                for (int e = 0; e < 4; e++) s[nt][e] *= scale;
        }

        float rmax0 = -INFINITY, rmax1 = -INFINITY;
#pragma unroll
        for (int nt = 0; nt < 8; nt++) {
            rmax0 = fmaxf(rmax0, fmaxf(s[nt][0], s[nt][1]));
            rmax1 = fmaxf(rmax1, fmaxf(s[nt][2], s[nt][3]));
        }
        rmax0 = fmaxf(rmax0, __shfl_xor_sync(0xffffffff, rmax0, 1));
        rmax0 = fmaxf(rmax0, __shfl_xor_sync(0xffffffff, rmax0, 2));
        rmax1 = fmaxf(rmax1, __shfl_xor_sync(0xffffffff, rmax1, 1));
        rmax1 = fmaxf(rmax1, __shfl_xor_sync(0xffffffff, rmax1, 2));

        const float mn0 = fmaxf(m0, rmax0), mn1 = fmaxf(m1, rmax1);
        const float a0 = __expf(m0 - mn0), a1 = __expf(m1 - mn1);

        float sum0 = 0.f, sum1 = 0.f;
#pragma unroll
        for (int nt = 0; nt < 8; nt++) {
            s[nt][0] = __expf(s[nt][0] - mn0);
            s[nt][1] = __expf(s[nt][1] - mn0);
            s[nt][2] = __expf(s[nt][2] - mn1);
            s[nt][3] = __expf(s[nt][3] - mn1);
            sum0 += s[nt][0] + s[nt][1];
            sum1 += s[nt][2] + s[nt][3];
        }
        sum0 += __shfl_xor_sync(0xffffffff, sum0, 1);
        sum0 += __shfl_xor_sync(0xffffffff, sum0, 2);
        sum1 += __shfl_xor_sync(0xffffffff, sum1, 1);
        sum1 += __shfl_xor_sync(0xffffffff, sum1, 2);

        l0 = l0 * a0 + sum0;
        l1 = l1 * a1 + sum1;
        m0 = mn0;
        m1 = mn1;

#pragma unroll
        for (int nt = 0; nt < 16; nt++) {
            o[nt][0] *= a0; o[nt][1] *= a0;
            o[nt][2] *= a1; o[nt][3] *= a1;
        }

        // pack P to fp16 A-frags
        uint32_t ph[4][4];
#pragma unroll
        for (int ks2 = 0; ks2 < 4; ks2++) {
            ph[ks2][0] = packh(s[2 * ks2][0],     s[2 * ks2][1]);
            ph[ks2][1] = packh(s[2 * ks2][2],     s[2 * ks2][3]);
            ph[ks2][2] = packh(s[2 * ks2 + 1][0], s[2 * ks2 + 1][1]);
            ph[ks2][3] = packh(s[2 * ks2 + 1][2], s[2 * ks2 + 1][3]);
        }

        // O += P V, fp16 1-product
#pragma unroll
        for (int ks2 = 0; ks2 < 4; ks2++) {
#pragma unroll
            for (int ntp = 0; ntp < 8; ntp++) {
                uint32_t vh4[4];
                LDSM4T(vh4, smb + FVH + voff + ks2 * 16 * FP + ntp * 32);
                MMAH(o[2 * ntp],     ph[ks2], vh4[0], vh4[1]);
                MMAH(o[2 * ntp + 1], ph[ks2], vh4[2], vh4[3]);
            }
        }
    }

    // epilogue: normalize, pack fp16, store
    const float inv0 = 1.f / l0, inv1 = 1.f / l1;
    const size_t rb0 = gbase + (size_t)grow0 * NN + 2 * (lane & 3);
    const size_t rb1 = gbase + (size_t)grow1 * NN + 2 * (lane & 3);
#pragma unroll
    for (int nt = 0; nt < 16; nt++) {
        *(uint32_t*)(Oh + rb0 + nt * 8) = packh(o[nt][0] * inv0, o[nt][1] * inv0);
        *(uint32_t*)(Oh + rb1 + nt * 8) = packh(o[nt][2] * inv1, o[nt][3] * inv1);
    }
}

// ============================================================================
// Launch
// ============================================================================
extern "C" void kernel_launch(void* const* d_in, const int* in_sizes, int n_in,
                              void* d_out, int out_size) {
    const float* x  = (const float*)d_in[0];
    const float* wq = (const float*)d_in[1];
    const float* wk = (const float*)d_in[2];
    const float* wv = (const float*)d_in[3];
    const float* wo = (const float*)d_in[4];
    float* out = (float*)d_out;

    __half *xfh, *wqh, *wql, *wkh, *wkl, *wvh, *woh, *vah, *aoh;
    __nv_bfloat16 *qah, *qal, *kah, *kal;
    cudaGetSymbolAddress((void**)&xfh, g_xf_h);
    cudaGetSymbolAddress((void**)&wqh, g_wq_h); cudaGetSymbolAddress((void**)&wql, g_wq_l);
    cudaGetSymbolAddress((void**)&wkh, g_wk_h); cudaGetSymbolAddress((void**)&wkl, g_wk_l);
    cudaGetSymbolAddress((void**)&wvh, g_wv_h);
    cudaGetSymbolAddress((void**)&woh, g_wo_h);
    cudaGetSymbolAddress((void**)&vah, g_va_h);
    cudaGetSymbolAddress((void**)&aoh, g_ao_h);
    cudaGetSymbolAddress((void**)&qah, g_qa_h); cudaGetSymbolAddress((void**)&qal, g_qa_l);
    cudaGetSymbolAddress((void**)&kah, g_ka_h); cudaGetSymbolAddress((void**)&kal, g_ka_l);

    cudaFuncSetAttribute(proj_all, cudaFuncAttributeMaxDynamicSharedMemorySize, PSMEM);
    cudaFuncSetAttribute(gemm1, cudaFuncAttributeMaxDynamicSharedMemorySize, SMEM1);
    cudaFuncSetAttribute(flash_mma, cudaFuncAttributeMaxDynamicSharedMemorySize,
                         FLASH_SMEM);

    const int splitBlocks = (MM * 4096) / (4 * 256);   // 16384
    pack_f16 <<<splitBlocks, 256>>>((const float4*)x,  (uint2*)xfh);
    split_h16<<<splitBlocks, 256>>>((const float4*)wq, (uint2*)wqh, (uint2*)wql);
    split_h16<<<splitBlocks, 256>>>((const float4*)wk, (uint2*)wkh, (uint2*)wkl);
    pack_f16 <<<splitBlocks, 256>>>((const float4*)wv, (uint2*)wvh);
    pack_f16 <<<splitBlocks, 256>>>((const float4*)wo, (uint2*)woh);

    dim3 gproj(NN / 128, MM / 128, 3);   // Q, K, V in one launch (V last)
    proj_all<<<gproj, 256, PSMEM>>>(xfh, wqh, wql, wkh, wkl, wvh,
                                    qah, qal, kah, kal, vah);

    dim3 fgrid(TLEN / 64, 2 * 32);       // heavy-first inside kernel
    flash_mma<<<fgrid, 128, FLASH_SMEM>>>(qah, qal, kah, kal, vah, aoh);

    dim3 ggrid(NN / 128, MM / 128);
    gemm1<<<ggrid, 256, SMEM1>>>(aoh, woh, out);   // output projection
}

// round 9
// speedup vs baseline: 7.0292x; 1.0670x over previous
#include <cuda_runtime.h>
#include <cuda_bf16.h>
#include <cuda_fp16.h>
#include <cstdint>
#include <math.h>

// ----------------------------------------------------------------------------
// B=2, T=2048, C=4096, H=32, hd=128.  M=N=K=4096.
// Precision plan (validated quadrature model, ~2e-4 per fp16 source):
//   Q/K projections: x_fp16 * (W_hi + W_lo)_fp16  -> 2-product HMMA.
//   V/output path:   fp16 1-product.
//   Flash S = QK^T:  bf16 3-product.  Flash PV: fp16 1-product.
// Rotary (theta = t) fused in Q/K projection epilogue.
// R9: flash BQ=128 w/ double-buffered K/V prefetch (1 CTA/SM, 256 thr);
//     GEMMs use 3-stage cp.async pipeline with a single sync per chunk.
// ----------------------------------------------------------------------------

#define MM 4096
#define NN 4096
#define KK 4096
#define TLEN 2048

// fp16 operands
__device__ __half g_xf_h[(size_t)MM * KK];
__device__ __half g_wq_h[(size_t)NN * KK], g_wq_l[(size_t)NN * KK];
__device__ __half g_wk_h[(size_t)NN * KK], g_wk_l[(size_t)NN * KK];
__device__ __half g_wv_h[(size_t)NN * KK];
__device__ __half g_wo_h[(size_t)NN * KK];
__device__ __half g_va_h[(size_t)MM * NN];
__device__ __half g_ao_h[(size_t)MM * NN];
// bf16 hi/lo Q,K activations
__device__ __nv_bfloat16 g_qa_h[(size_t)MM * NN], g_qa_l[(size_t)MM * NN];
__device__ __nv_bfloat16 g_ka_h[(size_t)MM * NN], g_ka_l[(size_t)MM * NN];

__device__ __forceinline__ uint32_t smem_u32(const void* p) {
    uint32_t a;
    asm("{ .reg .u64 t; cvta.to.shared.u64 t, %1; cvt.u32.u64 %0, t; }"
        : "=r"(a) : "l"(p));
    return a;
}

#define LDSM4(r, a)                                                            \
    asm volatile("ldmatrix.sync.aligned.m8n8.x4.shared.b16 {%0,%1,%2,%3}, [%4];" \
                 : "=r"((r)[0]), "=r"((r)[1]), "=r"((r)[2]), "=r"((r)[3])      \
                 : "r"(a))

#define LDSM4T(r, a)                                                           \
    asm volatile("ldmatrix.sync.aligned.m8n8.x4.trans.shared.b16 {%0,%1,%2,%3}, [%4];" \
                 : "=r"((r)[0]), "=r"((r)[1]), "=r"((r)[2]), "=r"((r)[3])      \
                 : "r"(a))

#define MMAB(c, a, b0, b1)                                                     \
    asm volatile("mma.sync.aligned.m16n8k16.row.col.f32.bf16.bf16.f32 "        \
                 "{%0,%1,%2,%3},{%4,%5,%6,%7},{%8,%9},{%0,%1,%2,%3};"          \
                 : "+f"((c)[0]), "+f"((c)[1]), "+f"((c)[2]), "+f"((c)[3])      \
                 : "r"((a)[0]), "r"((a)[1]), "r"((a)[2]), "r"((a)[3]),         \
                   "r"(b0), "r"(b1))

#define MMAH(c, a, b0, b1)                                                     \
    asm volatile("mma.sync.aligned.m16n8k16.row.col.f32.f16.f16.f32 "          \
                 "{%0,%1,%2,%3},{%4,%5,%6,%7},{%8,%9},{%0,%1,%2,%3};"          \
                 : "+f"((c)[0]), "+f"((c)[1]), "+f"((c)[2]), "+f"((c)[3])      \
                 : "r"((a)[0]), "r"((a)[1]), "r"((a)[2]), "r"((a)[3]),         \
                   "r"(b0), "r"(b1))

#define CPA16(dst, src)                                                        \
    asm volatile("cp.async.cg.shared.global [%0], [%1], 16;"                   \
                 :: "r"(dst), "l"(src) : "memory")
#define CPCOMMIT() asm volatile("cp.async.commit_group;" ::: "memory")
#define CPWAIT1()  asm volatile("cp.async.wait_group 1;" ::: "memory")
#define CPWAIT0()  asm volatile("cp.async.wait_group 0;" ::: "memory")

// bf16 split: hi = truncate, lo = rn(residual)
__device__ __forceinline__ void split2b(float x0, float x1,
                                        uint32_t& hi, uint32_t& lo) {
    uint32_t u0 = __float_as_uint(x0), u1 = __float_as_uint(x1);
    hi = __byte_perm(u0, u1, 0x7632);
    float l0 = x0 - __uint_as_float(u0 & 0xFFFF0000u);
    float l1 = x1 - __uint_as_float(u1 & 0xFFFF0000u);
    asm("cvt.rn.bf16x2.f32 %0, %1, %2;" : "=r"(lo) : "f"(l1), "f"(l0));
}

__device__ __forceinline__ uint32_t packh(float x0, float x1) {
    uint32_t r;
    asm("cvt.rn.f16x2.f32 %0, %1, %2;" : "=r"(r) : "f"(x1), "f"(x0));
    return r;
}

__device__ __forceinline__ void split2h(float x0, float x1,
                                        uint32_t& hi, uint32_t& lo) {
    hi = packh(x0, x1);
    float2 b = __half22float2(*reinterpret_cast<__half2*>(&hi));
    lo = packh(x0 - b.x, x1 - b.y);
}

// ============================================================================
// Pack / split kernels
// ============================================================================
__global__ __launch_bounds__(256)
void pack_f16(const float4* __restrict__ in, uint2* __restrict__ hi) {
    size_t i = (size_t)blockIdx.x * 256 + threadIdx.x;
    float4 v = in[i];
    hi[i] = make_uint2(packh(v.x, v.y), packh(v.z, v.w));
}

__global__ __launch_bounds__(256)
void split_h16(const float4* __restrict__ in, uint2* __restrict__ hi,
               uint2* __restrict__ lo) {
    size_t i = (size_t)blockIdx.x * 256 + threadIdx.x;
    float4 v = in[i];
    uint2 h, l;
    split2h(v.x, v.y, h.x, l.x);
    split2h(v.z, v.w, h.y, l.y);
    hi[i] = h;
    lo[i] = l;
}

// ============================================================================
// proj_all: fused Q/K/V projections.  C = x * W^T.
// z=0: Q (2-product, rotary, bf16 hi/lo out); z=1: K (same); z=2: V (1-prod).
// CTA 128x128, 8 warps 32x64, K-chunk 32, 3-stage cp.async, 1 sync/chunk.
// ============================================================================
#define PITCH 80
#define PMAT (128 * PITCH)         // 10240
#define PSTG (3 * PMAT)            // 30720
#define PSMEM (3 * PSTG)           // 92160  (3 stages)
#define NCH (KK / 32)              // 128

__global__ __launch_bounds__(256, 2)
void proj_all(const __half* __restrict__ Ah,
              const __half* __restrict__ Wqh, const __half* __restrict__ Wql,
              const __half* __restrict__ Wkh, const __half* __restrict__ Wkl,
              const __half* __restrict__ Wvh,
              __nv_bfloat16* __restrict__ Qh, __nv_bfloat16* __restrict__ Qlo,
              __nv_bfloat16* __restrict__ Kh, __nv_bfloat16* __restrict__ Klo,
              __half* __restrict__ Vh) {
    extern __shared__ __align__(1024) char sm[];
    const uint32_t wbase = smem_u32(sm);
    const int tid = threadIdx.x;
    const int wid = tid >> 5, lane = tid & 31;
    const int row0 = blockIdx.y * 128, col0 = blockIdx.x * 128;
    const int z = blockIdx.z;
    const bool twoP = (z < 2);

    const __half* Bh_ = (z == 0) ? Wqh : (z == 1) ? Wkh : Wvh;
    const __half* Bl_ = (z == 1) ? Wkl : Wql;   // valid dummy when z==2

    const int lrow = tid >> 2, lseg = tid & 3;
    const __half* pA  = Ah  + (size_t)(row0 + lrow) * KK + lseg * 8;
    const __half* pBh = Bh_ + (size_t)(col0 + lrow) * KK + lseg * 8;
    const __half* pBl = Bl_ + (size_t)(col0 + lrow) * KK + lseg * 8;
    const uint32_t doff = (uint32_t)lrow * PITCH + lseg * 16;
    const size_t rstep = (size_t)64 * KK;

#define LOADP(chunk, buf)                                                      \
    do {                                                                       \
        const uint32_t sb_ = wbase + (buf) * PSTG + doff;                      \
        const size_t ko_ = (size_t)(chunk) * 32;                               \
        CPA16(sb_,                      pA + ko_);                             \
        CPA16(sb_ + 64 * PITCH,         pA + ko_ + rstep);                     \
        CPA16(sb_ + PMAT,               pBh + ko_);                            \
        CPA16(sb_ + PMAT + 64 * PITCH,  pBh + ko_ + rstep);                    \
        if (twoP) {                                                            \
            CPA16(sb_ + 2 * PMAT,              pBl + ko_);                     \
            CPA16(sb_ + 2 * PMAT + 64 * PITCH, pBl + ko_ + rstep);             \
        }                                                                      \
        CPCOMMIT();                                                            \
    } while (0)

    const int wm = (wid & 3) * 32, wn = (wid >> 2) * 64;
    const int l = lane;
    const uint32_t aoff =
        (uint32_t)(wm + (l & 7) + 8 * ((l >> 3) & 1)) * PITCH + (l >> 4) * 16;
    const uint32_t boff = PMAT +
        (uint32_t)(wn + (l & 7) + 8 * (l >> 4)) * PITCH + ((l >> 3) & 1) * 16;

    float acc[2][8][4];
#pragma unroll
    for (int i = 0; i < 2; i++)
#pragma unroll
        for (int j = 0; j < 8; j++)
#pragma unroll
            for (int q = 0; q < 4; q++) acc[i][j][q] = 0.f;

    LOADP(0, 0);
    LOADP(1, 1);

    int buf = 0;
    for (int i = 0; i < NCH; i++) {
        if (i + 1 < NCH) { CPWAIT1(); } else { CPWAIT0(); }
        __syncthreads();
        if (i + 2 < NCH) {
            int nb = buf + 2; if (nb >= 3) nb -= 3;
            LOADP(i + 2, nb);
        }

        const uint32_t sb = wbase + buf * PSTG;
#pragma unroll
        for (int ks = 0; ks < 2; ks++) {
            uint32_t a4[2][4];
            const uint32_t ka = sb + aoff + ks * 32;
#pragma unroll
            for (int mt = 0; mt < 2; mt++)
                LDSM4(a4[mt], ka + mt * 16 * PITCH);
            const uint32_t kb = sb + boff + ks * 32;
#pragma unroll
            for (int p = 0; p < 4; p++) {
                uint32_t bh4[4];
                LDSM4(bh4, kb + p * 16 * PITCH);
#pragma unroll
                for (int mt = 0; mt < 2; mt++) {
                    MMAH(acc[mt][2 * p],     a4[mt], bh4[0], bh4[1]);
                    MMAH(acc[mt][2 * p + 1], a4[mt], bh4[2], bh4[3]);
                }
                if (twoP) {
                    uint32_t bl4[4];
                    LDSM4(bl4, kb + p * 16 * PITCH + PMAT);
#pragma unroll
                    for (int mt = 0; mt < 2; mt++) {
                        MMAH(acc[mt][2 * p],     a4[mt], bl4[0], bl4[1]);
                        MMAH(acc[mt][2 * p + 1], a4[mt], bl4[2], bl4[3]);
                    }
                }
            }
        }
        if (++buf == 3) buf = 0;
    }

    // epilogue
    const int mrow = lane >> 2, ncol = 2 * (lane & 3);
    __nv_bfloat16* Ch = (z == 0) ? Qh : Kh;
    __nv_bfloat16* Cl = (z == 0) ? Qlo : Klo;
#pragma unroll
    for (int mt = 0; mt < 2; mt++) {
#pragma unroll
        for (int part = 0; part < 2; part++) {
            const int m = row0 + wm + mt * 16 + mrow + part * 8;
            const size_t rowb = (size_t)m * NN + col0 + wn + ncol;
            if (twoP) {
                float sn, cs;
                sincosf((float)(m & (TLEN - 1)), &sn, &cs);
#pragma unroll
                for (int nt = 0; nt < 8; nt++) {
                    float x0 = acc[mt][nt][2 * part];
                    float x1 = acc[mt][nt][2 * part + 1];
                    float y0 = x0 * cs - x1 * sn;
                    float y1 = x0 * sn + x1 * cs;
                    uint32_t hi, lo;
                    split2b(y0, y1, hi, lo);
                    *(uint32_t*)(Ch + rowb + nt * 8) = hi;
                    *(uint32_t*)(Cl + rowb + nt * 8) = lo;
                }
            } else {
#pragma unroll
                for (int nt = 0; nt < 8; nt++) {
                    *(uint32_t*)(Vh + rowb + nt * 8) =
                        packh(acc[mt][nt][2 * part], acc[mt][nt][2 * part + 1]);
                }
            }
        }
    }
}

// ============================================================================
// gemm1: fp16 1-product. C = Ah*Bh^T, fp32 out. 3-stage pipeline.
// ============================================================================
#define STG1 (2 * PMAT)            // 20480
#define SMEM1 (3 * STG1)           // 61440

__global__ __launch_bounds__(256, 2)
void gemm1(const __half* __restrict__ Ah, const __half* __restrict__ Bh,
           float* __restrict__ Cf) {
    extern __shared__ __align__(1024) char sm[];
    const uint32_t wbase = smem_u32(sm);
    const int tid = threadIdx.x;
    const int wid = tid >> 5, lane = tid & 31;
    const int row0 = blockIdx.y * 128, col0 = blockIdx.x * 128;

    const int lrow = tid >> 2, lseg = tid & 3;
    const __half* pA = Ah + (size_t)(row0 + lrow) * KK + lseg * 8;
    const __half* pB = Bh + (size_t)(col0 + lrow) * KK + lseg * 8;
    const uint32_t doff = (uint32_t)lrow * PITCH + lseg * 16;
    const size_t rstep = (size_t)64 * KK;

#define LOAD1(chunk, buf)                                                      \
    do {                                                                       \
        const uint32_t sb_ = wbase + (buf) * STG1 + doff;                      \
        const size_t ko_ = (size_t)(chunk) * 32;                               \
        CPA16(sb_,                      pA + ko_);                             \
        CPA16(sb_ + 64 * PITCH,         pA + ko_ + rstep);                     \
        CPA16(sb_ + PMAT,               pB + ko_);                             \
        CPA16(sb_ + PMAT + 64 * PITCH,  pB + ko_ + rstep);                     \
        CPCOMMIT();                                                            \
    } while (0)

    const int wm = (wid & 3) * 32, wn = (wid >> 2) * 64;
    const int l = lane;
    const uint32_t aoff =
        (uint32_t)(wm + (l & 7) + 8 * ((l >> 3) & 1)) * PITCH + (l >> 4) * 16;
    const uint32_t boff = PMAT +
        (uint32_t)(wn + (l & 7) + 8 * (l >> 4)) * PITCH + ((l >> 3) & 1) * 16;

    float acc[2][8][4];
#pragma unroll
    for (int i = 0; i < 2; i++)
#pragma unroll
        for (int j = 0; j < 8; j++)
#pragma unroll
            for (int q = 0; q < 4; q++) acc[i][j][q] = 0.f;

    LOAD1(0, 0);
    LOAD1(1, 1);

    int buf = 0;
    for (int i = 0; i < NCH; i++) {
        if (i + 1 < NCH) { CPWAIT1(); } else { CPWAIT0(); }
        __syncthreads();
        if (i + 2 < NCH) {
            int nb = buf + 2; if (nb >= 3) nb -= 3;
            LOAD1(i + 2, nb);
        }

        const uint32_t sb = wbase + buf * STG1;
#pragma unroll
        for (int ks = 0; ks < 2; ks++) {
            uint32_t a4[2][4];
            const uint32_t ka = sb + aoff + ks * 32;
#pragma unroll
            for (int mt = 0; mt < 2; mt++)
                LDSM4(a4[mt], ka + mt * 16 * PITCH);
            const uint32_t kb = sb + boff + ks * 32;
#pragma unroll
            for (int p = 0; p < 4; p++) {
                uint32_t bh4[4];
                LDSM4(bh4, kb + p * 16 * PITCH);
#pragma unroll
                for (int mt = 0; mt < 2; mt++) {
                    MMAH(acc[mt][2 * p],     a4[mt], bh4[0], bh4[1]);
                    MMAH(acc[mt][2 * p + 1], a4[mt], bh4[2], bh4[3]);
                }
            }
        }
        if (++buf == 3) buf = 0;
    }

    const int mrow = lane >> 2, ncol = 2 * (lane & 3);
#pragma unroll
    for (int mt = 0; mt < 2; mt++) {
#pragma unroll
        for (int part = 0; part < 2; part++) {
            const int m = row0 + wm + mt * 16 + mrow + part * 8;
            const size_t rowb = (size_t)m * NN + col0 + wn + ncol;
#pragma unroll
            for (int nt = 0; nt < 8; nt++) {
                *(float2*)(Cf + rowb + nt * 8) =
                    make_float2(acc[mt][nt][2 * part], acc[mt][nt][2 * part + 1]);
            }
        }
    }
}

// ============================================================================
// Flash attention: BQ=128, BK=64, hd=128, 256 threads, 1 CTA/SM.
// S = QK^T bf16 3-product; PV fp16 1-product. K/V double-buffered prefetch.
// ============================================================================
#define FP 272
#define FQH 0
#define FQL 34816
#define FKV 69632
#define FSTG 52224          // KH | KL(+17408) | VH(+34816)
#define FLASH_SMEM (FKV + 2 * FSTG)   // 174080

__global__ __launch_bounds__(256, 1)
void flash_mma(const __nv_bfloat16* __restrict__ Qh, const __nv_bfloat16* __restrict__ Ql,
               const __nv_bfloat16* __restrict__ Kh, const __nv_bfloat16* __restrict__ Kl,
               const __half* __restrict__ Vh, __half* __restrict__ Oh) {
    extern __shared__ __align__(1024) char sm[];
    const uint32_t smb = smem_u32(sm);
    const int tid = threadIdx.x;
    const int wid = tid >> 5, lane = tid & 31;   // wid 0..7
    const int bh_ = blockIdx.y;
    const int b = bh_ >> 5, h = bh_ & 31;
    const int jt = (gridDim.x - 1) - blockIdx.x;   // heavy tiles first
    const int q0 = jt * 128;
    const int nkt = 2 * jt + 2;
    const float scale = 0.08838834764831845f;

    const size_t gbase = ((size_t)b * TLEN) * NN + (size_t)h * 128;

    // Q tile (128 rows, hi/lo): thread -> row tid>>1, half (tid&1)
    {
        const int qr = tid >> 1, qc = (tid & 1) * 8;
        const size_t gq = gbase + (size_t)(q0 + qr) * NN + qc * 8;
        const uint32_t sq = smb + qr * FP + qc * 16;
#pragma unroll
        for (int c = 0; c < 8; c++) {
            CPA16(sq + FQH + c * 16, Qh + gq + c * 8);
            CPA16(sq + FQL + c * 16, Ql + gq + c * 8);
        }
        CPCOMMIT();
    }

    // K/V loader: thread -> row tid>>2, quarter (tid&3)
    const int kvr = tid >> 2, kvs = tid & 3;
#define LOADKV(kt_, buf_)                                                      \
    do {                                                                       \
        const size_t gk_ = gbase + (size_t)((kt_) * 64 + kvr) * NN + kvs * 32; \
        const uint32_t sk_ = smb + FKV + (buf_) * FSTG + kvr * FP + kvs * 64;  \
        _Pragma("unroll")                                                      \
        for (int c = 0; c < 4; c++) {                                          \
            CPA16(sk_ + c * 16,         Kh + gk_ + c * 8);                     \
            CPA16(sk_ + c * 16 + 17408, Kl + gk_ + c * 8);                     \
            CPA16(sk_ + c * 16 + 34816, Vh + gk_ + c * 8);                     \
        }                                                                      \
        CPCOMMIT();                                                            \
    } while (0)

    LOADKV(0, 0);

    const int wm = wid * 16;
    const int l = lane;
    const uint32_t aoff =
        (uint32_t)(wm + (l & 7) + 8 * ((l >> 3) & 1)) * FP + (l >> 4) * 16;
    const uint32_t boff =
        (uint32_t)((l & 7) + 8 * (l >> 4)) * FP + ((l >> 3) & 1) * 16;
    const uint32_t voff =
        (uint32_t)((l & 7) + 8 * ((l >> 3) & 1)) * FP + (l >> 4) * 16;

    float o[16][4];
#pragma unroll
    for (int i = 0; i < 16; i++)
#pragma unroll
        for (int j = 0; j < 4; j++) o[i][j] = 0.f;
    float m0 = -INFINITY, m1 = -INFINITY, l0 = 0.f, l1 = 0.f;

    const int grow0 = q0 + wm + (lane >> 2);
    const int grow1 = grow0 + 8;

    for (int kt = 0; kt < nkt; kt++) {
        const int k0 = kt * 64;
        __syncthreads();   // all warps done with buf (kt+1)&1 from compute(kt-1)
        if (kt + 1 < nkt) {
            LOADKV(kt + 1, (kt + 1) & 1);
            CPWAIT1();
        } else {
            CPWAIT0();
        }
        __syncthreads();   // buf kt&1 visible

        // Fully-masked warp-tile combos do no math (loads stay cooperative)
        if (k0 > q0 + wm + 15) continue;

        const uint32_t kvb = smb + FKV + (kt & 1) * FSTG;

        // ---- S = Q K^T, bf16 3-product ----
        float s[8][4];
#pragma unroll
        for (int i = 0; i < 8; i++)
#pragma unroll
            for (int j = 0; j < 4; j++) s[i][j] = 0.f;

#pragma unroll
        for (int ks = 0; ks < 8; ks++) {
            uint32_t qh4[4], ql4[4];
            LDSM4(qh4, smb + FQH + aoff + ks * 32);
            LDSM4(ql4, smb + FQL + aoff + ks * 32);
#pragma unroll
            for (int p = 0; p < 4; p++) {
                uint32_t kh4[4], kl4[4];
                LDSM4(kh4, kvb + boff + p * 16 * FP + ks * 32);
                LDSM4(kl4, kvb + 17408 + boff + p * 16 * FP + ks * 32);
                MMAB(s[2 * p],     qh4, kh4[0], kh4[1]);
                MMAB(s[2 * p + 1], qh4, kh4[2], kh4[3]);
                MMAB(s[2 * p],     qh4, kl4[0], kl4[1]);
                MMAB(s[2 * p + 1], qh4, kl4[2], kl4[3]);
                MMAB(s[2 * p],     ql4, kh4[0], kh4[1]);
                MMAB(s[2 * p + 1], ql4, kh4[2], kh4[3]);
            }
        }

        // ---- mask + scale ----
        if (k0 + 63 > q0 + wm) {
#pragma unroll
            for (int nt = 0; nt < 8; nt++) {
                const int cbase = k0 + nt * 8 + 2 * (lane & 3);
                s[nt][0] = (cbase     > grow0) ? -INFINITY : s[nt][0] * scale;
                s[nt][1] = (cbase + 1 > grow0) ? -INFINITY : s[nt][1] * scale;
                s[nt][2] = (cbase     > grow1) ? -INFINITY : s[nt][2] * scale;
                s[nt][3] = (cbase + 1 > grow1) ? -INFINITY : s[nt][3] * scale;
            }
        } else {
#pragma unroll
            for (int nt = 0; nt < 8; nt++)
#pragma unroll
                for (int e = 0; e < 4; e++) s[nt][e] *= scale;
        }

        // ---- online softmax ----
        float rmax0 = -INFINITY, rmax1 = -INFINITY;
#pragma unroll
        for (int nt = 0; nt < 8; nt++) {
            rmax0 = fmaxf(rmax0, fmaxf(s[nt][0], s[nt][1]));
            rmax1 = fmaxf(rmax1, fmaxf(s[nt][2], s[nt][3]));
        }
        rmax0 = fmaxf(rmax0, __shfl_xor_sync(0xffffffff, rmax0, 1));
        rmax0 = fmaxf(rmax0, __shfl_xor_sync(0xffffffff, rmax0, 2));
        rmax1 = fmaxf(rmax1, __shfl_xor_sync(0xffffffff, rmax1, 1));
        rmax1 = fmaxf(rmax1, __shfl_xor_sync(0xffffffff, rmax1, 2));

        const float mn0 = fmaxf(m0, rmax0), mn1 = fmaxf(m1, rmax1);
        const float a0 = __expf(m0 - mn0), a1 = __expf(m1 - mn1);

        float sum0 = 0.f, sum1 = 0.f;
#pragma unroll
        for (int nt = 0; nt < 8; nt++) {
            s[nt][0] = __expf(s[nt][0] - mn0);
            s[nt][1] = __expf(s[nt][1] - mn0);
            s[nt][2] = __expf(s[nt][2] - mn1);
            s[nt][3] = __expf(s[nt][3] - mn1);
            sum0 += s[nt][0] + s[nt][1];
            sum1 += s[nt][2] + s[nt][3];
        }
        sum0 += __shfl_xor_sync(0xffffffff, sum0, 1);
        sum0 += __shfl_xor_sync(0xffffffff, sum0, 2);
        sum1 += __shfl_xor_sync(0xffffffff, sum1, 1);
        sum1 += __shfl_xor_sync(0xffffffff, sum1, 2);

        l0 = l0 * a0 + sum0;
        l1 = l1 * a1 + sum1;
        m0 = mn0;
        m1 = mn1;

#pragma unroll
        for (int nt = 0; nt < 16; nt++) {
            o[nt][0] *= a0; o[nt][1] *= a0;
            o[nt][2] *= a1; o[nt][3] *= a1;
        }

        // pack P to fp16 A-frags
        uint32_t ph[4][4];
#pragma unroll
        for (int ks2 = 0; ks2 < 4; ks2++) {
            ph[ks2][0] = packh(s[2 * ks2][0],     s[2 * ks2][1]);
            ph[ks2][1] = packh(s[2 * ks2][2],     s[2 * ks2][3]);
            ph[ks2][2] = packh(s[2 * ks2 + 1][0], s[2 * ks2 + 1][1]);
            ph[ks2][3] = packh(s[2 * ks2 + 1][2], s[2 * ks2 + 1][3]);
        }

        // ---- O += P V, fp16 1-product ----
#pragma unroll
        for (int ks2 = 0; ks2 < 4; ks2++) {
#pragma unroll
            for (int ntp = 0; ntp < 8; ntp++) {
                uint32_t vh4[4];
                LDSM4T(vh4, kvb + 34816 + voff + ks2 * 16 * FP + ntp * 32);
                MMAH(o[2 * ntp],     ph[ks2], vh4[0], vh4[1]);
                MMAH(o[2 * ntp + 1], ph[ks2], vh4[2], vh4[3]);
            }
        }
    }

    // epilogue: normalize, pack fp16, store
    const float inv0 = 1.f / l0, inv1 = 1.f / l1;
    const size_t rb0 = gbase + (size_t)grow0 * NN + 2 * (lane & 3);
    const size_t rb1 = gbase + (size_t)grow1 * NN + 2 * (lane & 3);
#pragma unroll
    for (int nt = 0; nt < 16; nt++) {
        *(uint32_t*)(Oh + rb0 + nt * 8) = packh(o[nt][0] * inv0, o[nt][1] * inv0);
        *(uint32_t*)(Oh + rb1 + nt * 8) = packh(o[nt][2] * inv1, o[nt][3] * inv1);
    }
}

// ============================================================================
// Launch
// ============================================================================
extern "C" void kernel_launch(void* const* d_in, const int* in_sizes, int n_in,
                              void* d_out, int out_size) {
    const float* x  = (const float*)d_in[0];
    const float* wq = (const float*)d_in[1];
    const float* wk = (const float*)d_in[2];
    const float* wv = (const float*)d_in[3];
    const float* wo = (const float*)d_in[4];
    float* out = (float*)d_out;

    __half *xfh, *wqh, *wql, *wkh, *wkl, *wvh, *woh, *vah, *aoh;
    __nv_bfloat16 *qah, *qal, *kah, *kal;
    cudaGetSymbolAddress((void**)&xfh, g_xf_h);
    cudaGetSymbolAddress((void**)&wqh, g_wq_h); cudaGetSymbolAddress((void**)&wql, g_wq_l);
    cudaGetSymbolAddress((void**)&wkh, g_wk_h); cudaGetSymbolAddress((void**)&wkl, g_wk_l);
    cudaGetSymbolAddress((void**)&wvh, g_wv_h);
    cudaGetSymbolAddress((void**)&woh, g_wo_h);
    cudaGetSymbolAddress((void**)&vah, g_va_h);
    cudaGetSymbolAddress((void**)&aoh, g_ao_h);
    cudaGetSymbolAddress((void**)&qah, g_qa_h); cudaGetSymbolAddress((void**)&qal, g_qa_l);
    cudaGetSymbolAddress((void**)&kah, g_ka_h); cudaGetSymbolAddress((void**)&kal, g_ka_l);

    cudaFuncSetAttribute(proj_all, cudaFuncAttributeMaxDynamicSharedMemorySize, PSMEM);
    cudaFuncSetAttribute(gemm1, cudaFuncAttributeMaxDynamicSharedMemorySize, SMEM1);
    cudaFuncSetAttribute(flash_mma, cudaFuncAttributeMaxDynamicSharedMemorySize,
                         FLASH_SMEM);

    const int splitBlocks = (MM * 4096) / (4 * 256);   // 16384
    pack_f16 <<<splitBlocks, 256>>>((const float4*)x,  (uint2*)xfh);
    split_h16<<<splitBlocks, 256>>>((const float4*)wq, (uint2*)wqh, (uint2*)wql);
    split_h16<<<splitBlocks, 256>>>((const float4*)wk, (uint2*)wkh, (uint2*)wkl);
    pack_f16 <<<splitBlocks, 256>>>((const float4*)wv, (uint2*)wvh);
    pack_f16 <<<splitBlocks, 256>>>((const float4*)wo, (uint2*)woh);

    dim3 gproj(NN / 128, MM / 128, 3);   // Q, K, V in one launch (V last)
    proj_all<<<gproj, 256, PSMEM>>>(xfh, wqh, wql, wkh, wkl, wvh,
                                    qah, qal, kah, kal, vah);

    dim3 fgrid(TLEN / 128, 2 * 32);      // (16, 64), heavy-first inside kernel
    flash_mma<<<fgrid, 256, FLASH_SMEM>>>(qah, qal, kah, kal, vah, aoh);

    dim3 ggrid(NN / 128, MM / 128);
    gemm1<<<ggrid, 256, SMEM1>>>(aoh, woh, out);   // output projection
}

// round 10
// speedup vs baseline: 9.6676x; 1.3753x over previous
#include <cuda_runtime.h>
#include <cuda_bf16.h>
#include <cuda_fp16.h>
#include <cstdint>
#include <math.h>

// ----------------------------------------------------------------------------
// B=2, T=2048, C=4096, H=32, hd=128.  M=N=K=4096.
// Precision plan (validated quadrature model, sources combine in quadrature):
//   ALL projections (Q,K,V,out): fp16 1-product HMMA (x,W single fp16).
//   Flash S = QK^T: bf16 3-product (Q,K stored as bf16 hi/lo).
//   Flash PV: fp16 1-product.
// Predicted rel_err ~7.5e-4 vs 1e-3 gate.
// Rotary (theta = t, adjacent pairs) fused in Q/K projection epilogue.
// ----------------------------------------------------------------------------

#define MM 4096
#define NN 4096
#define KK 4096
#define TLEN 2048

// fp16 operands
__device__ __half g_xf_h[(size_t)MM * KK];
__device__ __half g_wq_h[(size_t)NN * KK];
__device__ __half g_wk_h[(size_t)NN * KK];
__device__ __half g_wv_h[(size_t)NN * KK];
__device__ __half g_wo_h[(size_t)NN * KK];
__device__ __half g_va_h[(size_t)MM * NN];
__device__ __half g_ao_h[(size_t)MM * NN];
// bf16 hi/lo Q,K activations (flash S needs 3-product accuracy)
__device__ __nv_bfloat16 g_qa_h[(size_t)MM * NN], g_qa_l[(size_t)MM * NN];
__device__ __nv_bfloat16 g_ka_h[(size_t)MM * NN], g_ka_l[(size_t)MM * NN];

__device__ __forceinline__ uint32_t smem_u32(const void* p) {
    uint32_t a;
    asm("{ .reg .u64 t; cvta.to.shared.u64 t, %1; cvt.u32.u64 %0, t; }"
        : "=r"(a) : "l"(p));
    return a;
}

#define LDSM4(r, a)                                                            \
    asm volatile("ldmatrix.sync.aligned.m8n8.x4.shared.b16 {%0,%1,%2,%3}, [%4];" \
                 : "=r"((r)[0]), "=r"((r)[1]), "=r"((r)[2]), "=r"((r)[3])      \
                 : "r"(a))

#define LDSM4T(r, a)                                                           \
    asm volatile("ldmatrix.sync.aligned.m8n8.x4.trans.shared.b16 {%0,%1,%2,%3}, [%4];" \
                 : "=r"((r)[0]), "=r"((r)[1]), "=r"((r)[2]), "=r"((r)[3])      \
                 : "r"(a))

#define MMAB(c, a, b0, b1)                                                     \
    asm volatile("mma.sync.aligned.m16n8k16.row.col.f32.bf16.bf16.f32 "        \
                 "{%0,%1,%2,%3},{%4,%5,%6,%7},{%8,%9},{%0,%1,%2,%3};"          \
                 : "+f"((c)[0]), "+f"((c)[1]), "+f"((c)[2]), "+f"((c)[3])      \
                 : "r"((a)[0]), "r"((a)[1]), "r"((a)[2]), "r"((a)[3]),         \
                   "r"(b0), "r"(b1))

#define MMAH(c, a, b0, b1)                                                     \
    asm volatile("mma.sync.aligned.m16n8k16.row.col.f32.f16.f16.f32 "          \
                 "{%0,%1,%2,%3},{%4,%5,%6,%7},{%8,%9},{%0,%1,%2,%3};"          \
                 : "+f"((c)[0]), "+f"((c)[1]), "+f"((c)[2]), "+f"((c)[3])      \
                 : "r"((a)[0]), "r"((a)[1]), "r"((a)[2]), "r"((a)[3]),         \
                   "r"(b0), "r"(b1))

#define CPA16(dst, src)                                                        \
    asm volatile("cp.async.cg.shared.global [%0], [%1], 16;"                   \
                 :: "r"(dst), "l"(src) : "memory")
#define CPCOMMIT() asm volatile("cp.async.commit_group;" ::: "memory")
#define CPWAIT1()  asm volatile("cp.async.wait_group 1;" ::: "memory")
#define CPWAIT0()  asm volatile("cp.async.wait_group 0;" ::: "memory")

__device__ __forceinline__ void split2b(float x0, float x1,
                                        uint32_t& hi, uint32_t& lo) {
    uint32_t u0 = __float_as_uint(x0), u1 = __float_as_uint(x1);
    hi = __byte_perm(u0, u1, 0x7632);
    float l0 = x0 - __uint_as_float(u0 & 0xFFFF0000u);
    float l1 = x1 - __uint_as_float(u1 & 0xFFFF0000u);
    asm("cvt.rn.bf16x2.f32 %0, %1, %2;" : "=r"(lo) : "f"(l1), "f"(l0));
}

__device__ __forceinline__ uint32_t packh(float x0, float x1) {
    uint32_t r;
    asm("cvt.rn.f16x2.f32 %0, %1, %2;" : "=r"(r) : "f"(x1), "f"(x0));
    return r;
}

// ============================================================================
// pack5: all five fp32 -> fp16 packs in one launch (blockIdx.y selects matrix)
// ============================================================================
__global__ __launch_bounds__(256)
void pack5(const float4* __restrict__ s0, const float4* __restrict__ s1,
           const float4* __restrict__ s2, const float4* __restrict__ s3,
           const float4* __restrict__ s4,
           uint2* __restrict__ d0, uint2* __restrict__ d1,
           uint2* __restrict__ d2, uint2* __restrict__ d3,
           uint2* __restrict__ d4) {
    const int w = blockIdx.y;
    const float4* s = (w == 0) ? s0 : (w == 1) ? s1 : (w == 2) ? s2
                      : (w == 3) ? s3 : s4;
    uint2* d = (w == 0) ? d0 : (w == 1) ? d1 : (w == 2) ? d2
               : (w == 3) ? d3 : d4;
    size_t i = (size_t)blockIdx.x * 256 + threadIdx.x;
    float4 v = s[i];
    d[i] = make_uint2(packh(v.x, v.y), packh(v.z, v.w));
}

// ============================================================================
// proj_all: fused Q/K/V projections, all fp16 1-product.  C = x * W^T.
// z=0: Q (rotary, bf16 hi/lo out); z=1: K (same); z=2: V (fp16 out).
// CTA 128x128, 8 warps 32x64, K-chunk 32, 3-stage cp.async, 1 sync/chunk.
// ============================================================================
#define PITCH 80
#define PMAT (128 * PITCH)         // 10240
#define STG (2 * PMAT)             // 20480
#define GSMEM (3 * STG)            // 61440 (3 stages)
#define NCH (KK / 32)              // 128

__global__ __launch_bounds__(256, 2)
void proj_all(const __half* __restrict__ Ah,
              const __half* __restrict__ Wqh, const __half* __restrict__ Wkh,
              const __half* __restrict__ Wvh,
              __nv_bfloat16* __restrict__ Qh, __nv_bfloat16* __restrict__ Qlo,
              __nv_bfloat16* __restrict__ Kh, __nv_bfloat16* __restrict__ Klo,
              __half* __restrict__ Vh) {
    extern __shared__ __align__(1024) char sm[];
    const uint32_t wbase = smem_u32(sm);
    const int tid = threadIdx.x;
    const int wid = tid >> 5, lane = tid & 31;
    const int row0 = blockIdx.y * 128, col0 = blockIdx.x * 128;
    const int z = blockIdx.z;

    const __half* Bh_ = (z == 0) ? Wqh : (z == 1) ? Wkh : Wvh;

    const int lrow = tid >> 2, lseg = tid & 3;
    const __half* pA = Ah  + (size_t)(row0 + lrow) * KK + lseg * 8;
    const __half* pB = Bh_ + (size_t)(col0 + lrow) * KK + lseg * 8;
    const uint32_t doff = (uint32_t)lrow * PITCH + lseg * 16;
    const size_t rstep = (size_t)64 * KK;

#define LOADG(chunk, buf)                                                      \
    do {                                                                       \
        const uint32_t sb_ = wbase + (buf) * STG + doff;                       \
        const size_t ko_ = (size_t)(chunk) * 32;                               \
        CPA16(sb_,                      pA + ko_);                             \
        CPA16(sb_ + 64 * PITCH,         pA + ko_ + rstep);                     \
        CPA16(sb_ + PMAT,               pB + ko_);                             \
        CPA16(sb_ + PMAT + 64 * PITCH,  pB + ko_ + rstep);                     \
        CPCOMMIT();                                                            \
    } while (0)

    const int wm = (wid & 3) * 32, wn = (wid >> 2) * 64;
    const int l = lane;
    const uint32_t aoff =
        (uint32_t)(wm + (l & 7) + 8 * ((l >> 3) & 1)) * PITCH + (l >> 4) * 16;
    const uint32_t boff = PMAT +
        (uint32_t)(wn + (l & 7) + 8 * (l >> 4)) * PITCH + ((l >> 3) & 1) * 16;

    float acc[2][8][4];
#pragma unroll
    for (int i = 0; i < 2; i++)
#pragma unroll
        for (int j = 0; j < 8; j++)
#pragma unroll
            for (int q = 0; q < 4; q++) acc[i][j][q] = 0.f;

    LOADG(0, 0);
    LOADG(1, 1);

    int buf = 0;
    for (int i = 0; i < NCH; i++) {
        if (i + 1 < NCH) { CPWAIT1(); } else { CPWAIT0(); }
        __syncthreads();
        if (i + 2 < NCH) {
            int nb = buf + 2; if (nb >= 3) nb -= 3;
            LOADG(i + 2, nb);
        }

        const uint32_t sb = wbase + buf * STG;
#pragma unroll
        for (int ks = 0; ks < 2; ks++) {
            uint32_t a4[2][4];
            const uint32_t ka = sb + aoff + ks * 32;
#pragma unroll
            for (int mt = 0; mt < 2; mt++)
                LDSM4(a4[mt], ka + mt * 16 * PITCH);
            const uint32_t kb = sb + boff + ks * 32;
#pragma unroll
            for (int p = 0; p < 4; p++) {
                uint32_t bh4[4];
                LDSM4(bh4, kb + p * 16 * PITCH);
#pragma unroll
                for (int mt = 0; mt < 2; mt++) {
                    MMAH(acc[mt][2 * p],     a4[mt], bh4[0], bh4[1]);
                    MMAH(acc[mt][2 * p + 1], a4[mt], bh4[2], bh4[3]);
                }
            }
        }
        if (++buf == 3) buf = 0;
    }

    // epilogue
    const int mrow = lane >> 2, ncol = 2 * (lane & 3);
    __nv_bfloat16* Ch = (z == 0) ? Qh : Kh;
    __nv_bfloat16* Cl = (z == 0) ? Qlo : Klo;
#pragma unroll
    for (int mt = 0; mt < 2; mt++) {
#pragma unroll
        for (int part = 0; part < 2; part++) {
            const int m = row0 + wm + mt * 16 + mrow + part * 8;
            const size_t rowb = (size_t)m * NN + col0 + wn + ncol;
            if (z < 2) {
                float sn, cs;
                sincosf((float)(m & (TLEN - 1)), &sn, &cs);
#pragma unroll
                for (int nt = 0; nt < 8; nt++) {
                    float x0 = acc[mt][nt][2 * part];
                    float x1 = acc[mt][nt][2 * part + 1];
                    float y0 = x0 * cs - x1 * sn;
                    float y1 = x0 * sn + x1 * cs;
                    uint32_t hi, lo;
                    split2b(y0, y1, hi, lo);
                    *(uint32_t*)(Ch + rowb + nt * 8) = hi;
                    *(uint32_t*)(Cl + rowb + nt * 8) = lo;
                }
            } else {
#pragma unroll
                for (int nt = 0; nt < 8; nt++) {
                    *(uint32_t*)(Vh + rowb + nt * 8) =
                        packh(acc[mt][nt][2 * part], acc[mt][nt][2 * part + 1]);
                }
            }
        }
    }
}

// ============================================================================
// gemm1: fp16 1-product. C = Ah*Bh^T, fp32 out. 3-stage pipeline.
// ============================================================================
__global__ __launch_bounds__(256, 2)
void gemm1(const __half* __restrict__ Ah, const __half* __restrict__ Bh,
           float* __restrict__ Cf) {
    extern __shared__ __align__(1024) char sm[];
    const uint32_t wbase = smem_u32(sm);
    const int tid = threadIdx.x;
    const int wid = tid >> 5, lane = tid & 31;
    const int row0 = blockIdx.y * 128, col0 = blockIdx.x * 128;

    const int lrow = tid >> 2, lseg = tid & 3;
    const __half* pA = Ah + (size_t)(row0 + lrow) * KK + lseg * 8;
    const __half* pB = Bh + (size_t)(col0 + lrow) * KK + lseg * 8;
    const uint32_t doff = (uint32_t)lrow * PITCH + lseg * 16;
    const size_t rstep = (size_t)64 * KK;

#define LOAD1(chunk, buf)                                                      \
    do {                                                                       \
        const uint32_t sb_ = wbase + (buf) * STG + doff;                       \
        const size_t ko_ = (size_t)(chunk) * 32;                               \
        CPA16(sb_,                      pA + ko_);                             \
        CPA16(sb_ + 64 * PITCH,         pA + ko_ + rstep);                     \
        CPA16(sb_ + PMAT,               pB + ko_);                             \
        CPA16(sb_ + PMAT + 64 * PITCH,  pB + ko_ + rstep);                     \
        CPCOMMIT();                                                            \
    } while (0)

    const int wm = (wid & 3) * 32, wn = (wid >> 2) * 64;
    const int l = lane;
    const uint32_t aoff =
        (uint32_t)(wm + (l & 7) + 8 * ((l >> 3) & 1)) * PITCH + (l >> 4) * 16;
    const uint32_t boff = PMAT +
        (uint32_t)(wn + (l & 7) + 8 * (l >> 4)) * PITCH + ((l >> 3) & 1) * 16;

    float acc[2][8][4];
#pragma unroll
    for (int i = 0; i < 2; i++)
#pragma unroll
        for (int j = 0; j < 8; j++)
#pragma unroll
            for (int q = 0; q < 4; q++) acc[i][j][q] = 0.f;

    LOAD1(0, 0);
    LOAD1(1, 1);

    int buf = 0;
    for (int i = 0; i < NCH; i++) {
        if (i + 1 < NCH) { CPWAIT1(); } else { CPWAIT0(); }
        __syncthreads();
        if (i + 2 < NCH) {
            int nb = buf + 2; if (nb >= 3) nb -= 3;
            LOAD1(i + 2, nb);
        }

        const uint32_t sb = wbase + buf * STG;
#pragma unroll
        for (int ks = 0; ks < 2; ks++) {
            uint32_t a4[2][4];
            const uint32_t ka = sb + aoff + ks * 32;
#pragma unroll
            for (int mt = 0; mt < 2; mt++)
                LDSM4(a4[mt], ka + mt * 16 * PITCH);
            const uint32_t kb = sb + boff + ks * 32;
#pragma unroll
            for (int p = 0; p < 4; p++) {
                uint32_t bh4[4];
                LDSM4(bh4, kb + p * 16 * PITCH);
#pragma unroll
                for (int mt = 0; mt < 2; mt++) {
                    MMAH(acc[mt][2 * p],     a4[mt], bh4[0], bh4[1]);
                    MMAH(acc[mt][2 * p + 1], a4[mt], bh4[2], bh4[3]);
                }
            }
        }
        if (++buf == 3) buf = 0;
    }

    const int mrow = lane >> 2, ncol = 2 * (lane & 3);
#pragma unroll
    for (int mt = 0; mt < 2; mt++) {
#pragma unroll
        for (int part = 0; part < 2; part++) {
            const int m = row0 + wm + mt * 16 + mrow + part * 8;
            const size_t rowb = (size_t)m * NN + col0 + wn + ncol;
#pragma unroll
            for (int nt = 0; nt < 8; nt++) {
                *(float2*)(Cf + rowb + nt * 8) =
                    make_float2(acc[mt][nt][2 * part], acc[mt][nt][2 * part + 1]);
            }
        }
    }
}

// ============================================================================
// Flash attention: BQ=128, BK=64, hd=128, 256 threads, 1 CTA/SM.
// S = QK^T bf16 3-product; PV fp16 1-product. K/V double-buffered prefetch.
// ============================================================================
#define FP 272
#define FQH 0
#define FQL 34816
#define FKV 69632
#define FSTG 52224          // KH | KL(+17408) | VH(+34816)
#define FLASH_SMEM (FKV + 2 * FSTG)   // 174080

__global__ __launch_bounds__(256, 1)
void flash_mma(const __nv_bfloat16* __restrict__ Qh, const __nv_bfloat16* __restrict__ Ql,
               const __nv_bfloat16* __restrict__ Kh, const __nv_bfloat16* __restrict__ Kl,
               const __half* __restrict__ Vh, __half* __restrict__ Oh) {
    extern __shared__ __align__(1024) char sm[];
    const uint32_t smb = smem_u32(sm);
    const int tid = threadIdx.x;
    const int wid = tid >> 5, lane = tid & 31;
    const int bh_ = blockIdx.y;
    const int b = bh_ >> 5, h = bh_ & 31;
    const int jt = (gridDim.x - 1) - blockIdx.x;   // heavy tiles first
    const int q0 = jt * 128;
    const int nkt = 2 * jt + 2;
    const float scale = 0.08838834764831845f;

    const size_t gbase = ((size_t)b * TLEN) * NN + (size_t)h * 128;

    {
        const int qr = tid >> 1, qc = (tid & 1) * 8;
        const size_t gq = gbase + (size_t)(q0 + qr) * NN + qc * 8;
        const uint32_t sq = smb + qr * FP + qc * 16;
#pragma unroll
        for (int c = 0; c < 8; c++) {
            CPA16(sq + FQH + c * 16, Qh + gq + c * 8);
            CPA16(sq + FQL + c * 16, Ql + gq + c * 8);
        }
        CPCOMMIT();
    }

    const int kvr = tid >> 2, kvs = tid & 3;
#define LOADKV(kt_, buf_)                                                      \
    do {                                                                       \
        const size_t gk_ = gbase + (size_t)((kt_) * 64 + kvr) * NN + kvs * 32; \
        const uint32_t sk_ = smb + FKV + (buf_) * FSTG + kvr * FP + kvs * 64;  \
        _Pragma("unroll")                                                      \
        for (int c = 0; c < 4; c++) {                                          \
            CPA16(sk_ + c * 16,         Kh + gk_ + c * 8);                     \
            CPA16(sk_ + c * 16 + 17408, Kl + gk_ + c * 8);                     \
            CPA16(sk_ + c * 16 + 34816, Vh + gk_ + c * 8);                     \
        }                                                                      \
        CPCOMMIT();                                                            \
    } while (0)

    LOADKV(0, 0);

    const int wm = wid * 16;
    const int l = lane;
    const uint32_t aoff =
        (uint32_t)(wm + (l & 7) + 8 * ((l >> 3) & 1)) * FP + (l >> 4) * 16;
    const uint32_t boff =
        (uint32_t)((l & 7) + 8 * (l >> 4)) * FP + ((l >> 3) & 1) * 16;
    const uint32_t voff =
        (uint32_t)((l & 7) + 8 * ((l >> 3) & 1)) * FP + (l >> 4) * 16;

    float o[16][4];
#pragma unroll
    for (int i = 0; i < 16; i++)
#pragma unroll
        for (int j = 0; j < 4; j++) o[i][j] = 0.f;
    float m0 = -INFINITY, m1 = -INFINITY, l0 = 0.f, l1 = 0.f;

    const int grow0 = q0 + wm + (lane >> 2);
    const int grow1 = grow0 + 8;

    for (int kt = 0; kt < nkt; kt++) {
        const int k0 = kt * 64;
        __syncthreads();
        if (kt + 1 < nkt) {
            LOADKV(kt + 1, (kt + 1) & 1);
            CPWAIT1();
        } else {
            CPWAIT0();
        }
        __syncthreads();

        if (k0 > q0 + wm + 15) continue;   // fully masked for this warp

        const uint32_t kvb = smb + FKV + (kt & 1) * FSTG;

        float s[8][4];
#pragma unroll
        for (int i = 0; i < 8; i++)
#pragma unroll
            for (int j = 0; j < 4; j++) s[i][j] = 0.f;

#pragma unroll
        for (int ks = 0; ks < 8; ks++) {
            uint32_t qh4[4], ql4[4];
            LDSM4(qh4, smb + FQH + aoff + ks * 32);
            LDSM4(ql4, smb + FQL + aoff + ks * 32);
#pragma unroll
            for (int p = 0; p < 4; p++) {
                uint32_t kh4[4], kl4[4];
                LDSM4(kh4, kvb + boff + p * 16 * FP + ks * 32);
                LDSM4(kl4, kvb + 17408 + boff + p * 16 * FP + ks * 32);
                MMAB(s[2 * p],     qh4, kh4[0], kh4[1]);
                MMAB(s[2 * p + 1], qh4, kh4[2], kh4[3]);
                MMAB(s[2 * p],     qh4, kl4[0], kl4[1]);
                MMAB(s[2 * p + 1], qh4, kl4[2], kl4[3]);
                MMAB(s[2 * p],     ql4, kh4[0], kh4[1]);
                MMAB(s[2 * p + 1], ql4, kh4[2], kh4[3]);
            }
        }

        if (k0 + 63 > q0 + wm) {
#pragma unroll
            for (int nt = 0; nt < 8; nt++) {
                const int cbase = k0 + nt * 8 + 2 * (lane & 3);
                s[nt][0] = (cbase     > grow0) ? -INFINITY : s[nt][0] * scale;
                s[nt][1] = (cbase + 1 > grow0) ? -INFINITY : s[nt][1] * scale;
                s[nt][2] = (cbase     > grow1) ? -INFINITY : s[nt][2] * scale;
                s[nt][3] = (cbase + 1 > grow1) ? -INFINITY : s[nt][3] * scale;
            }
        } else {
#pragma unroll
            for (int nt = 0; nt < 8; nt++)
#pragma unroll
                for (int e = 0; e < 4; e++) s[nt][e] *= scale;
        }

        float rmax0 = -INFINITY, rmax1 = -INFINITY;
#pragma unroll
        for (int nt = 0; nt < 8; nt++) {
            rmax0 = fmaxf(rmax0, fmaxf(s[nt][0], s[nt][1]));
            rmax1 = fmaxf(rmax1, fmaxf(s[nt][2], s[nt][3]));
        }
        rmax0 = fmaxf(rmax0, __shfl_xor_sync(0xffffffff, rmax0, 1));
        rmax0 = fmaxf(rmax0, __shfl_xor_sync(0xffffffff, rmax0, 2));
        rmax1 = fmaxf(rmax1, __shfl_xor_sync(0xffffffff, rmax1, 1));
        rmax1 = fmaxf(rmax1, __shfl_xor_sync(0xffffffff, rmax1, 2));

        const float mn0 = fmaxf(m0, rmax0), mn1 = fmaxf(m1, rmax1);
        const float a0 = __expf(m0 - mn0), a1 = __expf(m1 - mn1);

        float sum0 = 0.f, sum1 = 0.f;
#pragma unroll
        for (int nt = 0; nt < 8; nt++) {
            s[nt][0] = __expf(s[nt][0] - mn0);
            s[nt][1] = __expf(s[nt][1] - mn0);
            s[nt][2] = __expf(s[nt][2] - mn1);
            s[nt][3] = __expf(s[nt][3] - mn1);
            sum0 += s[nt][0] + s[nt][1];
            sum1 += s[nt][2] + s[nt][3];
        }
        sum0 += __shfl_xor_sync(0xffffffff, sum0, 1);
        sum0 += __shfl_xor_sync(0xffffffff, sum0, 2);
        sum1 += __shfl_xor_sync(0xffffffff, sum1, 1);
        sum1 += __shfl_xor_sync(0xffffffff, sum1, 2);

        l0 = l0 * a0 + sum0;
        l1 = l1 * a1 + sum1;
        m0 = mn0;
        m1 = mn1;

#pragma unroll
        for (int nt = 0; nt < 16; nt++) {
            o[nt][0] *= a0; o[nt][1] *= a0;
            o[nt][2] *= a1; o[nt][3] *= a1;
        }

        uint32_t ph[4][4];
#pragma unroll
        for (int ks2 = 0; ks2 < 4; ks2++) {
            ph[ks2][0] = packh(s[2 * ks2][0],     s[2 * ks2][1]);
            ph[ks2][1] = packh(s[2 * ks2][2],     s[2 * ks2][3]);
            ph[ks2][2] = packh(s[2 * ks2 + 1][0], s[2 * ks2 + 1][1]);
            ph[ks2][3] = packh(s[2 * ks2 + 1][2], s[2 * ks2 + 1][3]);
        }

#pragma unroll
        for (int ks2 = 0; ks2 < 4; ks2++) {
#pragma unroll
            for (int ntp = 0; ntp < 8; ntp++) {
                uint32_t vh4[4];
                LDSM4T(vh4, kvb + 34816 + voff + ks2 * 16 * FP + ntp * 32);
                MMAH(o[2 * ntp],     ph[ks2], vh4[0], vh4[1]);
                MMAH(o[2 * ntp + 1], ph[ks2], vh4[2], vh4[3]);
            }
        }
    }

    const float inv0 = 1.f / l0, inv1 = 1.f / l1;
    const size_t rb0 = gbase + (size_t)grow0 * NN + 2 * (lane & 3);
    const size_t rb1 = gbase + (size_t)grow1 * NN + 2 * (lane & 3);
#pragma unroll
    for (int nt = 0; nt < 16; nt++) {
        *(uint32_t*)(Oh + rb0 + nt * 8) = packh(o[nt][0] * inv0, o[nt][1] * inv0);
        *(uint32_t*)(Oh + rb1 + nt * 8) = packh(o[nt][2] * inv1, o[nt][3] * inv1);
    }
}

// ============================================================================
// Launch
// ============================================================================
extern "C" void kernel_launch(void* const* d_in, const int* in_sizes, int n_in,
                              void* d_out, int out_size) {
    const float* x  = (const float*)d_in[0];
    const float* wq = (const float*)d_in[1];
    const float* wk = (const float*)d_in[2];
    const float* wv = (const float*)d_in[3];
    const float* wo = (const float*)d_in[4];
    float* out = (float*)d_out;

    __half *xfh, *wqh, *wkh, *wvh, *woh, *vah, *aoh;
    __nv_bfloat16 *qah, *qal, *kah, *kal;
    cudaGetSymbolAddress((void**)&xfh, g_xf_h);
    cudaGetSymbolAddress((void**)&wqh, g_wq_h);
    cudaGetSymbolAddress((void**)&wkh, g_wk_h);
    cudaGetSymbolAddress((void**)&wvh, g_wv_h);
    cudaGetSymbolAddress((void**)&woh, g_wo_h);
    cudaGetSymbolAddress((void**)&vah, g_va_h);
    cudaGetSymbolAddress((void**)&aoh, g_ao_h);
    cudaGetSymbolAddress((void**)&qah, g_qa_h); cudaGetSymbolAddress((void**)&qal, g_qa_l);
    cudaGetSymbolAddress((void**)&kah, g_ka_h); cudaGetSymbolAddress((void**)&kal, g_ka_l);

    cudaFuncSetAttribute(proj_all, cudaFuncAttributeMaxDynamicSharedMemorySize, GSMEM);
    cudaFuncSetAttribute(gemm1, cudaFuncAttributeMaxDynamicSharedMemorySize, GSMEM);
    cudaFuncSetAttribute(flash_mma, cudaFuncAttributeMaxDynamicSharedMemorySize,
                         FLASH_SMEM);

    dim3 gpack((MM * 4096) / (4 * 256), 5);   // all 5 packs, one launch
    pack5<<<gpack, 256>>>((const float4*)x, (const float4*)wq, (const float4*)wk,
                          (const float4*)wv, (const float4*)wo,
                          (uint2*)xfh, (uint2*)wqh, (uint2*)wkh,
                          (uint2*)wvh, (uint2*)woh);

    dim3 gproj(NN / 128, MM / 128, 3);   // Q, K, V in one launch (V last)
    proj_all<<<gproj, 256, GSMEM>>>(xfh, wqh, wkh, wvh, qah, qal, kah, kal, vah);

    dim3 fgrid(TLEN / 128, 2 * 32);      // heavy-first inside kernel
    flash_mma<<<fgrid, 256, FLASH_SMEM>>>(qah, qal, kah, kal, vah, aoh);

    dim3 ggrid(NN / 128, MM / 128);
    gemm1<<<ggrid, 256, GSMEM>>>(aoh, woh, out);   // output projection
}